// round 1
// baseline (speedup 1.0000x reference)
#include <cuda_runtime.h>
#include <math.h>

// ---------------------------------------------------------------------------
// Model dims
// ---------------------------------------------------------------------------
#define B_      64
#define N_      512
#define D_      256
#define H_      4
#define HD_     64
#define M_      (B_ * N_)         // 32768 rows
#define EPS_    1e-5f

// ---------------------------------------------------------------------------
// Scratch (static __device__ globals; no allocations allowed)
// ---------------------------------------------------------------------------
__device__ float g_xp  [M_ * D_];
__device__ float g_yp  [M_ * D_];
__device__ float g_q   [M_ * D_];
__device__ float g_k   [M_ * D_];
__device__ float g_v   [M_ * D_];
__device__ float g_ctx [M_ * D_];
__device__ float g_xres[M_ * D_];
__device__ float g_hid [M_ * D_];
__device__ float g_xmlp[M_ * D_];

// ---------------------------------------------------------------------------
// Positional embedding value for (pos, col)
// pe[:,0::2] = sin(pos * exp(-(2i) ln(10000)/256)), pe[:,1::2] = cos(...)
// ---------------------------------------------------------------------------
__device__ __forceinline__ float pe_val(int pos, int c) {
    int i2 = c & ~1;
    float div = expf(-logf(10000.0f) * (float)i2 / (float)D_);
    float ang = (float)pos * div;
    return (c & 1) ? cosf(ang) : sinf(ang);
}

// ---------------------------------------------------------------------------
// Generic GEMM: out[M x 256] = A[M x K] @ W[256 x K]^T  (+ epilogue)
// Block tile: 32 rows x 256 cols, BK=32, 256 threads, 32 acc/thread.
// EPI: 0 = +bias ; 1 = relu(+bias) ; 2 = +bias+res ; 3 = LN(+bias [+pe] [+res])
// ---------------------------------------------------------------------------
template <int EPI>
__global__ __launch_bounds__(256) void gemm256(
    const float* __restrict__ A, int K,
    const float* __restrict__ W,
    const float* __restrict__ bias,
    const float* __restrict__ gamma,
    const float* __restrict__ beta,
    const float* __restrict__ res,
    int addPE,
    float* __restrict__ out)
{
    __shared__ float As[32][33];
    __shared__ float Bs[32 * 256];   // reused as the LN staging buffer (Csm)

    const int tid  = threadIdx.x;
    const int tcol = tid & 31;       // column group base
    const int trow = tid >> 5;       // row group (0..7), 4 rows each
    const int row0 = blockIdx.x * 32;

    float acc[4][8];
#pragma unroll
    for (int j = 0; j < 4; ++j)
#pragma unroll
        for (int i = 0; i < 8; ++i) acc[j][i] = 0.0f;

    for (int k0 = 0; k0 < K; k0 += 32) {
        // load A tile: 32x32, 4 contiguous elems / thread
        {
            int idx = tid * 4;
            int m   = idx >> 5;
            int kk  = idx & 31;
            const float* ap = A + (size_t)(row0 + m) * K + k0 + kk;
#pragma unroll
            for (int u = 0; u < 4; ++u) {
                int kg = k0 + kk + u;
                As[m][kk + u] = (kg < K) ? ap[u] : 0.0f;
            }
        }
        // load W tile: 256 out-rows x 32 k, thread t -> out-row t
        {
            const float* wp = W + (size_t)tid * K + k0;
#pragma unroll
            for (int kk = 0; kk < 32; ++kk) {
                int kg = k0 + kk;
                Bs[kk * 256 + tid] = (kg < K) ? wp[kk] : 0.0f;
            }
        }
        __syncthreads();
#pragma unroll
        for (int kk = 0; kk < 32; ++kk) {
            float a[4], b[8];
#pragma unroll
            for (int j = 0; j < 4; ++j) a[j] = As[trow * 4 + j][kk];
#pragma unroll
            for (int i = 0; i < 8; ++i) b[i] = Bs[kk * 256 + tcol + 32 * i];
#pragma unroll
            for (int j = 0; j < 4; ++j)
#pragma unroll
                for (int i = 0; i < 8; ++i) acc[j][i] = fmaf(a[j], b[i], acc[j][i]);
        }
        __syncthreads();
    }

    if (EPI <= 2) {
#pragma unroll
        for (int j = 0; j < 4; ++j) {
            int grow = row0 + trow * 4 + j;
#pragma unroll
            for (int i = 0; i < 8; ++i) {
                int c = tcol + 32 * i;
                float vv = acc[j][i] + bias[c];
                if (EPI == 1) vv = fmaxf(vv, 0.0f);
                if (EPI == 2) vv += res[(size_t)grow * D_ + c];
                out[(size_t)grow * D_ + c] = vv;
            }
        }
    } else {
        // stage (acc + bias [+pe] [+res]) into smem, then per-row LayerNorm
#pragma unroll
        for (int j = 0; j < 4; ++j) {
            int lrow = trow * 4 + j;
            int grow = row0 + lrow;
            int pos  = grow & (N_ - 1);
#pragma unroll
            for (int i = 0; i < 8; ++i) {
                int c = tcol + 32 * i;
                float vv = acc[j][i] + bias[c];
                if (addPE) vv += pe_val(pos, c);
                if (res)   vv += res[(size_t)grow * D_ + c];
                Bs[lrow * 256 + c] = vv;
            }
        }
        __syncthreads();
        const int warp = tid >> 5;
        const int lane = tid & 31;
        for (int sub = 0; sub < 4; ++sub) {
            int r = warp * 4 + sub;
            float vv[8];
            float sum = 0.0f, sq = 0.0f;
#pragma unroll
            for (int i = 0; i < 8; ++i) {
                vv[i] = Bs[r * 256 + lane + 32 * i];
                sum += vv[i];
                sq  = fmaf(vv[i], vv[i], sq);
            }
#pragma unroll
            for (int off = 16; off > 0; off >>= 1) {
                sum += __shfl_xor_sync(0xffffffffu, sum, off);
                sq  += __shfl_xor_sync(0xffffffffu, sq,  off);
            }
            float mu  = sum * (1.0f / 256.0f);
            float var = sq * (1.0f / 256.0f) - mu * mu;
            float rs  = rsqrtf(var + EPS_);
            int grow  = row0 + r;
#pragma unroll
            for (int i = 0; i < 8; ++i) {
                int c = lane + 32 * i;
                out[(size_t)grow * D_ + c] = (vv[i] - mu) * rs * gamma[c] + beta[c];
            }
        }
    }
}

// ---------------------------------------------------------------------------
// Flash attention: per (b,h), q-tile of 32 rows, kv-tiles of 32, hd=64
// thread: r = tid/8 (row), oct = tid%8; 4 S-cols + 8 O-cols per thread
// ---------------------------------------------------------------------------
__global__ __launch_bounds__(256) void attn_kernel(
    const float* __restrict__ q,
    const float* __restrict__ k,
    const float* __restrict__ v,
    float* __restrict__ ctx)
{
    __shared__ float Qs[32][65];
    __shared__ float Ks[32][65];
    __shared__ float Vs[32][65];
    __shared__ float Ps[32][33];

    const int tid = threadIdx.x;
    const int oct = tid & 7;
    const int r   = tid >> 3;
    const int bh  = blockIdx.y;
    const int b   = bh >> 2;
    const int h   = bh & 3;
    const int q0  = blockIdx.x * 32;

    // load Q tile (32 x 64), 8 contiguous / thread
    {
        int jr = tid >> 3;
        int kc = (tid & 7) * 8;
        const float* qb = q + ((size_t)(b * N_ + q0 + jr)) * D_ + h * HD_ + kc;
#pragma unroll
        for (int u = 0; u < 8; ++u) Qs[jr][kc + u] = qb[u];
    }

    float m = -1e30f, l = 0.0f;
    float o[8];
#pragma unroll
    for (int i = 0; i < 8; ++i) o[i] = 0.0f;
    const float scale = 0.125f;  // 1/sqrt(64)

    for (int t0 = 0; t0 < N_; t0 += 32) {
        __syncthreads();
        {
            int jr = tid >> 3;
            int kc = (tid & 7) * 8;
            const float* kb = k + ((size_t)(b * N_ + t0 + jr)) * D_ + h * HD_ + kc;
            const float* vb = v + ((size_t)(b * N_ + t0 + jr)) * D_ + h * HD_ + kc;
#pragma unroll
            for (int u = 0; u < 8; ++u) { Ks[jr][kc + u] = kb[u]; Vs[jr][kc + u] = vb[u]; }
        }
        __syncthreads();

        float s[4] = {0.f, 0.f, 0.f, 0.f};
#pragma unroll 8
        for (int kk = 0; kk < 64; ++kk) {
            float qv = Qs[r][kk];
#pragma unroll
            for (int jj = 0; jj < 4; ++jj) s[jj] = fmaf(qv, Ks[oct * 4 + jj][kk], s[jj]);
        }
#pragma unroll
        for (int jj = 0; jj < 4; ++jj) s[jj] *= scale;

        float mx = fmaxf(fmaxf(s[0], s[1]), fmaxf(s[2], s[3]));
#pragma unroll
        for (int off = 1; off <= 4; off <<= 1)
            mx = fmaxf(mx, __shfl_xor_sync(0xffffffffu, mx, off));
        float mnew = fmaxf(m, mx);
        float corr = __expf(m - mnew);
        float p[4], psum = 0.0f;
#pragma unroll
        for (int jj = 0; jj < 4; ++jj) { p[jj] = __expf(s[jj] - mnew); psum += p[jj]; }
#pragma unroll
        for (int off = 1; off <= 4; off <<= 1)
            psum += __shfl_xor_sync(0xffffffffu, psum, off);
        l = l * corr + psum;
        m = mnew;
#pragma unroll
        for (int i = 0; i < 8; ++i) o[i] *= corr;
#pragma unroll
        for (int jj = 0; jj < 4; ++jj) Ps[r][oct * 4 + jj] = p[jj];
        __syncthreads();
#pragma unroll 4
        for (int j = 0; j < 32; ++j) {
            float pv = Ps[r][j];
#pragma unroll
            for (int cc = 0; cc < 8; ++cc) o[cc] = fmaf(pv, Vs[j][oct * 8 + cc], o[cc]);
        }
    }

    float inv = 1.0f / l;
    float* cb = ctx + ((size_t)(b * N_ + q0 + r)) * D_ + h * HD_ + oct * 8;
#pragma unroll
    for (int cc = 0; cc < 8; ++cc) cb[cc] = o[cc] * inv;
}

// ---------------------------------------------------------------------------
// mean-pool over N, then logits = pooled @ Wc^T + bc
// ---------------------------------------------------------------------------
__global__ __launch_bounds__(256) void pool_cls_kernel(
    const float* __restrict__ xm,
    const float* __restrict__ Wc,
    const float* __restrict__ bc,
    float* __restrict__ out)
{
    __shared__ float pooled[D_];
    const int b = blockIdx.x;
    const int t = threadIdx.x;
    float s = 0.0f;
    const float* p = xm + (size_t)b * N_ * D_ + t;
#pragma unroll 8
    for (int n = 0; n < N_; ++n) s += p[(size_t)n * D_];
    pooled[t] = s * (1.0f / (float)N_);
    __syncthreads();
    if (t < 2) {
        float a = bc[t];
        for (int c = 0; c < D_; ++c) a = fmaf(pooled[c], Wc[t * D_ + c], a);
        out[b * 2 + t] = a;
    }
}

// ---------------------------------------------------------------------------
// Launch
// ---------------------------------------------------------------------------
static float* sym(const void* s) {
    void* p = nullptr;
    cudaGetSymbolAddress(&p, s);
    return (float*)p;
}

extern "C" void kernel_launch(void* const* d_in, const int* in_sizes, int n_in,
                              void* d_out, int out_size)
{
    const float* x   = (const float*)d_in[0];
    const float* y   = (const float*)d_in[1];
    // d_in[2] = z (unused by the model)
    const float* Wr  = (const float*)d_in[3];
    const float* br  = (const float*)d_in[4];
    const float* Wf  = (const float*)d_in[5];
    const float* bf  = (const float*)d_in[6];
    const float* g_x = (const float*)d_in[7];
    const float* b_x = (const float*)d_in[8];
    const float* g_y = (const float*)d_in[9];
    const float* b_y = (const float*)d_in[10];
    const float* Wq  = (const float*)d_in[11];
    const float* bq  = (const float*)d_in[12];
    const float* Wk  = (const float*)d_in[13];
    const float* bk  = (const float*)d_in[14];
    const float* Wv  = (const float*)d_in[15];
    const float* bv  = (const float*)d_in[16];
    const float* Wo  = (const float*)d_in[17];
    const float* bo  = (const float*)d_in[18];
    const float* g_m = (const float*)d_in[19];
    const float* b_m = (const float*)d_in[20];
    const float* W1  = (const float*)d_in[21];
    const float* b1  = (const float*)d_in[22];
    const float* W2  = (const float*)d_in[23];
    const float* b2  = (const float*)d_in[24];
    const float* Wc  = (const float*)d_in[25];
    const float* bc  = (const float*)d_in[26];
    float* out = (float*)d_out;

    float* xp   = sym(g_xp);
    float* yp   = sym(g_yp);
    float* qb   = sym(g_q);
    float* kb   = sym(g_k);
    float* vb   = sym(g_v);
    float* ctx  = sym(g_ctx);
    float* xres = sym(g_xres);
    float* hid  = sym(g_hid);
    float* xmlp = sym(g_xmlp);

    dim3 gg(M_ / 32);
    dim3 bb(256);

    // xp = LN(x @ Wr^T + br + pe)
    gemm256<3><<<gg, bb>>>(x, 769, Wr, br, g_x, b_x, nullptr, 1, xp);
    // yp = LN(y @ Wf^T + bf + pe)
    gemm256<3><<<gg, bb>>>(y, 674, Wf, bf, g_y, b_y, nullptr, 1, yp);
    // q,k,v
    gemm256<0><<<gg, bb>>>(xp, 256, Wq, bq, nullptr, nullptr, nullptr, 0, qb);
    gemm256<0><<<gg, bb>>>(yp, 256, Wk, bk, nullptr, nullptr, nullptr, 0, kb);
    gemm256<0><<<gg, bb>>>(yp, 256, Wv, bv, nullptr, nullptr, nullptr, 0, vb);
    // attention
    dim3 ag(N_ / 32, B_ * H_);
    attn_kernel<<<ag, bb>>>(qb, kb, vb, ctx);
    // x_res = LN(xp + ctx @ Wo^T + bo)
    gemm256<3><<<gg, bb>>>(ctx, 256, Wo, bo, g_m, b_m, xp, 0, xres);
    // hid = relu(x_res @ W1^T + b1)
    gemm256<1><<<gg, bb>>>(xres, 256, W1, b1, nullptr, nullptr, nullptr, 0, hid);
    // xmlp = x_res + hid @ W2^T + b2
    gemm256<2><<<gg, bb>>>(hid, 256, W2, b2, nullptr, nullptr, xres, 0, xmlp);
    // pooled mean + classifier
    pool_cls_kernel<<<B_, bb>>>(xmlp, Wc, bc, out);
}

// round 2
// speedup vs baseline: 1.7298x; 1.7298x over previous
#include <cuda_runtime.h>
#include <math.h>

// ---------------------------------------------------------------------------
// Model dims
// ---------------------------------------------------------------------------
#define B_      64
#define N_      512
#define D_      256
#define H_      4
#define HD_     64
#define M_      (B_ * N_)         // 32768 rows
#define EPS_    1e-5f

// ---------------------------------------------------------------------------
// Scratch (static __device__ globals; no allocations allowed)
// ---------------------------------------------------------------------------
__device__ float g_xp  [M_ * D_];
__device__ float g_yp  [M_ * D_];
__device__ float g_q   [M_ * D_];
__device__ float g_k   [M_ * D_];
__device__ float g_v   [M_ * D_];
__device__ float g_ctx [M_ * D_];
__device__ float g_xres[M_ * D_];
__device__ float g_hid [M_ * D_];
__device__ float g_xmlp[M_ * D_];
__device__ float g_pe  [N_ * D_];

// ---------------------------------------------------------------------------
// Packed f32x2 helpers (sm_103a FFMA2 — only reachable via PTX)
// ---------------------------------------------------------------------------
__device__ __forceinline__ unsigned long long pk2(float lo, float hi) {
    unsigned long long r;
    asm("mov.b64 %0, {%1, %2};" : "=l"(r) : "f"(lo), "f"(hi));
    return r;
}
__device__ __forceinline__ void upk2(unsigned long long v, float& lo, float& hi) {
    asm("mov.b64 {%0, %1}, %2;" : "=f"(lo), "=f"(hi) : "l"(v));
}
__device__ __forceinline__ void ffma2(unsigned long long& acc,
                                      unsigned long long a,
                                      unsigned long long b) {
    asm("fma.rn.f32x2 %0, %1, %2, %0;" : "+l"(acc) : "l"(a), "l"(b));
}

// ---------------------------------------------------------------------------
// PE table fill (once per launch; graph-capturable kernel)
// ---------------------------------------------------------------------------
__global__ void pe_fill_kernel() {
    int idx = blockIdx.x * blockDim.x + threadIdx.x;   // over N_*D_
    int pos = idx >> 8;
    int c   = idx & 255;
    int i2  = c & ~1;
    float div = expf(-logf(10000.0f) * (float)i2 / (float)D_);
    float ang = (float)pos * div;
    g_pe[idx] = (c & 1) ? cosf(ang) : sinf(ang);
}

// ---------------------------------------------------------------------------
// GEMM: out[M x 256] = A[M x K] @ W[256 x K]^T  (+ epilogue)
// Block tile 64 x 256, BK=16, 256 threads, 8x8 per-thread microtile via
// packed f32x2 accumulators. Double-buffered smem.
// EPI: 0 = +bias ; 1 = relu(+bias) ; 2 = +bias+res ; 3 = LN(+bias [+pe] [+res])
// ---------------------------------------------------------------------------
template <int EPI>
__global__ __launch_bounds__(256) void gemm64x256(
    const float* __restrict__ A, int K,
    const float* __restrict__ W,
    const float* __restrict__ bias,
    const float* __restrict__ gamma,
    const float* __restrict__ beta,
    const float* __restrict__ res,
    const float* __restrict__ pe,
    float* __restrict__ out)
{
    __shared__ __align__(16) float As[2][16][68];
    __shared__ __align__(16) float Bs[2][16][260];

    const int tid  = threadIdx.x;
    const int lane = tid & 31;       // col thread: cols lane*4.. & 128+lane*4..
    const int warp = tid >> 5;       // row thread: rows warp*4.. & 32+warp*4..
    const int row0 = blockIdx.x * 64;

    // staging index maps
    const int am = tid >> 2;         // 0..63 : A row within tile
    const int ah = tid & 3;          // kk base = ah*4
    const float* Aptr = A + (size_t)(row0 + am) * K;
    const float* Wptr = W + (size_t)tid * K;     // tid = output column 0..255

    unsigned long long acc[8][4];    // 8 rows x 4 col-pairs (cols: lo0 lo1 hi0 hi1)
#pragma unroll
    for (int j = 0; j < 8; ++j)
#pragma unroll
        for (int p = 0; p < 4; ++p) acc[j][p] = 0ull;

    // ---- initial tile (k0 = 0) straight to smem
#pragma unroll
    for (int u = 0; u < 4; ++u) {
        int kk = ah * 4 + u;
        As[0][kk][am] = (kk < K) ? Aptr[kk] : 0.0f;
    }
#pragma unroll
    for (int kk = 0; kk < 16; ++kk)
        Bs[0][kk][tid] = (kk < K) ? Wptr[kk] : 0.0f;
    __syncthreads();

    int buf = 0;
    for (int k0 = 16; k0 < K; k0 += 16) {
        // prefetch next tile into registers
        float ra[4], rb[16];
#pragma unroll
        for (int u = 0; u < 4; ++u) {
            int kg = k0 + ah * 4 + u;
            ra[u] = (kg < K) ? Aptr[kg] : 0.0f;
        }
#pragma unroll
        for (int u = 0; u < 16; ++u) {
            int kg = k0 + u;
            rb[u] = (kg < K) ? Wptr[kg] : 0.0f;
        }
        // compute current tile
#pragma unroll
        for (int kk = 0; kk < 16; ++kk) {
            float4 a0 = *(const float4*)&As[buf][kk][warp * 4];
            float4 a1 = *(const float4*)&As[buf][kk][32 + warp * 4];
            ulonglong2 b0 = *(const ulonglong2*)&Bs[buf][kk][lane * 4];
            ulonglong2 b1 = *(const ulonglong2*)&Bs[buf][kk][128 + lane * 4];
            float ar[8] = {a0.x, a0.y, a0.z, a0.w, a1.x, a1.y, a1.z, a1.w};
#pragma unroll
            for (int j = 0; j < 8; ++j) {
                unsigned long long ad = pk2(ar[j], ar[j]);
                ffma2(acc[j][0], ad, b0.x);
                ffma2(acc[j][1], ad, b0.y);
                ffma2(acc[j][2], ad, b1.x);
                ffma2(acc[j][3], ad, b1.y);
            }
        }
        // store prefetched tile
#pragma unroll
        for (int u = 0; u < 4; ++u) As[buf ^ 1][ah * 4 + u][am] = ra[u];
#pragma unroll
        for (int u = 0; u < 16; ++u) Bs[buf ^ 1][u][tid] = rb[u];
        __syncthreads();
        buf ^= 1;
    }
    // last tile compute
#pragma unroll
    for (int kk = 0; kk < 16; ++kk) {
        float4 a0 = *(const float4*)&As[buf][kk][warp * 4];
        float4 a1 = *(const float4*)&As[buf][kk][32 + warp * 4];
        ulonglong2 b0 = *(const ulonglong2*)&Bs[buf][kk][lane * 4];
        ulonglong2 b1 = *(const ulonglong2*)&Bs[buf][kk][128 + lane * 4];
        float ar[8] = {a0.x, a0.y, a0.z, a0.w, a1.x, a1.y, a1.z, a1.w};
#pragma unroll
        for (int j = 0; j < 8; ++j) {
            unsigned long long ad = pk2(ar[j], ar[j]);
            ffma2(acc[j][0], ad, b0.x);
            ffma2(acc[j][1], ad, b0.y);
            ffma2(acc[j][2], ad, b1.x);
            ffma2(acc[j][3], ad, b1.y);
        }
    }

    const int cl = lane * 4;         // low col base
    const int ch = 128 + lane * 4;   // high col base

    // bias frags
    float blo[4], bhi[4];
#pragma unroll
    for (int i = 0; i < 4; ++i) { blo[i] = bias[cl + i]; bhi[i] = bias[ch + i]; }

#pragma unroll
    for (int j = 0; j < 8; ++j) {
        int r    = (j < 4) ? (warp * 4 + j) : (32 + warp * 4 + j - 4);
        int grow = row0 + r;
        float v[8];
        upk2(acc[j][0], v[0], v[1]);
        upk2(acc[j][1], v[2], v[3]);
        upk2(acc[j][2], v[4], v[5]);
        upk2(acc[j][3], v[6], v[7]);
#pragma unroll
        for (int i = 0; i < 4; ++i) { v[i] += blo[i]; v[4 + i] += bhi[i]; }

        if (EPI == 1) {
#pragma unroll
            for (int i = 0; i < 8; ++i) v[i] = fmaxf(v[i], 0.0f);
        }
        if (EPI == 2) {
            const float* rp = res + (size_t)grow * D_;
#pragma unroll
            for (int i = 0; i < 4; ++i) { v[i] += rp[cl + i]; v[4 + i] += rp[ch + i]; }
        }
        if (EPI == 3) {
            int pos = grow & (N_ - 1);
            if (pe) {
                const float* pp = pe + (size_t)pos * D_;
#pragma unroll
                for (int i = 0; i < 4; ++i) { v[i] += pp[cl + i]; v[4 + i] += pp[ch + i]; }
            }
            if (res) {
                const float* rp = res + (size_t)grow * D_;
#pragma unroll
                for (int i = 0; i < 4; ++i) { v[i] += rp[cl + i]; v[4 + i] += rp[ch + i]; }
            }
            // register LayerNorm: full 256-col row owned by this warp
            float sum = 0.0f, sq = 0.0f;
#pragma unroll
            for (int i = 0; i < 8; ++i) { sum += v[i]; sq = fmaf(v[i], v[i], sq); }
#pragma unroll
            for (int off = 16; off > 0; off >>= 1) {
                sum += __shfl_xor_sync(0xffffffffu, sum, off);
                sq  += __shfl_xor_sync(0xffffffffu, sq,  off);
            }
            float mu  = sum * (1.0f / 256.0f);
            float var = sq * (1.0f / 256.0f) - mu * mu;
            float rs  = rsqrtf(var + EPS_);
#pragma unroll
            for (int i = 0; i < 4; ++i) {
                v[i]     = (v[i]     - mu) * rs * gamma[cl + i] + beta[cl + i];
                v[4 + i] = (v[4 + i] - mu) * rs * gamma[ch + i] + beta[ch + i];
            }
        }
        float* op = out + (size_t)grow * D_;
        *(float4*)&op[cl] = make_float4(v[0], v[1], v[2], v[3]);
        *(float4*)&op[ch] = make_float4(v[4], v[5], v[6], v[7]);
    }
}

// ---------------------------------------------------------------------------
// Flash attention, 64q x 64kv tiles, hd=64. 256 threads:
//  cx = tid%16 (4 cols), ry = tid/16 (4 rows). Rows of S/O owned by the 16
//  lanes sharing ry (same half-warp) -> shfl reductions over 16 lanes.
// ---------------------------------------------------------------------------
__global__ __launch_bounds__(256) void attn_kernel(
    const float* __restrict__ q,
    const float* __restrict__ k,
    const float* __restrict__ v,
    float* __restrict__ ctx)
{
    extern __shared__ __align__(16) float sm[];
    float (*Qt)[68] = (float (*)[68])sm;                 // [64][68] kk-major
    float (*Kt)[68] = (float (*)[68])(sm + 64 * 68);     // [64][68] kk-major
    float (*Vs)[68] = (float (*)[68])(sm + 2 * 64 * 68); // [64][68] t-major
    float (*Ps)[68] = (float (*)[68])(sm + 3 * 64 * 68); // [64][68] Ps[t][r]

    const int tid = threadIdx.x;
    const int cx  = tid & 15;
    const int ry  = tid >> 4;
    const int bh  = blockIdx.y;
    const int b   = bh >> 2;
    const int h   = bh & 3;
    const int q0  = blockIdx.x * 64;

    // staging maps: r = tid/4 (tile row), seg = tid%4 (16 contiguous cols)
    const int sr = tid >> 2;
    const int sg = (tid & 3) * 16;

    // load Q (transposed -> Qt[kk][r])
    {
        const float* qp = q + ((size_t)(b * N_ + q0 + sr)) * D_ + h * HD_ + sg;
#pragma unroll
        for (int u = 0; u < 16; ++u) Qt[sg + u][sr] = qp[u];
    }

    float mrow[4], lrow[4];
    float o[4][4];
#pragma unroll
    for (int j = 0; j < 4; ++j) {
        mrow[j] = -1e30f; lrow[j] = 0.0f;
#pragma unroll
        for (int i = 0; i < 4; ++i) o[j][i] = 0.0f;
    }
    const float scale = 0.125f;   // 1/sqrt(64)

    for (int t0 = 0; t0 < N_; t0 += 64) {
        __syncthreads();   // prev PV done; Kt/Vs/Ps free
        {
            const float* kp = k + ((size_t)(b * N_ + t0 + sr)) * D_ + h * HD_ + sg;
            const float* vp = v + ((size_t)(b * N_ + t0 + sr)) * D_ + h * HD_ + sg;
#pragma unroll
            for (int u = 0; u < 16; ++u) {
                Kt[sg + u][sr] = kp[u];      // transposed
                Vs[sr][sg + u] = vp[u];      // natural
            }
        }
        __syncthreads();

        // S = Q K^T  (4x4 microtile)
        float s[4][4];
#pragma unroll
        for (int j = 0; j < 4; ++j)
#pragma unroll
            for (int i = 0; i < 4; ++i) s[j][i] = 0.0f;
#pragma unroll 8
        for (int kk = 0; kk < 64; ++kk) {
            float4 a = *(const float4*)&Qt[kk][ry * 4];
            float4 bb = *(const float4*)&Kt[kk][cx * 4];
            float av[4] = {a.x, a.y, a.z, a.w};
            float bv[4] = {bb.x, bb.y, bb.z, bb.w};
#pragma unroll
            for (int j = 0; j < 4; ++j)
#pragma unroll
                for (int i = 0; i < 4; ++i) s[j][i] = fmaf(av[j], bv[i], s[j][i]);
        }

        // online softmax per row
        float p[4][4];
#pragma unroll
        for (int j = 0; j < 4; ++j) {
            float mx = -1e30f;
#pragma unroll
            for (int i = 0; i < 4; ++i) { s[j][i] *= scale; mx = fmaxf(mx, s[j][i]); }
#pragma unroll
            for (int off = 1; off <= 8; off <<= 1)
                mx = fmaxf(mx, __shfl_xor_sync(0xffffffffu, mx, off));
            float mnew = fmaxf(mrow[j], mx);
            float corr = __expf(mrow[j] - mnew);
            float ps = 0.0f;
#pragma unroll
            for (int i = 0; i < 4; ++i) { p[j][i] = __expf(s[j][i] - mnew); ps += p[j][i]; }
#pragma unroll
            for (int off = 1; off <= 8; off <<= 1)
                ps += __shfl_xor_sync(0xffffffffu, ps, off);
            lrow[j] = lrow[j] * corr + ps;
            mrow[j] = mnew;
#pragma unroll
            for (int i = 0; i < 4; ++i) o[j][i] *= corr;
        }

        // stage P transposed: Ps[t][r]
#pragma unroll
        for (int j = 0; j < 4; ++j)
#pragma unroll
            for (int i = 0; i < 4; ++i) Ps[cx * 4 + i][ry * 4 + j] = p[j][i];
        __syncthreads();

        // O += P V
#pragma unroll 8
        for (int t = 0; t < 64; ++t) {
            float4 a = *(const float4*)&Ps[t][ry * 4];
            float4 bb = *(const float4*)&Vs[t][cx * 4];
            float av[4] = {a.x, a.y, a.z, a.w};
            float bv[4] = {bb.x, bb.y, bb.z, bb.w};
#pragma unroll
            for (int j = 0; j < 4; ++j)
#pragma unroll
                for (int i = 0; i < 4; ++i) o[j][i] = fmaf(av[j], bv[i], o[j][i]);
        }
    }

    // write ctx
#pragma unroll
    for (int j = 0; j < 4; ++j) {
        float inv = 1.0f / lrow[j];
        float* cp = ctx + ((size_t)(b * N_ + q0 + ry * 4 + j)) * D_ + h * HD_ + cx * 4;
        *(float4*)cp = make_float4(o[j][0] * inv, o[j][1] * inv,
                                   o[j][2] * inv, o[j][3] * inv);
    }
}

// ---------------------------------------------------------------------------
// mean-pool over N, then logits = pooled @ Wc^T + bc
// ---------------------------------------------------------------------------
__global__ __launch_bounds__(256) void pool_cls_kernel(
    const float* __restrict__ xm,
    const float* __restrict__ Wc,
    const float* __restrict__ bc,
    float* __restrict__ out)
{
    __shared__ float pooled[D_];
    const int b = blockIdx.x;
    const int t = threadIdx.x;
    float s = 0.0f;
    const float* p = xm + (size_t)b * N_ * D_ + t;
#pragma unroll 8
    for (int n = 0; n < N_; ++n) s += p[(size_t)n * D_];
    pooled[t] = s * (1.0f / (float)N_);
    __syncthreads();
    if (t < 2) {
        float a = bc[t];
        for (int c = 0; c < D_; ++c) a = fmaf(pooled[c], Wc[t * D_ + c], a);
        out[b * 2 + t] = a;
    }
}

// ---------------------------------------------------------------------------
// Launch
// ---------------------------------------------------------------------------
static float* sym(const void* s) {
    void* p = nullptr;
    cudaGetSymbolAddress(&p, s);
    return (float*)p;
}

extern "C" void kernel_launch(void* const* d_in, const int* in_sizes, int n_in,
                              void* d_out, int out_size)
{
    const float* x   = (const float*)d_in[0];
    const float* y   = (const float*)d_in[1];
    // d_in[2] = z (unused)
    const float* Wr  = (const float*)d_in[3];
    const float* br  = (const float*)d_in[4];
    const float* Wf  = (const float*)d_in[5];
    const float* bf  = (const float*)d_in[6];
    const float* g_x = (const float*)d_in[7];
    const float* b_x = (const float*)d_in[8];
    const float* g_y = (const float*)d_in[9];
    const float* b_y = (const float*)d_in[10];
    const float* Wq  = (const float*)d_in[11];
    const float* bq  = (const float*)d_in[12];
    const float* Wk  = (const float*)d_in[13];
    const float* bk  = (const float*)d_in[14];
    const float* Wv  = (const float*)d_in[15];
    const float* bv  = (const float*)d_in[16];
    const float* Wo  = (const float*)d_in[17];
    const float* bo  = (const float*)d_in[18];
    const float* g_m = (const float*)d_in[19];
    const float* b_m = (const float*)d_in[20];
    const float* W1  = (const float*)d_in[21];
    const float* b1  = (const float*)d_in[22];
    const float* W2  = (const float*)d_in[23];
    const float* b2  = (const float*)d_in[24];
    const float* Wc  = (const float*)d_in[25];
    const float* bc  = (const float*)d_in[26];
    float* out = (float*)d_out;

    float* xp   = sym(g_xp);
    float* yp   = sym(g_yp);
    float* qb   = sym(g_q);
    float* kb   = sym(g_k);
    float* vb   = sym(g_v);
    float* ctx  = sym(g_ctx);
    float* xres = sym(g_xres);
    float* hid  = sym(g_hid);
    float* xmlp = sym(g_xmlp);
    float* pe   = sym(g_pe);

    static bool attr_set = false;
    if (!attr_set) {
        cudaFuncSetAttribute(attn_kernel,
                             cudaFuncAttributeMaxDynamicSharedMemorySize,
                             4 * 64 * 68 * sizeof(float));
        attr_set = true;
    }

    dim3 gg(M_ / 64);
    dim3 bb(256);

    pe_fill_kernel<<<N_ * D_ / 256, 256>>>();

    // xp = LN(x @ Wr^T + br + pe)
    gemm64x256<3><<<gg, bb>>>(x, 769, Wr, br, g_x, b_x, nullptr, pe, xp);
    // yp = LN(y @ Wf^T + bf + pe)
    gemm64x256<3><<<gg, bb>>>(y, 674, Wf, bf, g_y, b_y, nullptr, pe, yp);
    // q,k,v
    gemm64x256<0><<<gg, bb>>>(xp, 256, Wq, bq, nullptr, nullptr, nullptr, nullptr, qb);
    gemm64x256<0><<<gg, bb>>>(yp, 256, Wk, bk, nullptr, nullptr, nullptr, nullptr, kb);
    gemm64x256<0><<<gg, bb>>>(yp, 256, Wv, bv, nullptr, nullptr, nullptr, nullptr, vb);
    // attention
    dim3 ag(N_ / 64, B_ * H_);
    attn_kernel<<<ag, bb, 4 * 64 * 68 * sizeof(float)>>>(qb, kb, vb, ctx);
    // x_res = LN(xp + ctx @ Wo^T + bo)
    gemm64x256<3><<<gg, bb>>>(ctx, 256, Wo, bo, g_m, b_m, xp, nullptr, xres);
    // hid = relu(x_res @ W1^T + b1)
    gemm64x256<1><<<gg, bb>>>(xres, 256, W1, b1, nullptr, nullptr, nullptr, nullptr, hid);
    // xmlp = x_res + hid @ W2^T + b2
    gemm64x256<2><<<gg, bb>>>(hid, 256, W2, b2, nullptr, nullptr, xres, nullptr, xmlp);
    // pooled mean + classifier
    pool_cls_kernel<<<B_, bb>>>(xmlp, Wc, bc, out);
}

// round 5
// speedup vs baseline: 2.9726x; 1.7185x over previous
#include <cuda_runtime.h>
#include <cuda_bf16.h>
#include <math.h>
#include <stdint.h>

// ---------------------------------------------------------------------------
// Model dims
// ---------------------------------------------------------------------------
#define B_      64
#define N_      512
#define D_      256
#define H_      4
#define HD_     64
#define M_      (B_ * N_)         // 32768 rows
#define EPS_    1e-5f

// ---------------------------------------------------------------------------
// Scratch (static __device__ globals; no allocations allowed)
// ---------------------------------------------------------------------------
__device__ float g_xp  [M_ * D_];
__device__ float g_yp  [M_ * D_];
__device__ float g_q   [M_ * D_];
__device__ float g_k   [M_ * D_];
__device__ float g_v   [M_ * D_];
__device__ float g_ctx [M_ * D_];
__device__ float g_xres[M_ * D_];
__device__ float g_hid [M_ * D_];
__device__ float g_xmlp[M_ * D_];
__device__ float g_pe  [N_ * D_];

// bf16 hi/lo weight scratch (u32 words; per 32-k chunk: 16 hi-words, 16 lo-words)
// rowU32 = nc*32. Wr nc=25 -> 800/row ; Wf nc=22 -> 704 ; others nc=8 -> 256
#define WR_OFF  0
#define WF_OFF  (WR_OFF + 256 * 800)
#define WQ_OFF  (WF_OFF + 256 * 704)
#define WK_OFF  (WQ_OFF + 256 * 256)
#define WV_OFF  (WK_OFF + 256 * 256)
#define WO_OFF  (WV_OFF + 256 * 256)
#define W1_OFF  (WO_OFF + 256 * 256)
#define W2_OFF  (W1_OFF + 256 * 256)
#define WB_TOT  (W2_OFF + 256 * 256)
__device__ uint32_t g_wbuf[WB_TOT];

// ---------------------------------------------------------------------------
// hi = truncation of x to bf16 (exact; lo = x - hi fits bf16 with tiny error)
// ---------------------------------------------------------------------------
__device__ __forceinline__ uint32_t hi_pair(float x0, float x1) {
    uint32_t a = __float_as_uint(x0), b = __float_as_uint(x1);
    return (b & 0xffff0000u) | (a >> 16);
}
__device__ __forceinline__ uint32_t lo_pair(float x0, float x1) {
    float l0 = x0 - __uint_as_float(__float_as_uint(x0) & 0xffff0000u);
    float l1 = x1 - __uint_as_float(__float_as_uint(x1) & 0xffff0000u);
    uint32_t a = (uint32_t)__bfloat16_as_ushort(__float2bfloat16(l0));
    uint32_t b = (uint32_t)__bfloat16_as_ushort(__float2bfloat16(l1));
    return (b << 16) | a;
}

__device__ __forceinline__ uint32_t smem_u32(const void* p) {
    uint32_t a;
    asm("{ .reg .u64 t; cvta.to.shared.u64 t, %1; cvt.u32.u64 %0, t; }"
        : "=r"(a) : "l"(p));
    return a;
}

#define LDMX4(r0, r1, r2, r3, addr) \
    asm volatile("ldmatrix.sync.aligned.m8n8.x4.shared.b16 {%0,%1,%2,%3}, [%4];" \
                 : "=r"(r0), "=r"(r1), "=r"(r2), "=r"(r3) : "r"(addr))

#define MMA_BF16(c, a, b0, b1) \
    asm volatile("mma.sync.aligned.m16n8k16.row.col.f32.bf16.bf16.f32 " \
                 "{%0,%1,%2,%3}, {%4,%5,%6,%7}, {%8,%9}, {%0,%1,%2,%3};" \
                 : "+f"((c)[0]), "+f"((c)[1]), "+f"((c)[2]), "+f"((c)[3]) \
                 : "r"((a)[0]), "r"((a)[1]), "r"((a)[2]), "r"((a)[3]), \
                   "r"(b0), "r"(b1))

// ---------------------------------------------------------------------------
// PE table fill
// ---------------------------------------------------------------------------
__global__ void pe_fill_kernel() {
    int idx = blockIdx.x * blockDim.x + threadIdx.x;
    int pos = idx >> 8;
    int c   = idx & 255;
    int i2  = c & ~1;
    float div = expf(-logf(10000.0f) * (float)i2 / (float)D_);
    float ang = (float)pos * div;
    g_pe[idx] = (c & 1) ? cosf(ang) : sinf(ang);
}

// ---------------------------------------------------------------------------
// Weight -> bf16 hi/lo conversion.
// Word j in a row: chunk c = j/32, t = j%32. t<16: hi word of elements
// (c*32+2t, +1) ; t>=16: lo word of elements (c*32+2(t-16), +1).
// ---------------------------------------------------------------------------
__global__ void wconv_kernel(const float* __restrict__ W, int K, int rowU32,
                             int dstOff) {
    int idx = blockIdx.x * blockDim.x + threadIdx.x;
    if (idx >= 256 * rowU32) return;
    int row = idx / rowU32;
    int j   = idx - row * rowU32;
    int c   = j >> 5;
    int t   = j & 31;
    int e0  = c * 32 + ((t & 15) << 1);
    float v0 = (e0     < K) ? W[(size_t)row * K + e0]     : 0.0f;
    float v1 = (e0 + 1 < K) ? W[(size_t)row * K + e0 + 1] : 0.0f;
    g_wbuf[dstOff + idx] = (t < 16) ? hi_pair(v0, v1) : lo_pair(v0, v1);
}

// ---------------------------------------------------------------------------
// HMMA GEMM (bf16x3): out[M x 256] = A[M x K] @ W[256 x K]^T (+ epilogue)
// acc = A_hi*W_hi + A_lo*W_hi + A_hi*W_lo. CTA tile 128x256, 8 warps (2x4),
// warp tile 64x64. Chunk = 32 k: smem row = [hi(32 bf16) | lo(32 bf16) | pad]
// -> 144B stride (16 mod 128: conflict-free ldmatrix).
// EPI: 0=+bias 1=relu(+bias) 2=+bias+res 3=LN(+bias[+pe][+res])
// ---------------------------------------------------------------------------
#define ROWB   144
#define SM_B   0                          // B tile: 256 rows
#define SM_A   (256 * ROWB)               // A tile: 128 rows
#define SM_TOT (SM_A + 128 * ROWB)        // 55296 B

template <int EPI>
__global__ __launch_bounds__(256) void hmma_gemm(
    const float* __restrict__ A, int K, int NC,
    const uint32_t* __restrict__ Wbf, int rowU32,
    const float* __restrict__ bias,
    const float* __restrict__ gamma,
    const float* __restrict__ beta,
    const float* __restrict__ res,
    const float* __restrict__ pe,
    float* __restrict__ out)
{
    extern __shared__ __align__(16) char sm[];
    const uint32_t smb = smem_u32(sm);
    const int tid  = threadIdx.x;
    const int lane = tid & 31;
    const int warp = tid >> 5;
    const int wr   = warp >> 2;        // 0..1 : row 64-block
    const int wc   = warp & 3;         // 0..3 : col 64-block
    const int row0 = blockIdx.x * 128;

    // staging maps
    const int arow  = tid >> 1;        // 0..127
    const int ahalf = tid & 1;         // 16 k each
    const float* Ap = A + (size_t)(row0 + arow) * K + ahalf * 16;
    const uint32_t* Wp = Wbf + (size_t)tid * rowU32;

    float acc[4][8][4];
#pragma unroll
    for (int mt = 0; mt < 4; ++mt)
#pragma unroll
        for (int nt = 0; nt < 8; ++nt)
#pragma unroll
            for (int i = 0; i < 4; ++i) acc[mt][nt][i] = 0.0f;

    // ldmatrix base addresses (validated layout from R4)
    const uint32_t a_base = smb + SM_A
        + (uint32_t)(wr * 64 + (lane & 15)) * ROWB + (uint32_t)(lane >> 4) * 16;
    const uint32_t b_base = smb + SM_B
        + (uint32_t)(wc * 64 + ((lane >> 4) << 3) + (lane & 7)) * ROWB
        + (uint32_t)((lane >> 3) & 1) * 16;

    for (int c = 0; c < NC; ++c) {
        const int k0 = c * 32;
        __syncthreads();
        // --- stage A half-row: 16 f32 -> hi 8 u32 + lo 8 u32
        {
            float f[16];
#pragma unroll
            for (int j = 0; j < 16; ++j) {
                int kg = k0 + ahalf * 16 + j;
                f[j] = (kg < K) ? Ap[k0 + j] : 0.0f;
            }
            uint32_t hw[8], lw[8];
#pragma unroll
            for (int w = 0; w < 8; ++w) {
                hw[w] = hi_pair(f[2*w], f[2*w+1]);
                lw[w] = lo_pair(f[2*w], f[2*w+1]);
            }
            char* dh = sm + SM_A + arow * ROWB + ahalf * 32;       // hi block
            char* dl = dh + 64;                                    // lo block
#pragma unroll
            for (int g2 = 0; g2 < 2; ++g2) {
                *(uint4*)(dh + g2 * 16) =
                    make_uint4(hw[4*g2], hw[4*g2+1], hw[4*g2+2], hw[4*g2+3]);
                *(uint4*)(dl + g2 * 16) =
                    make_uint4(lw[4*g2], lw[4*g2+1], lw[4*g2+2], lw[4*g2+3]);
            }
        }
        // --- stage B row: copy 32 u32 (hi16+lo16 words) per chunk
        {
            const uint4* src = (const uint4*)(Wp + c * 32);
            char* dst = sm + SM_B + tid * ROWB;
#pragma unroll
            for (int g2 = 0; g2 < 8; ++g2)
                *(uint4*)(dst + g2 * 16) = src[g2];
        }
        __syncthreads();

        // --- 2 k16 steps, 3-term MMA each
#pragma unroll
        for (int ks = 0; ks < 2; ++ks) {
            uint32_t ah[4][4], al[4][4];
#pragma unroll
            for (int mt = 0; mt < 4; ++mt) {
                LDMX4(ah[mt][0], ah[mt][1], ah[mt][2], ah[mt][3],
                      a_base + mt * (16 * ROWB) + ks * 32);
                LDMX4(al[mt][0], al[mt][1], al[mt][2], al[mt][3],
                      a_base + mt * (16 * ROWB) + ks * 32 + 64);
            }
#pragma unroll
            for (int np = 0; np < 4; ++np) {
                uint32_t bh[4], bl[4];
                LDMX4(bh[0], bh[1], bh[2], bh[3],
                      b_base + np * (16 * ROWB) + ks * 32);
                LDMX4(bl[0], bl[1], bl[2], bl[3],
                      b_base + np * (16 * ROWB) + ks * 32 + 64);
#pragma unroll
                for (int mt = 0; mt < 4; ++mt) {
                    MMA_BF16(acc[mt][2*np],     ah[mt], bh[0], bh[1]);
                    MMA_BF16(acc[mt][2*np],     al[mt], bh[0], bh[1]);
                    MMA_BF16(acc[mt][2*np],     ah[mt], bl[0], bl[1]);
                    MMA_BF16(acc[mt][2*np + 1], ah[mt], bh[2], bh[3]);
                    MMA_BF16(acc[mt][2*np + 1], al[mt], bh[2], bh[3]);
                    MMA_BF16(acc[mt][2*np + 1], ah[mt], bl[2], bl[3]);
                }
            }
        }
    }
    __syncthreads();   // smem free for LN buffer

    // ---------------- epilogue ----------------
    const int g  = lane >> 2;
    const int t4 = lane & 3;

#pragma unroll
    for (int nt = 0; nt < 8; ++nt) {
        int cc = wc * 64 + nt * 8 + t4 * 2;
        float b0 = bias[cc], b1 = bias[cc + 1];
#pragma unroll
        for (int mt = 0; mt < 4; ++mt) {
            acc[mt][nt][0] += b0; acc[mt][nt][1] += b1;
            acc[mt][nt][2] += b0; acc[mt][nt][3] += b1;
        }
    }
    if (EPI == 3) {
#pragma unroll
        for (int mt = 0; mt < 4; ++mt)
#pragma unroll
            for (int h = 0; h < 2; ++h) {
                int row  = wr * 64 + mt * 16 + g + h * 8;
                int grow = row0 + row;
                if (pe) {
                    const float* pp = pe + (size_t)(grow & (N_ - 1)) * D_;
#pragma unroll
                    for (int nt = 0; nt < 8; ++nt) {
                        int cc = wc * 64 + nt * 8 + t4 * 2;
                        float2 pv = *(const float2*)&pp[cc];
                        acc[mt][nt][h*2]   += pv.x;
                        acc[mt][nt][h*2+1] += pv.y;
                    }
                }
                if (res) {
                    const float* rp = res + (size_t)grow * D_;
#pragma unroll
                    for (int nt = 0; nt < 8; ++nt) {
                        int cc = wc * 64 + nt * 8 + t4 * 2;
                        float2 rv = *(const float2*)&rp[cc];
                        acc[mt][nt][h*2]   += rv.x;
                        acc[mt][nt][h*2+1] += rv.y;
                    }
                }
            }

        float* lnsum = (float*)sm;          // [128][4]
        float* lnsq  = (float*)sm + 512;    // [128][4]
#pragma unroll
        for (int mt = 0; mt < 4; ++mt)
#pragma unroll
            for (int h = 0; h < 2; ++h) {
                float s = 0.0f, q = 0.0f;
#pragma unroll
                for (int nt = 0; nt < 8; ++nt) {
                    float v0 = acc[mt][nt][h*2], v1 = acc[mt][nt][h*2+1];
                    s += v0 + v1;
                    q = fmaf(v0, v0, q); q = fmaf(v1, v1, q);
                }
#pragma unroll
                for (int off = 1; off <= 2; off <<= 1) {
                    s += __shfl_xor_sync(0xffffffffu, s, off);
                    q += __shfl_xor_sync(0xffffffffu, q, off);
                }
                if (t4 == 0) {
                    int row = wr * 64 + mt * 16 + g + h * 8;
                    lnsum[row * 4 + wc] = s;
                    lnsq [row * 4 + wc] = q;
                }
            }
        __syncthreads();

#pragma unroll
        for (int mt = 0; mt < 4; ++mt)
#pragma unroll
            for (int h = 0; h < 2; ++h) {
                int row  = wr * 64 + mt * 16 + g + h * 8;
                int grow = row0 + row;
                float s = lnsum[row*4] + lnsum[row*4+1] + lnsum[row*4+2] + lnsum[row*4+3];
                float q = lnsq [row*4] + lnsq [row*4+1] + lnsq [row*4+2] + lnsq [row*4+3];
                float mu  = s * (1.0f / 256.0f);
                float var = q * (1.0f / 256.0f) - mu * mu;
                float rs  = rsqrtf(var + EPS_);
                float* op = out + (size_t)grow * D_;
#pragma unroll
                for (int nt = 0; nt < 8; ++nt) {
                    int cc = wc * 64 + nt * 8 + t4 * 2;
                    float v0 = (acc[mt][nt][h*2]   - mu) * rs * gamma[cc]   + beta[cc];
                    float v1 = (acc[mt][nt][h*2+1] - mu) * rs * gamma[cc+1] + beta[cc+1];
                    *(float2*)&op[cc] = make_float2(v0, v1);
                }
            }
    } else {
#pragma unroll
        for (int mt = 0; mt < 4; ++mt)
#pragma unroll
            for (int h = 0; h < 2; ++h) {
                int row  = wr * 64 + mt * 16 + g + h * 8;
                int grow = row0 + row;
                const float* rp = (EPI == 2) ? res + (size_t)grow * D_ : nullptr;
                float* op = out + (size_t)grow * D_;
#pragma unroll
                for (int nt = 0; nt < 8; ++nt) {
                    int cc = wc * 64 + nt * 8 + t4 * 2;
                    float v0 = acc[mt][nt][h*2];
                    float v1 = acc[mt][nt][h*2+1];
                    if (EPI == 1) { v0 = fmaxf(v0, 0.0f); v1 = fmaxf(v1, 0.0f); }
                    if (EPI == 2) {
                        float2 rv = *(const float2*)&rp[cc];
                        v0 += rv.x; v1 += rv.y;
                    }
                    *(float2*)&op[cc] = make_float2(v0, v1);
                }
            }
    }
}

// ---------------------------------------------------------------------------
// Flash attention (SIMT, validated): 64q x 64kv tiles, hd=64
// ---------------------------------------------------------------------------
__global__ __launch_bounds__(256) void attn_kernel(
    const float* __restrict__ q,
    const float* __restrict__ k,
    const float* __restrict__ v,
    float* __restrict__ ctx)
{
    extern __shared__ __align__(16) float smf[];
    float (*Qt)[68] = (float (*)[68])smf;
    float (*Kt)[68] = (float (*)[68])(smf + 64 * 68);
    float (*Vs)[68] = (float (*)[68])(smf + 2 * 64 * 68);
    float (*Ps)[68] = (float (*)[68])(smf + 3 * 64 * 68);

    const int tid = threadIdx.x;
    const int cx  = tid & 15;
    const int ry  = tid >> 4;
    const int bh  = blockIdx.y;
    const int b   = bh >> 2;
    const int h   = bh & 3;
    const int q0  = blockIdx.x * 64;

    const int sr = tid >> 2;
    const int sg = (tid & 3) * 16;

    {
        const float* qp = q + ((size_t)(b * N_ + q0 + sr)) * D_ + h * HD_ + sg;
#pragma unroll
        for (int u = 0; u < 16; ++u) Qt[sg + u][sr] = qp[u];
    }

    float mrow[4], lrow[4];
    float o[4][4];
#pragma unroll
    for (int j = 0; j < 4; ++j) {
        mrow[j] = -1e30f; lrow[j] = 0.0f;
#pragma unroll
        for (int i = 0; i < 4; ++i) o[j][i] = 0.0f;
    }
    const float scale = 0.125f;

    for (int t0 = 0; t0 < N_; t0 += 64) {
        __syncthreads();
        {
            const float* kp = k + ((size_t)(b * N_ + t0 + sr)) * D_ + h * HD_ + sg;
            const float* vp = v + ((size_t)(b * N_ + t0 + sr)) * D_ + h * HD_ + sg;
#pragma unroll
            for (int u = 0; u < 16; ++u) {
                Kt[sg + u][sr] = kp[u];
                Vs[sr][sg + u] = vp[u];
            }
        }
        __syncthreads();

        float s[4][4];
#pragma unroll
        for (int j = 0; j < 4; ++j)
#pragma unroll
            for (int i = 0; i < 4; ++i) s[j][i] = 0.0f;
#pragma unroll 8
        for (int kk = 0; kk < 64; ++kk) {
            float4 a = *(const float4*)&Qt[kk][ry * 4];
            float4 bb = *(const float4*)&Kt[kk][cx * 4];
            float av[4] = {a.x, a.y, a.z, a.w};
            float bv[4] = {bb.x, bb.y, bb.z, bb.w};
#pragma unroll
            for (int j = 0; j < 4; ++j)
#pragma unroll
                for (int i = 0; i < 4; ++i) s[j][i] = fmaf(av[j], bv[i], s[j][i]);
        }

        float p[4][4];
#pragma unroll
        for (int j = 0; j < 4; ++j) {
            float mx = -1e30f;
#pragma unroll
            for (int i = 0; i < 4; ++i) { s[j][i] *= scale; mx = fmaxf(mx, s[j][i]); }
#pragma unroll
            for (int off = 1; off <= 8; off <<= 1)
                mx = fmaxf(mx, __shfl_xor_sync(0xffffffffu, mx, off));
            float mnew = fmaxf(mrow[j], mx);
            float corr = __expf(mrow[j] - mnew);
            float ps = 0.0f;
#pragma unroll
            for (int i = 0; i < 4; ++i) { p[j][i] = __expf(s[j][i] - mnew); ps += p[j][i]; }
#pragma unroll
            for (int off = 1; off <= 8; off <<= 1)
                ps += __shfl_xor_sync(0xffffffffu, ps, off);
            lrow[j] = lrow[j] * corr + ps;
            mrow[j] = mnew;
#pragma unroll
            for (int i = 0; i < 4; ++i) o[j][i] *= corr;
        }

#pragma unroll
        for (int j = 0; j < 4; ++j)
#pragma unroll
            for (int i = 0; i < 4; ++i) Ps[cx * 4 + i][ry * 4 + j] = p[j][i];
        __syncthreads();

#pragma unroll 8
        for (int t = 0; t < 64; ++t) {
            float4 a = *(const float4*)&Ps[t][ry * 4];
            float4 bb = *(const float4*)&Vs[t][cx * 4];
            float av[4] = {a.x, a.y, a.z, a.w};
            float bv[4] = {bb.x, bb.y, bb.z, bb.w};
#pragma unroll
            for (int j = 0; j < 4; ++j)
#pragma unroll
                for (int i = 0; i < 4; ++i) o[j][i] = fmaf(av[j], bv[i], o[j][i]);
        }
    }

#pragma unroll
    for (int j = 0; j < 4; ++j) {
        float inv = 1.0f / lrow[j];
        float* cp = ctx + ((size_t)(b * N_ + q0 + ry * 4 + j)) * D_ + h * HD_ + cx * 4;
        *(float4*)cp = make_float4(o[j][0] * inv, o[j][1] * inv,
                                   o[j][2] * inv, o[j][3] * inv);
    }
}

// ---------------------------------------------------------------------------
// mean-pool + classifier
// ---------------------------------------------------------------------------
__global__ __launch_bounds__(256) void pool_cls_kernel(
    const float* __restrict__ xm,
    const float* __restrict__ Wc,
    const float* __restrict__ bc,
    float* __restrict__ out)
{
    __shared__ float pooled[D_];
    const int b = blockIdx.x;
    const int t = threadIdx.x;
    float s = 0.0f;
    const float* p = xm + (size_t)b * N_ * D_ + t;
#pragma unroll 8
    for (int n = 0; n < N_; ++n) s += p[(size_t)n * D_];
    pooled[t] = s * (1.0f / (float)N_);
    __syncthreads();
    if (t < 2) {
        float a = bc[t];
        for (int c = 0; c < D_; ++c) a = fmaf(pooled[c], Wc[t * D_ + c], a);
        out[b * 2 + t] = a;
    }
}

// ---------------------------------------------------------------------------
// Launch
// ---------------------------------------------------------------------------
static float* sym(const void* s) {
    void* p = nullptr;
    cudaGetSymbolAddress(&p, s);
    return (float*)p;
}

extern "C" void kernel_launch(void* const* d_in, const int* in_sizes, int n_in,
                              void* d_out, int out_size)
{
    const float* x   = (const float*)d_in[0];
    const float* y   = (const float*)d_in[1];
    const float* Wr  = (const float*)d_in[3];
    const float* br  = (const float*)d_in[4];
    const float* Wf  = (const float*)d_in[5];
    const float* bf  = (const float*)d_in[6];
    const float* g_x = (const float*)d_in[7];
    const float* b_x = (const float*)d_in[8];
    const float* g_y = (const float*)d_in[9];
    const float* b_y = (const float*)d_in[10];
    const float* Wq  = (const float*)d_in[11];
    const float* bq  = (const float*)d_in[12];
    const float* Wk  = (const float*)d_in[13];
    const float* bk  = (const float*)d_in[14];
    const float* Wv  = (const float*)d_in[15];
    const float* bv  = (const float*)d_in[16];
    const float* Wo  = (const float*)d_in[17];
    const float* bo  = (const float*)d_in[18];
    const float* g_m = (const float*)d_in[19];
    const float* b_m = (const float*)d_in[20];
    const float* W1  = (const float*)d_in[21];
    const float* b1  = (const float*)d_in[22];
    const float* W2  = (const float*)d_in[23];
    const float* b2  = (const float*)d_in[24];
    const float* Wc  = (const float*)d_in[25];
    const float* bc  = (const float*)d_in[26];
    float* out = (float*)d_out;

    float* xp   = sym(g_xp);
    float* yp   = sym(g_yp);
    float* qb   = sym(g_q);
    float* kb   = sym(g_k);
    float* vb   = sym(g_v);
    float* ctx  = sym(g_ctx);
    float* xres = sym(g_xres);
    float* hid  = sym(g_hid);
    float* xmlp = sym(g_xmlp);
    float* pe   = sym(g_pe);
    uint32_t* wb;
    {
        void* p = nullptr;
        cudaGetSymbolAddress(&p, g_wbuf);
        wb = (uint32_t*)p;
    }

    static bool attr_set = false;
    if (!attr_set) {
        cudaFuncSetAttribute(attn_kernel,
                             cudaFuncAttributeMaxDynamicSharedMemorySize,
                             4 * 64 * 68 * sizeof(float));
        cudaFuncSetAttribute(hmma_gemm<0>,
                             cudaFuncAttributeMaxDynamicSharedMemorySize, SM_TOT);
        cudaFuncSetAttribute(hmma_gemm<1>,
                             cudaFuncAttributeMaxDynamicSharedMemorySize, SM_TOT);
        cudaFuncSetAttribute(hmma_gemm<2>,
                             cudaFuncAttributeMaxDynamicSharedMemorySize, SM_TOT);
        cudaFuncSetAttribute(hmma_gemm<3>,
                             cudaFuncAttributeMaxDynamicSharedMemorySize, SM_TOT);
        attr_set = true;
    }

    dim3 gg(M_ / 128);    // 256 CTAs
    dim3 bb(256);

    pe_fill_kernel<<<N_ * D_ / 256, 256>>>();

    // weight hi/lo conversions
    wconv_kernel<<<(256*800 + 255)/256, 256>>>(Wr, 769, 800, WR_OFF);
    wconv_kernel<<<(256*704 + 255)/256, 256>>>(Wf, 674, 704, WF_OFF);
    wconv_kernel<<<(256*256 + 255)/256, 256>>>(Wq, 256, 256, WQ_OFF);
    wconv_kernel<<<(256*256 + 255)/256, 256>>>(Wk, 256, 256, WK_OFF);
    wconv_kernel<<<(256*256 + 255)/256, 256>>>(Wv, 256, 256, WV_OFF);
    wconv_kernel<<<(256*256 + 255)/256, 256>>>(Wo, 256, 256, WO_OFF);
    wconv_kernel<<<(256*256 + 255)/256, 256>>>(W1, 256, 256, W1_OFF);
    wconv_kernel<<<(256*256 + 255)/256, 256>>>(W2, 256, 256, W2_OFF);

    // xp = LN(x @ Wr^T + br + pe)
    hmma_gemm<3><<<gg, bb, SM_TOT>>>(x, 769, 25, wb + WR_OFF, 800,
                                     br, g_x, b_x, nullptr, pe, xp);
    // yp = LN(y @ Wf^T + bf + pe)
    hmma_gemm<3><<<gg, bb, SM_TOT>>>(y, 674, 22, wb + WF_OFF, 704,
                                     bf, g_y, b_y, nullptr, pe, yp);
    // q,k,v
    hmma_gemm<0><<<gg, bb, SM_TOT>>>(xp, 256, 8, wb + WQ_OFF, 256,
                                     bq, nullptr, nullptr, nullptr, nullptr, qb);
    hmma_gemm<0><<<gg, bb, SM_TOT>>>(yp, 256, 8, wb + WK_OFF, 256,
                                     bk, nullptr, nullptr, nullptr, nullptr, kb);
    hmma_gemm<0><<<gg, bb, SM_TOT>>>(yp, 256, 8, wb + WV_OFF, 256,
                                     bv, nullptr, nullptr, nullptr, nullptr, vb);
    // attention
    dim3 ag(N_ / 64, B_ * H_);
    attn_kernel<<<ag, bb, 4 * 64 * 68 * sizeof(float)>>>(qb, kb, vb, ctx);
    // x_res = LN(xp + ctx @ Wo^T + bo)
    hmma_gemm<3><<<gg, bb, SM_TOT>>>(ctx, 256, 8, wb + WO_OFF, 256,
                                     bo, g_m, b_m, xp, nullptr, xres);
    // hid = relu(x_res @ W1^T + b1)
    hmma_gemm<1><<<gg, bb, SM_TOT>>>(xres, 256, 8, wb + W1_OFF, 256,
                                     b1, nullptr, nullptr, nullptr, nullptr, hid);
    // xmlp = x_res + hid @ W2^T + b2
    hmma_gemm<2><<<gg, bb, SM_TOT>>>(hid, 256, 8, wb + W2_OFF, 256,
                                     b2, nullptr, nullptr, xres, nullptr, xmlp);
    // pool + classifier
    pool_cls_kernel<<<B_, bb>>>(xmlp, Wc, bc, out);
}

// round 7
// speedup vs baseline: 3.3367x; 1.1225x over previous
#include <cuda_runtime.h>
#include <cuda_bf16.h>
#include <math.h>
#include <stdint.h>

// ---------------------------------------------------------------------------
// Model dims
// ---------------------------------------------------------------------------
#define B_      64
#define N_      512
#define D_      256
#define H_      4
#define HD_     64
#define M_      (B_ * N_)         // 32768 rows
#define EPS_    1e-5f

// ---------------------------------------------------------------------------
// Scratch
// ---------------------------------------------------------------------------
__device__ float g_xp  [M_ * D_];
__device__ float g_yp  [M_ * D_];
__device__ float g_q   [M_ * D_];
__device__ float g_k   [M_ * D_];
__device__ float g_v   [M_ * D_];
__device__ float g_ctx [M_ * D_];
__device__ float g_xres[M_ * D_];
__device__ float g_hid [M_ * D_];
__device__ float g_xmlp[M_ * D_];
__device__ float g_pe  [N_ * D_];

// bf16 hi/lo weight scratch
#define WR_OFF  0
#define WF_OFF  (WR_OFF + 256 * 800)
#define WQ_OFF  (WF_OFF + 256 * 704)
#define WK_OFF  (WQ_OFF + 256 * 256)
#define WV_OFF  (WK_OFF + 256 * 256)
#define WO_OFF  (WV_OFF + 256 * 256)
#define W1_OFF  (WO_OFF + 256 * 256)
#define W2_OFF  (W1_OFF + 256 * 256)
#define WB_TOT  (W2_OFF + 256 * 256)
__device__ uint32_t g_wbuf[WB_TOT];

// ---------------------------------------------------------------------------
// hi = truncation to bf16 (exact); lo = rn-bf16(x - hi)
// ---------------------------------------------------------------------------
__device__ __forceinline__ uint32_t hi_pair(float x0, float x1) {
    uint32_t a = __float_as_uint(x0), b = __float_as_uint(x1);
    return (b & 0xffff0000u) | (a >> 16);
}
__device__ __forceinline__ uint32_t lo_pair(float x0, float x1) {
    float l0 = x0 - __uint_as_float(__float_as_uint(x0) & 0xffff0000u);
    float l1 = x1 - __uint_as_float(__float_as_uint(x1) & 0xffff0000u);
    uint32_t a = (uint32_t)__bfloat16_as_ushort(__float2bfloat16(l0));
    uint32_t b = (uint32_t)__bfloat16_as_ushort(__float2bfloat16(l1));
    return (b << 16) | a;
}

__device__ __forceinline__ uint32_t smem_u32(const void* p) {
    uint32_t a;
    asm("{ .reg .u64 t; cvta.to.shared.u64 t, %1; cvt.u32.u64 %0, t; }"
        : "=r"(a) : "l"(p));
    return a;
}

#define LDMX4(r0, r1, r2, r3, addr) \
    asm volatile("ldmatrix.sync.aligned.m8n8.x4.shared.b16 {%0,%1,%2,%3}, [%4];" \
                 : "=r"(r0), "=r"(r1), "=r"(r2), "=r"(r3) : "r"(addr))

#define MMA_BF16(c, a, b0, b1) \
    asm volatile("mma.sync.aligned.m16n8k16.row.col.f32.bf16.bf16.f32 " \
                 "{%0,%1,%2,%3}, {%4,%5,%6,%7}, {%8,%9}, {%0,%1,%2,%3};" \
                 : "+f"((c)[0]), "+f"((c)[1]), "+f"((c)[2]), "+f"((c)[3]) \
                 : "r"((a)[0]), "r"((a)[1]), "r"((a)[2]), "r"((a)[3]), \
                   "r"(b0), "r"(b1))

// fast 2^x for x <= 0 (softmax domain); rel err ~1.5e-5; no MUFU
__device__ __forceinline__ float fexp2(float x) {
    x = fmaxf(x, -80.0f);
    float n = floorf(x);
    float f = x - n;
    float p = 1.5404e-4f;
    p = fmaf(p, f, 1.333356e-3f);
    p = fmaf(p, f, 9.618130e-3f);
    p = fmaf(p, f, 5.550411e-2f);
    p = fmaf(p, f, 2.402265e-1f);
    p = fmaf(p, f, 6.931472e-1f);
    p = fmaf(p, f, 1.0f);
    return __int_as_float(__float_as_int(p) + ((int)n << 23));
}

// ---------------------------------------------------------------------------
// PE table fill
// ---------------------------------------------------------------------------
__global__ void pe_fill_kernel() {
    int idx = blockIdx.x * blockDim.x + threadIdx.x;
    int pos = idx >> 8;
    int c   = idx & 255;
    int i2  = c & ~1;
    float div = expf(-logf(10000.0f) * (float)i2 / (float)D_);
    float ang = (float)pos * div;
    g_pe[idx] = (c & 1) ? cosf(ang) : sinf(ang);
}

// ---------------------------------------------------------------------------
// All-weight hi/lo conversion in one launch
// ---------------------------------------------------------------------------
__global__ void wconv_all(const float* __restrict__ Wr, const float* __restrict__ Wf,
                          const float* __restrict__ Wq, const float* __restrict__ Wk,
                          const float* __restrict__ Wv, const float* __restrict__ Wo,
                          const float* __restrict__ W1, const float* __restrict__ W2) {
    int idx = blockIdx.x * blockDim.x + threadIdx.x;
    if (idx >= WB_TOT) return;
    const float* W; int K, rowU32, base;
    if      (idx < WF_OFF) { W = Wr; K = 769; rowU32 = 800; base = WR_OFF; }
    else if (idx < WQ_OFF) { W = Wf; K = 674; rowU32 = 704; base = WF_OFF; }
    else if (idx < WK_OFF) { W = Wq; K = 256; rowU32 = 256; base = WQ_OFF; }
    else if (idx < WV_OFF) { W = Wk; K = 256; rowU32 = 256; base = WK_OFF; }
    else if (idx < WO_OFF) { W = Wv; K = 256; rowU32 = 256; base = WV_OFF; }
    else if (idx < W1_OFF) { W = Wo; K = 256; rowU32 = 256; base = WO_OFF; }
    else if (idx < W2_OFF) { W = W1; K = 256; rowU32 = 256; base = W1_OFF; }
    else                   { W = W2; K = 256; rowU32 = 256; base = W2_OFF; }
    int j   = idx - base;
    int row = j / rowU32;
    int jj  = j - row * rowU32;
    int c   = jj >> 5;
    int t   = jj & 31;
    int e0  = c * 32 + ((t & 15) << 1);
    float v0 = (e0     < K) ? W[(size_t)row * K + e0]     : 0.0f;
    float v1 = (e0 + 1 < K) ? W[(size_t)row * K + e0 + 1] : 0.0f;
    g_wbuf[idx] = (t < 16) ? hi_pair(v0, v1) : lo_pair(v0, v1);
}

// ---------------------------------------------------------------------------
// HMMA GEMM (bf16x3) — validated in R5, unchanged
// ---------------------------------------------------------------------------
#define ROWB   144
#define SM_B   0
#define SM_A   (256 * ROWB)
#define SM_TOT (SM_A + 128 * ROWB)

template <int EPI>
__global__ __launch_bounds__(256) void hmma_gemm(
    const float* __restrict__ A, int K, int NC,
    const uint32_t* __restrict__ Wbf, int rowU32,
    const float* __restrict__ bias,
    const float* __restrict__ gamma,
    const float* __restrict__ beta,
    const float* __restrict__ res,
    const float* __restrict__ pe,
    float* __restrict__ out)
{
    extern __shared__ __align__(16) char sm[];
    const uint32_t smb = smem_u32(sm);
    const int tid  = threadIdx.x;
    const int lane = tid & 31;
    const int warp = tid >> 5;
    const int wr   = warp >> 2;
    const int wc   = warp & 3;
    const int row0 = blockIdx.x * 128;

    const int arow  = tid >> 1;
    const int ahalf = tid & 1;
    const float* Ap = A + (size_t)(row0 + arow) * K + ahalf * 16;
    const uint32_t* Wp = Wbf + (size_t)tid * rowU32;

    float acc[4][8][4];
#pragma unroll
    for (int mt = 0; mt < 4; ++mt)
#pragma unroll
        for (int nt = 0; nt < 8; ++nt)
#pragma unroll
            for (int i = 0; i < 4; ++i) acc[mt][nt][i] = 0.0f;

    const uint32_t a_base = smb + SM_A
        + (uint32_t)(wr * 64 + (lane & 15)) * ROWB + (uint32_t)(lane >> 4) * 16;
    const uint32_t b_base = smb + SM_B
        + (uint32_t)(wc * 64 + ((lane >> 4) << 3) + (lane & 7)) * ROWB
        + (uint32_t)((lane >> 3) & 1) * 16;

    for (int c = 0; c < NC; ++c) {
        const int k0 = c * 32;
        __syncthreads();
        {
            float f[16];
#pragma unroll
            for (int j = 0; j < 16; ++j) {
                int kg = k0 + ahalf * 16 + j;
                f[j] = (kg < K) ? Ap[k0 + j] : 0.0f;
            }
            uint32_t hw[8], lw[8];
#pragma unroll
            for (int w = 0; w < 8; ++w) {
                hw[w] = hi_pair(f[2*w], f[2*w+1]);
                lw[w] = lo_pair(f[2*w], f[2*w+1]);
            }
            char* dh = sm + SM_A + arow * ROWB + ahalf * 32;
            char* dl = dh + 64;
#pragma unroll
            for (int g2 = 0; g2 < 2; ++g2) {
                *(uint4*)(dh + g2 * 16) =
                    make_uint4(hw[4*g2], hw[4*g2+1], hw[4*g2+2], hw[4*g2+3]);
                *(uint4*)(dl + g2 * 16) =
                    make_uint4(lw[4*g2], lw[4*g2+1], lw[4*g2+2], lw[4*g2+3]);
            }
        }
        {
            const uint4* src = (const uint4*)(Wp + c * 32);
            char* dst = sm + SM_B + tid * ROWB;
#pragma unroll
            for (int g2 = 0; g2 < 8; ++g2)
                *(uint4*)(dst + g2 * 16) = src[g2];
        }
        __syncthreads();

#pragma unroll
        for (int ks = 0; ks < 2; ++ks) {
            uint32_t ah[4][4], al[4][4];
#pragma unroll
            for (int mt = 0; mt < 4; ++mt) {
                LDMX4(ah[mt][0], ah[mt][1], ah[mt][2], ah[mt][3],
                      a_base + mt * (16 * ROWB) + ks * 32);
                LDMX4(al[mt][0], al[mt][1], al[mt][2], al[mt][3],
                      a_base + mt * (16 * ROWB) + ks * 32 + 64);
            }
#pragma unroll
            for (int np = 0; np < 4; ++np) {
                uint32_t bh[4], bl[4];
                LDMX4(bh[0], bh[1], bh[2], bh[3],
                      b_base + np * (16 * ROWB) + ks * 32);
                LDMX4(bl[0], bl[1], bl[2], bl[3],
                      b_base + np * (16 * ROWB) + ks * 32 + 64);
#pragma unroll
                for (int mt = 0; mt < 4; ++mt) {
                    MMA_BF16(acc[mt][2*np],     ah[mt], bh[0], bh[1]);
                    MMA_BF16(acc[mt][2*np],     al[mt], bh[0], bh[1]);
                    MMA_BF16(acc[mt][2*np],     ah[mt], bl[0], bl[1]);
                    MMA_BF16(acc[mt][2*np + 1], ah[mt], bh[2], bh[3]);
                    MMA_BF16(acc[mt][2*np + 1], al[mt], bh[2], bh[3]);
                    MMA_BF16(acc[mt][2*np + 1], ah[mt], bl[2], bl[3]);
                }
            }
        }
    }
    __syncthreads();

    const int g  = lane >> 2;
    const int t4 = lane & 3;

#pragma unroll
    for (int nt = 0; nt < 8; ++nt) {
        int cc = wc * 64 + nt * 8 + t4 * 2;
        float b0 = bias[cc], b1 = bias[cc + 1];
#pragma unroll
        for (int mt = 0; mt < 4; ++mt) {
            acc[mt][nt][0] += b0; acc[mt][nt][1] += b1;
            acc[mt][nt][2] += b0; acc[mt][nt][3] += b1;
        }
    }
    if (EPI == 3) {
#pragma unroll
        for (int mt = 0; mt < 4; ++mt)
#pragma unroll
            for (int h = 0; h < 2; ++h) {
                int row  = wr * 64 + mt * 16 + g + h * 8;
                int grow = row0 + row;
                if (pe) {
                    const float* pp = pe + (size_t)(grow & (N_ - 1)) * D_;
#pragma unroll
                    for (int nt = 0; nt < 8; ++nt) {
                        int cc = wc * 64 + nt * 8 + t4 * 2;
                        float2 pv = *(const float2*)&pp[cc];
                        acc[mt][nt][h*2]   += pv.x;
                        acc[mt][nt][h*2+1] += pv.y;
                    }
                }
                if (res) {
                    const float* rp = res + (size_t)grow * D_;
#pragma unroll
                    for (int nt = 0; nt < 8; ++nt) {
                        int cc = wc * 64 + nt * 8 + t4 * 2;
                        float2 rv = *(const float2*)&rp[cc];
                        acc[mt][nt][h*2]   += rv.x;
                        acc[mt][nt][h*2+1] += rv.y;
                    }
                }
            }

        float* lnsum = (float*)sm;
        float* lnsq  = (float*)sm + 512;
#pragma unroll
        for (int mt = 0; mt < 4; ++mt)
#pragma unroll
            for (int h = 0; h < 2; ++h) {
                float s = 0.0f, q = 0.0f;
#pragma unroll
                for (int nt = 0; nt < 8; ++nt) {
                    float v0 = acc[mt][nt][h*2], v1 = acc[mt][nt][h*2+1];
                    s += v0 + v1;
                    q = fmaf(v0, v0, q); q = fmaf(v1, v1, q);
                }
#pragma unroll
                for (int off = 1; off <= 2; off <<= 1) {
                    s += __shfl_xor_sync(0xffffffffu, s, off);
                    q += __shfl_xor_sync(0xffffffffu, q, off);
                }
                if (t4 == 0) {
                    int row = wr * 64 + mt * 16 + g + h * 8;
                    lnsum[row * 4 + wc] = s;
                    lnsq [row * 4 + wc] = q;
                }
            }
        __syncthreads();

#pragma unroll
        for (int mt = 0; mt < 4; ++mt)
#pragma unroll
            for (int h = 0; h < 2; ++h) {
                int row  = wr * 64 + mt * 16 + g + h * 8;
                int grow = row0 + row;
                float s = lnsum[row*4] + lnsum[row*4+1] + lnsum[row*4+2] + lnsum[row*4+3];
                float q = lnsq [row*4] + lnsq [row*4+1] + lnsq [row*4+2] + lnsq [row*4+3];
                float mu  = s * (1.0f / 256.0f);
                float var = q * (1.0f / 256.0f) - mu * mu;
                float rs  = rsqrtf(var + EPS_);
                float* op = out + (size_t)grow * D_;
#pragma unroll
                for (int nt = 0; nt < 8; ++nt) {
                    int cc = wc * 64 + nt * 8 + t4 * 2;
                    float v0 = (acc[mt][nt][h*2]   - mu) * rs * gamma[cc]   + beta[cc];
                    float v1 = (acc[mt][nt][h*2+1] - mu) * rs * gamma[cc+1] + beta[cc+1];
                    *(float2*)&op[cc] = make_float2(v0, v1);
                }
            }
    } else {
#pragma unroll
        for (int mt = 0; mt < 4; ++mt)
#pragma unroll
            for (int h = 0; h < 2; ++h) {
                int row  = wr * 64 + mt * 16 + g + h * 8;
                int grow = row0 + row;
                const float* rp = (EPI == 2) ? res + (size_t)grow * D_ : nullptr;
                float* op = out + (size_t)grow * D_;
#pragma unroll
                for (int nt = 0; nt < 8; ++nt) {
                    int cc = wc * 64 + nt * 8 + t4 * 2;
                    float v0 = acc[mt][nt][h*2];
                    float v1 = acc[mt][nt][h*2+1];
                    if (EPI == 1) { v0 = fmaxf(v0, 0.0f); v1 = fmaxf(v1, 0.0f); }
                    if (EPI == 2) {
                        float2 rv = *(const float2*)&rp[cc];
                        v0 += rv.x; v1 += rv.y;
                    }
                    *(float2*)&op[cc] = make_float2(v0, v1);
                }
            }
    }
}

// ---------------------------------------------------------------------------
// HMMA flash attention. CTA = (qtile 64 rows, bh). 128 threads, 4 warps,
// warp w owns q rows [w*16, w*16+16). bf16x3 QK^T and PV; base-2 softmax
// (0.125*log2e folded into Q); P fragments built in-register from S accs.
// Smem rows: 272B = [hi 128B | lo 128B | pad 16] (stride 17 mod 8 -> cf).
// ---------------------------------------------------------------------------
#define AROWB   272
#define AQ_OFF  0
#define AK_OFF  (64 * AROWB)
#define AV_OFF  (2 * 64 * AROWB)
#define ASM_TOT (3 * 64 * AROWB)          // 52224
#define QSCALE  0.1803368801111204f       // 0.125 * log2(e)

__global__ __launch_bounds__(128) void attn_kernel(
    const float* __restrict__ q,
    const float* __restrict__ k,
    const float* __restrict__ v,
    float* __restrict__ ctx)
{
    extern __shared__ __align__(16) char asm_[];
    const uint32_t smb = smem_u32(asm_);
    const int tid  = threadIdx.x;
    const int lane = tid & 31;
    const int warp = tid >> 5;
    const int bh   = blockIdx.y;
    const int b    = bh >> 2;
    const int h    = bh & 3;
    const int q0   = blockIdx.x * 64;
    const int g    = lane >> 2;
    const int t4   = lane & 3;

    // ---- stage Q (scaled) : thread -> row tid>>1, half tid&1 (32 cols)
    {
        const int r  = tid >> 1;
        const int hf = tid & 1;
        const float* qp = q + ((size_t)(b * N_ + q0 + r)) * D_ + h * HD_ + hf * 32;
        float f[32];
#pragma unroll
        for (int j = 0; j < 32; ++j) f[j] = qp[j] * QSCALE;
        uint32_t hw[16], lw[16];
#pragma unroll
        for (int w = 0; w < 16; ++w) {
            hw[w] = hi_pair(f[2*w], f[2*w+1]);
            lw[w] = lo_pair(f[2*w], f[2*w+1]);
        }
        char* dh = asm_ + AQ_OFF + r * AROWB + hf * 64;
        char* dl = dh + 128;
#pragma unroll
        for (int g2 = 0; g2 < 4; ++g2) {
            *(uint4*)(dh + g2 * 16) =
                make_uint4(hw[4*g2], hw[4*g2+1], hw[4*g2+2], hw[4*g2+3]);
            *(uint4*)(dl + g2 * 16) =
                make_uint4(lw[4*g2], lw[4*g2+1], lw[4*g2+2], lw[4*g2+3]);
        }
    }

    // ldmatrix bases
    const uint32_t a_base = smb + AQ_OFF
        + (uint32_t)(warp * 16 + (lane & 15)) * AROWB + (uint32_t)(lane >> 4) * 16;
    const uint32_t kb_base = smb + AK_OFF
        + (uint32_t)(((lane >> 4) << 3) + (lane & 7)) * AROWB
        + (uint32_t)((lane >> 3) & 1) * 16;
    const uint32_t vb_base = smb + AV_OFF
        + (uint32_t)(((lane >> 4) << 3) + (lane & 7)) * AROWB
        + (uint32_t)((lane >> 3) & 1) * 16;

    float acc_o[8][4];
#pragma unroll
    for (int nt = 0; nt < 8; ++nt)
#pragma unroll
        for (int i = 0; i < 4; ++i) acc_o[nt][i] = 0.0f;
    float mrow[2] = {-1e30f, -1e30f};
    float lrow[2] = {0.0f, 0.0f};

    for (int t0 = 0; t0 < N_; t0 += 64) {
        __syncthreads();
        // ---- stage K: row tid>>1, half tid&1
        {
            const int r  = tid >> 1;
            const int hf = tid & 1;
            const float* kp = k + ((size_t)(b * N_ + t0 + r)) * D_ + h * HD_ + hf * 32;
            float f[32];
#pragma unroll
            for (int j = 0; j < 32; ++j) f[j] = kp[j];
            uint32_t hw[16], lw[16];
#pragma unroll
            for (int w = 0; w < 16; ++w) {
                hw[w] = hi_pair(f[2*w], f[2*w+1]);
                lw[w] = lo_pair(f[2*w], f[2*w+1]);
            }
            char* dh = asm_ + AK_OFF + r * AROWB + hf * 64;
            char* dl = dh + 128;
#pragma unroll
            for (int g2 = 0; g2 < 4; ++g2) {
                *(uint4*)(dh + g2 * 16) =
                    make_uint4(hw[4*g2], hw[4*g2+1], hw[4*g2+2], hw[4*g2+3]);
                *(uint4*)(dl + g2 * 16) =
                    make_uint4(lw[4*g2], lw[4*g2+1], lw[4*g2+2], lw[4*g2+3]);
            }
        }
        // ---- stage V transposed: Vt[hd][kv] hi/lo packed kv-pairs
        {
            const int p  = tid >> 2;          // kv pair 0..31
            const int qd = tid & 3;           // hd quarter
            const float* v0p = v + ((size_t)(b * N_ + t0 + 2*p))     * D_ + h * HD_;
            const float* v1p = v + ((size_t)(b * N_ + t0 + 2*p + 1)) * D_ + h * HD_;
#pragma unroll
            for (int j = 0; j < 16; ++j) {
                int hd = qd * 16 + j;
                float f0 = v0p[hd], f1 = v1p[hd];
                *(uint32_t*)(asm_ + AV_OFF + hd * AROWB + p * 4)       = hi_pair(f0, f1);
                *(uint32_t*)(asm_ + AV_OFF + hd * AROWB + 128 + p * 4) = lo_pair(f0, f1);
            }
        }
        __syncthreads();

        // ---- S = Q K^T (m16 x n64, k=64, bf16x3)
        float s[8][4];
#pragma unroll
        for (int nt = 0; nt < 8; ++nt)
#pragma unroll
            for (int i = 0; i < 4; ++i) s[nt][i] = 0.0f;
#pragma unroll
        for (int ks = 0; ks < 4; ++ks) {
            uint32_t ah[4], al[4];
            LDMX4(ah[0], ah[1], ah[2], ah[3], a_base + ks * 32);
            LDMX4(al[0], al[1], al[2], al[3], a_base + ks * 32 + 128);
#pragma unroll
            for (int np = 0; np < 4; ++np) {
                uint32_t bh4[4], bl4[4];
                LDMX4(bh4[0], bh4[1], bh4[2], bh4[3],
                      kb_base + np * (16 * AROWB) + ks * 32);
                LDMX4(bl4[0], bl4[1], bl4[2], bl4[3],
                      kb_base + np * (16 * AROWB) + ks * 32 + 128);
                MMA_BF16(s[2*np],     ah, bh4[0], bh4[1]);
                MMA_BF16(s[2*np],     al, bh4[0], bh4[1]);
                MMA_BF16(s[2*np],     ah, bl4[0], bl4[1]);
                MMA_BF16(s[2*np + 1], ah, bh4[2], bh4[3]);
                MMA_BF16(s[2*np + 1], al, bh4[2], bh4[3]);
                MMA_BF16(s[2*np + 1], ah, bl4[2], bl4[3]);
            }
        }

        // ---- online softmax (base 2), rows g (i=0,1) and g+8 (i=2,3)
#pragma unroll
        for (int r2 = 0; r2 < 2; ++r2) {
            float mx = -1e30f;
#pragma unroll
            for (int nt = 0; nt < 8; ++nt)
                mx = fmaxf(mx, fmaxf(s[nt][r2*2], s[nt][r2*2+1]));
#pragma unroll
            for (int off = 1; off <= 2; off <<= 1)
                mx = fmaxf(mx, __shfl_xor_sync(0xffffffffu, mx, off));
            float mnew = fmaxf(mrow[r2], mx);
            float corr = fexp2(mrow[r2] - mnew);
            float ps = 0.0f;
#pragma unroll
            for (int nt = 0; nt < 8; ++nt) {
                float p0 = fexp2(s[nt][r2*2]   - mnew);
                float p1 = fexp2(s[nt][r2*2+1] - mnew);
                s[nt][r2*2] = p0; s[nt][r2*2+1] = p1;
                ps += p0 + p1;
            }
#pragma unroll
            for (int off = 1; off <= 2; off <<= 1)
                ps += __shfl_xor_sync(0xffffffffu, ps, off);
            lrow[r2] = lrow[r2] * corr + ps;
            mrow[r2] = mnew;
#pragma unroll
            for (int nt = 0; nt < 8; ++nt) {
                acc_o[nt][r2*2]   *= corr;
                acc_o[nt][r2*2+1] *= corr;
            }
        }

        // ---- O += P V : P A-fragments straight from s[] (C-frag -> A-frag)
#pragma unroll
        for (int kt = 0; kt < 4; ++kt) {
            uint32_t pah[4], pal[4];
            pah[0] = hi_pair(s[2*kt][0],   s[2*kt][1]);
            pah[1] = hi_pair(s[2*kt][2],   s[2*kt][3]);
            pah[2] = hi_pair(s[2*kt+1][0], s[2*kt+1][1]);
            pah[3] = hi_pair(s[2*kt+1][2], s[2*kt+1][3]);
            pal[0] = lo_pair(s[2*kt][0],   s[2*kt][1]);
            pal[1] = lo_pair(s[2*kt][2],   s[2*kt][3]);
            pal[2] = lo_pair(s[2*kt+1][0], s[2*kt+1][1]);
            pal[3] = lo_pair(s[2*kt+1][2], s[2*kt+1][3]);
#pragma unroll
            for (int np = 0; np < 4; ++np) {
                uint32_t vh4[4], vl4[4];
                LDMX4(vh4[0], vh4[1], vh4[2], vh4[3],
                      vb_base + np * (16 * AROWB) + kt * 32);
                LDMX4(vl4[0], vl4[1], vl4[2], vl4[3],
                      vb_base + np * (16 * AROWB) + kt * 32 + 128);
                MMA_BF16(acc_o[2*np],     pah, vh4[0], vh4[1]);
                MMA_BF16(acc_o[2*np],     pal, vh4[0], vh4[1]);
                MMA_BF16(acc_o[2*np],     pah, vl4[0], vl4[1]);
                MMA_BF16(acc_o[2*np + 1], pah, vh4[2], vh4[3]);
                MMA_BF16(acc_o[2*np + 1], pal, vh4[2], vh4[3]);
                MMA_BF16(acc_o[2*np + 1], pah, vl4[2], vl4[3]);
            }
        }
    }

    // ---- write ctx
    float inv0 = 1.0f / lrow[0];
    float inv1 = 1.0f / lrow[1];
#pragma unroll
    for (int r2 = 0; r2 < 2; ++r2) {
        int grow = b * N_ + q0 + warp * 16 + g + r2 * 8;
        float inv = r2 ? inv1 : inv0;
        float* cp = ctx + (size_t)grow * D_ + h * HD_;
#pragma unroll
        for (int nt = 0; nt < 8; ++nt) {
            int cc = nt * 8 + t4 * 2;
            *(float2*)&cp[cc] = make_float2(acc_o[nt][r2*2] * inv,
                                            acc_o[nt][r2*2+1] * inv);
        }
    }
}

// ---------------------------------------------------------------------------
// mean-pool + classifier
// ---------------------------------------------------------------------------
__global__ __launch_bounds__(256) void pool_cls_kernel(
    const float* __restrict__ xm,
    const float* __restrict__ Wc,
    const float* __restrict__ bc,
    float* __restrict__ out)
{
    __shared__ float pooled[D_];
    const int b = blockIdx.x;
    const int t = threadIdx.x;
    float s = 0.0f;
    const float* p = xm + (size_t)b * N_ * D_ + t;
#pragma unroll 8
    for (int n = 0; n < N_; ++n) s += p[(size_t)n * D_];
    pooled[t] = s * (1.0f / (float)N_);
    __syncthreads();
    if (t < 2) {
        float a = bc[t];
        for (int c = 0; c < D_; ++c) a = fmaf(pooled[c], Wc[t * D_ + c], a);
        out[b * 2 + t] = a;
    }
}

// ---------------------------------------------------------------------------
// Launch
// ---------------------------------------------------------------------------
static float* sym(const void* s) {
    void* p = nullptr;
    cudaGetSymbolAddress(&p, s);
    return (float*)p;
}

extern "C" void kernel_launch(void* const* d_in, const int* in_sizes, int n_in,
                              void* d_out, int out_size)
{
    const float* x   = (const float*)d_in[0];
    const float* y   = (const float*)d_in[1];
    const float* Wr  = (const float*)d_in[3];
    const float* br  = (const float*)d_in[4];
    const float* Wf  = (const float*)d_in[5];
    const float* bf  = (const float*)d_in[6];
    const float* g_x = (const float*)d_in[7];
    const float* b_x = (const float*)d_in[8];
    const float* g_y = (const float*)d_in[9];
    const float* b_y = (const float*)d_in[10];
    const float* Wq  = (const float*)d_in[11];
    const float* bq  = (const float*)d_in[12];
    const float* Wk  = (const float*)d_in[13];
    const float* bk  = (const float*)d_in[14];
    const float* Wv  = (const float*)d_in[15];
    const float* bv  = (const float*)d_in[16];
    const float* Wo  = (const float*)d_in[17];
    const float* bo  = (const float*)d_in[18];
    const float* g_m = (const float*)d_in[19];
    const float* b_m = (const float*)d_in[20];
    const float* W1  = (const float*)d_in[21];
    const float* b1  = (const float*)d_in[22];
    const float* W2  = (const float*)d_in[23];
    const float* b2  = (const float*)d_in[24];
    const float* Wc  = (const float*)d_in[25];
    const float* bc  = (const float*)d_in[26];
    float* out = (float*)d_out;

    float* xp   = sym(g_xp);
    float* yp   = sym(g_yp);
    float* qb   = sym(g_q);
    float* kb   = sym(g_k);
    float* vb   = sym(g_v);
    float* ctx  = sym(g_ctx);
    float* xres = sym(g_xres);
    float* hid  = sym(g_hid);
    float* xmlp = sym(g_xmlp);
    float* pe   = sym(g_pe);
    uint32_t* wb;
    {
        void* p = nullptr;
        cudaGetSymbolAddress(&p, g_wbuf);
        wb = (uint32_t*)p;
    }

    static bool attr_set = false;
    if (!attr_set) {
        cudaFuncSetAttribute(attn_kernel,
                             cudaFuncAttributeMaxDynamicSharedMemorySize, ASM_TOT);
        cudaFuncSetAttribute(hmma_gemm<0>,
                             cudaFuncAttributeMaxDynamicSharedMemorySize, SM_TOT);
        cudaFuncSetAttribute(hmma_gemm<1>,
                             cudaFuncAttributeMaxDynamicSharedMemorySize, SM_TOT);
        cudaFuncSetAttribute(hmma_gemm<2>,
                             cudaFuncAttributeMaxDynamicSharedMemorySize, SM_TOT);
        cudaFuncSetAttribute(hmma_gemm<3>,
                             cudaFuncAttributeMaxDynamicSharedMemorySize, SM_TOT);
        attr_set = true;
    }

    dim3 gg(M_ / 128);
    dim3 bb(256);

    pe_fill_kernel<<<N_ * D_ / 256, 256>>>();
    wconv_all<<<(WB_TOT + 255) / 256, 256>>>(Wr, Wf, Wq, Wk, Wv, Wo, W1, W2);

    // xp = LN(x @ Wr^T + br + pe)
    hmma_gemm<3><<<gg, bb, SM_TOT>>>(x, 769, 25, wb + WR_OFF, 800,
                                     br, g_x, b_x, nullptr, pe, xp);
    // yp = LN(y @ Wf^T + bf + pe)
    hmma_gemm<3><<<gg, bb, SM_TOT>>>(y, 674, 22, wb + WF_OFF, 704,
                                     bf, g_y, b_y, nullptr, pe, yp);
    // q,k,v
    hmma_gemm<0><<<gg, bb, SM_TOT>>>(xp, 256, 8, wb + WQ_OFF, 256,
                                     bq, nullptr, nullptr, nullptr, nullptr, qb);
    hmma_gemm<0><<<gg, bb, SM_TOT>>>(yp, 256, 8, wb + WK_OFF, 256,
                                     bk, nullptr, nullptr, nullptr, nullptr, kb);
    hmma_gemm<0><<<gg, bb, SM_TOT>>>(yp, 256, 8, wb + WV_OFF, 256,
                                     bv, nullptr, nullptr, nullptr, nullptr, vb);
    // attention (HMMA)
    dim3 ag(N_ / 64, B_ * H_);
    attn_kernel<<<ag, dim3(128), ASM_TOT>>>(qb, kb, vb, ctx);
    // x_res = LN(xp + ctx @ Wo^T + bo)
    hmma_gemm<3><<<gg, bb, SM_TOT>>>(ctx, 256, 8, wb + WO_OFF, 256,
                                     bo, g_m, b_m, xp, nullptr, xres);
    // hid = relu(x_res @ W1^T + b1)
    hmma_gemm<1><<<gg, bb, SM_TOT>>>(xres, 256, 8, wb + W1_OFF, 256,
                                     b1, nullptr, nullptr, nullptr, nullptr, hid);
    // xmlp = x_res + hid @ W2^T + b2
    hmma_gemm<2><<<gg, bb, SM_TOT>>>(hid, 256, 8, wb + W2_OFF, 256,
                                     b2, nullptr, nullptr, xres, nullptr, xmlp);
    // pool + classifier
    pool_cls_kernel<<<B_, bb>>>(xmlp, Wc, bc, out);
}

// round 8
// speedup vs baseline: 3.5742x; 1.0712x over previous
#include <cuda_runtime.h>
#include <cuda_bf16.h>
#include <math.h>
#include <stdint.h>

// ---------------------------------------------------------------------------
// Model dims
// ---------------------------------------------------------------------------
#define B_      64
#define N_      512
#define D_      256
#define H_      4
#define HD_     64
#define M_      (B_ * N_)         // 32768 rows
#define EPS_    1e-5f

// ---------------------------------------------------------------------------
// Scratch
// ---------------------------------------------------------------------------
__device__ float g_xp  [M_ * D_];
__device__ float g_yp  [M_ * D_];
__device__ float g_q   [M_ * D_];
__device__ float g_k   [M_ * D_];
__device__ float g_v   [M_ * D_];
__device__ float g_ctx [M_ * D_];
__device__ float g_xres[M_ * D_];
__device__ float g_hid [M_ * D_];
__device__ float g_xmlp[M_ * D_];
__device__ float g_pe  [N_ * D_];

// bf16 hi/lo weight scratch
#define WR_OFF  0
#define WF_OFF  (WR_OFF + 256 * 800)
#define WQ_OFF  (WF_OFF + 256 * 704)
#define WK_OFF  (WQ_OFF + 256 * 256)
#define WV_OFF  (WK_OFF + 256 * 256)
#define WO_OFF  (WV_OFF + 256 * 256)
#define W1_OFF  (WO_OFF + 256 * 256)
#define W2_OFF  (W1_OFF + 256 * 256)
#define WB_TOT  (W2_OFF + 256 * 256)
__device__ uint32_t g_wbuf[WB_TOT];

// ---------------------------------------------------------------------------
// hi = truncation to bf16 (exact); lo = rn-bf16(x - hi)
// ---------------------------------------------------------------------------
__device__ __forceinline__ uint32_t hi_pair(float x0, float x1) {
    uint32_t a = __float_as_uint(x0), b = __float_as_uint(x1);
    return (b & 0xffff0000u) | (a >> 16);
}
__device__ __forceinline__ uint32_t lo_pair(float x0, float x1) {
    float l0 = x0 - __uint_as_float(__float_as_uint(x0) & 0xffff0000u);
    float l1 = x1 - __uint_as_float(__float_as_uint(x1) & 0xffff0000u);
    uint32_t a = (uint32_t)__bfloat16_as_ushort(__float2bfloat16(l0));
    uint32_t b = (uint32_t)__bfloat16_as_ushort(__float2bfloat16(l1));
    return (b << 16) | a;
}

__device__ __forceinline__ uint32_t smem_u32(const void* p) {
    uint32_t a;
    asm("{ .reg .u64 t; cvta.to.shared.u64 t, %1; cvt.u32.u64 %0, t; }"
        : "=r"(a) : "l"(p));
    return a;
}

#define LDMX4(r0, r1, r2, r3, addr) \
    asm volatile("ldmatrix.sync.aligned.m8n8.x4.shared.b16 {%0,%1,%2,%3}, [%4];" \
                 : "=r"(r0), "=r"(r1), "=r"(r2), "=r"(r3) : "r"(addr))

#define MMA_BF16(c, a, b0, b1) \
    asm volatile("mma.sync.aligned.m16n8k16.row.col.f32.bf16.bf16.f32 " \
                 "{%0,%1,%2,%3}, {%4,%5,%6,%7}, {%8,%9}, {%0,%1,%2,%3};" \
                 : "+f"((c)[0]), "+f"((c)[1]), "+f"((c)[2]), "+f"((c)[3]) \
                 : "r"((a)[0]), "r"((a)[1]), "r"((a)[2]), "r"((a)[3]), \
                   "r"(b0), "r"(b1))

#define CPASYNC16(dst, src) \
    asm volatile("cp.async.cg.shared.global [%0], [%1], 16;" \
                 :: "r"(dst), "l"(src))
#define CPASYNC_COMMIT()  asm volatile("cp.async.commit_group;" ::: "memory")
#define CPASYNC_WAIT0()   asm volatile("cp.async.wait_group 0;" ::: "memory")

// fast 2^x for x <= 0; rel err ~1.5e-5; no MUFU
__device__ __forceinline__ float fexp2(float x) {
    x = fmaxf(x, -80.0f);
    float n = floorf(x);
    float f = x - n;
    float p = 1.5404e-4f;
    p = fmaf(p, f, 1.333356e-3f);
    p = fmaf(p, f, 9.618130e-3f);
    p = fmaf(p, f, 5.550411e-2f);
    p = fmaf(p, f, 2.402265e-1f);
    p = fmaf(p, f, 6.931472e-1f);
    p = fmaf(p, f, 1.0f);
    return __int_as_float(__float_as_int(p) + ((int)n << 23));
}

// ---------------------------------------------------------------------------
// PE table fill
// ---------------------------------------------------------------------------
__global__ void pe_fill_kernel() {
    int idx = blockIdx.x * blockDim.x + threadIdx.x;
    int pos = idx >> 8;
    int c   = idx & 255;
    int i2  = c & ~1;
    float div = expf(-logf(10000.0f) * (float)i2 / (float)D_);
    float ang = (float)pos * div;
    g_pe[idx] = (c & 1) ? cosf(ang) : sinf(ang);
}

// ---------------------------------------------------------------------------
// All-weight hi/lo conversion in one launch
// ---------------------------------------------------------------------------
__global__ void wconv_all(const float* __restrict__ Wr, const float* __restrict__ Wf,
                          const float* __restrict__ Wq, const float* __restrict__ Wk,
                          const float* __restrict__ Wv, const float* __restrict__ Wo,
                          const float* __restrict__ W1, const float* __restrict__ W2) {
    int idx = blockIdx.x * blockDim.x + threadIdx.x;
    if (idx >= WB_TOT) return;
    const float* W; int K, rowU32, base;
    if      (idx < WF_OFF) { W = Wr; K = 769; rowU32 = 800; base = WR_OFF; }
    else if (idx < WQ_OFF) { W = Wf; K = 674; rowU32 = 704; base = WF_OFF; }
    else if (idx < WK_OFF) { W = Wq; K = 256; rowU32 = 256; base = WQ_OFF; }
    else if (idx < WV_OFF) { W = Wk; K = 256; rowU32 = 256; base = WK_OFF; }
    else if (idx < WO_OFF) { W = Wv; K = 256; rowU32 = 256; base = WV_OFF; }
    else if (idx < W1_OFF) { W = Wo; K = 256; rowU32 = 256; base = WO_OFF; }
    else if (idx < W2_OFF) { W = W1; K = 256; rowU32 = 256; base = W1_OFF; }
    else                   { W = W2; K = 256; rowU32 = 256; base = W2_OFF; }
    int j   = idx - base;
    int row = j / rowU32;
    int jj  = j - row * rowU32;
    int c   = jj >> 5;
    int t   = jj & 31;
    int e0  = c * 32 + ((t & 15) << 1);
    float v0 = (e0     < K) ? W[(size_t)row * K + e0]     : 0.0f;
    float v1 = (e0 + 1 < K) ? W[(size_t)row * K + e0 + 1] : 0.0f;
    g_wbuf[idx] = (t < 16) ? hi_pair(v0, v1) : lo_pair(v0, v1);
}

// ---------------------------------------------------------------------------
// HMMA GEMM (bf16x3), pipelined: out[M x 256] = A[M x K] @ W[256 x K]^T
// CTA tile 64x256, 8 warps (2x4), warp tile 32x64 (mt=2). Double-buffered
// smem; B staged via cp.async (pre-converted pairs), A via LDG prefetch +
// convert + STS overlapped with MMAs. 2 CTAs/SM.
// EPI: 0=+bias 1=relu(+bias) 2=+bias+res 3=LN(+bias[+pe][+res])
// ---------------------------------------------------------------------------
#define ROWB   144
#define ABUF   (64 * ROWB)                // 9216
#define BBUF   (256 * ROWB)               // 36864
#define BUFSZ  (ABUF + BBUF)              // 46080
#define SM_TOT (2 * BUFSZ)                // 92160

template <int EPI>
__global__ __launch_bounds__(256, 2) void hmma_gemm(
    const float* __restrict__ A, int K, int NC,
    const uint32_t* __restrict__ Wbf, int rowU32,
    const float* __restrict__ bias,
    const float* __restrict__ gamma,
    const float* __restrict__ beta,
    const float* __restrict__ res,
    const float* __restrict__ pe,
    float* __restrict__ out)
{
    extern __shared__ __align__(16) char sm[];
    const uint32_t smb = smem_u32(sm);
    const int tid  = threadIdx.x;
    const int lane = tid & 31;
    const int warp = tid >> 5;
    const int wr   = warp >> 2;          // 0..1 : 32-row block
    const int wc   = warp & 3;           // 0..3 : 64-col block
    const int row0 = blockIdx.x * 64;

    // A staging: row = tid>>2 (0..63), 8 k-elements each (quarter aq)
    const int arow = tid >> 2;
    const int aq   = tid & 3;
    const float* Ap = A + (size_t)(row0 + arow) * K + aq * 8;
    const uint32_t* Wp = Wbf + (size_t)tid * rowU32;

    float acc[2][8][4];
#pragma unroll
    for (int mt = 0; mt < 2; ++mt)
#pragma unroll
        for (int nt = 0; nt < 8; ++nt)
#pragma unroll
            for (int i = 0; i < 4; ++i) acc[mt][nt][i] = 0.0f;

    // relative ldmatrix bases (add p*BUFSZ at use)
    const uint32_t a_rel = (uint32_t)(wr * 32 + (lane & 15)) * ROWB
                         + (uint32_t)(lane >> 4) * 16;
    const uint32_t b_rel = ABUF
                         + (uint32_t)(wc * 64 + ((lane >> 4) << 3) + (lane & 7)) * ROWB
                         + (uint32_t)((lane >> 3) & 1) * 16;

    // ---- staging helpers
    auto ldgA = [&](int c, float* f) {
#pragma unroll
        for (int j = 0; j < 8; ++j) {
            int kg = c * 32 + aq * 8 + j;
            f[j] = (kg < K) ? Ap[c * 32 + j] : 0.0f;
        }
    };
    auto stsA = [&](const float* f, int p) {
        uint32_t hw[4], lw[4];
#pragma unroll
        for (int w = 0; w < 4; ++w) {
            hw[w] = hi_pair(f[2*w], f[2*w+1]);
            lw[w] = lo_pair(f[2*w], f[2*w+1]);
        }
        char* dh = sm + p * BUFSZ + arow * ROWB + aq * 16;
        *(uint4*)dh        = make_uint4(hw[0], hw[1], hw[2], hw[3]);
        *(uint4*)(dh + 64) = make_uint4(lw[0], lw[1], lw[2], lw[3]);
    };
    auto cpB = [&](int c, int p) {
        uint32_t dst = smb + p * BUFSZ + ABUF + tid * ROWB;
        const char* src = (const char*)(Wp + c * 32);
#pragma unroll
        for (int g2 = 0; g2 < 8; ++g2)
            CPASYNC16(dst + g2 * 16, src + g2 * 16);
    };

    // ---- prologue: chunk 0 into buffer 0
    {
        float f0[8];
        ldgA(0, f0);
        cpB(0, 0);
        CPASYNC_COMMIT();
        stsA(f0, 0);
        CPASYNC_WAIT0();
    }
    __syncthreads();

    int p = 0;
    for (int c = 0; c < NC; ++c) {
        const bool have = (c + 1 < NC);
        float fn[8];
        if (have) {
            cpB(c + 1, p ^ 1);
            CPASYNC_COMMIT();
            ldgA(c + 1, fn);
        }
        // ---- compute chunk c from buffer p
        const uint32_t ab = smb + p * BUFSZ + a_rel;
        const uint32_t bb = smb + p * BUFSZ + b_rel;
#pragma unroll
        for (int ks = 0; ks < 2; ++ks) {
            uint32_t ah[2][4], al[2][4];
#pragma unroll
            for (int mt = 0; mt < 2; ++mt) {
                LDMX4(ah[mt][0], ah[mt][1], ah[mt][2], ah[mt][3],
                      ab + mt * (16 * ROWB) + ks * 32);
                LDMX4(al[mt][0], al[mt][1], al[mt][2], al[mt][3],
                      ab + mt * (16 * ROWB) + ks * 32 + 64);
            }
#pragma unroll
            for (int np = 0; np < 4; ++np) {
                uint32_t bh[4], bl[4];
                LDMX4(bh[0], bh[1], bh[2], bh[3],
                      bb + np * (16 * ROWB) + ks * 32);
                LDMX4(bl[0], bl[1], bl[2], bl[3],
                      bb + np * (16 * ROWB) + ks * 32 + 64);
#pragma unroll
                for (int mt = 0; mt < 2; ++mt) {
                    MMA_BF16(acc[mt][2*np],     ah[mt], bh[0], bh[1]);
                    MMA_BF16(acc[mt][2*np],     al[mt], bh[0], bh[1]);
                    MMA_BF16(acc[mt][2*np],     ah[mt], bl[0], bl[1]);
                    MMA_BF16(acc[mt][2*np + 1], ah[mt], bh[2], bh[3]);
                    MMA_BF16(acc[mt][2*np + 1], al[mt], bh[2], bh[3]);
                    MMA_BF16(acc[mt][2*np + 1], ah[mt], bl[2], bl[3]);
                }
            }
        }
        if (have) stsA(fn, p ^ 1);
        CPASYNC_WAIT0();
        __syncthreads();
        p ^= 1;
    }

    // ---------------- epilogue ----------------
    const int g  = lane >> 2;
    const int t4 = lane & 3;

#pragma unroll
    for (int nt = 0; nt < 8; ++nt) {
        int cc = wc * 64 + nt * 8 + t4 * 2;
        float b0 = bias[cc], b1 = bias[cc + 1];
#pragma unroll
        for (int mt = 0; mt < 2; ++mt) {
            acc[mt][nt][0] += b0; acc[mt][nt][1] += b1;
            acc[mt][nt][2] += b0; acc[mt][nt][3] += b1;
        }
    }
    if (EPI == 3) {
#pragma unroll
        for (int mt = 0; mt < 2; ++mt)
#pragma unroll
            for (int h = 0; h < 2; ++h) {
                int row  = wr * 32 + mt * 16 + g + h * 8;
                int grow = row0 + row;
                if (pe) {
                    const float* pp = pe + (size_t)(grow & (N_ - 1)) * D_;
#pragma unroll
                    for (int nt = 0; nt < 8; ++nt) {
                        int cc = wc * 64 + nt * 8 + t4 * 2;
                        float2 pv = *(const float2*)&pp[cc];
                        acc[mt][nt][h*2]   += pv.x;
                        acc[mt][nt][h*2+1] += pv.y;
                    }
                }
                if (res) {
                    const float* rp = res + (size_t)grow * D_;
#pragma unroll
                    for (int nt = 0; nt < 8; ++nt) {
                        int cc = wc * 64 + nt * 8 + t4 * 2;
                        float2 rv = *(const float2*)&rp[cc];
                        acc[mt][nt][h*2]   += rv.x;
                        acc[mt][nt][h*2+1] += rv.y;
                    }
                }
            }

        float* lnsum = (float*)sm;          // [64][4]
        float* lnsq  = (float*)sm + 256;
#pragma unroll
        for (int mt = 0; mt < 2; ++mt)
#pragma unroll
            for (int h = 0; h < 2; ++h) {
                float s = 0.0f, q = 0.0f;
#pragma unroll
                for (int nt = 0; nt < 8; ++nt) {
                    float v0 = acc[mt][nt][h*2], v1 = acc[mt][nt][h*2+1];
                    s += v0 + v1;
                    q = fmaf(v0, v0, q); q = fmaf(v1, v1, q);
                }
#pragma unroll
                for (int off = 1; off <= 2; off <<= 1) {
                    s += __shfl_xor_sync(0xffffffffu, s, off);
                    q += __shfl_xor_sync(0xffffffffu, q, off);
                }
                if (t4 == 0) {
                    int row = wr * 32 + mt * 16 + g + h * 8;
                    lnsum[row * 4 + wc] = s;
                    lnsq [row * 4 + wc] = q;
                }
            }
        __syncthreads();

#pragma unroll
        for (int mt = 0; mt < 2; ++mt)
#pragma unroll
            for (int h = 0; h < 2; ++h) {
                int row  = wr * 32 + mt * 16 + g + h * 8;
                int grow = row0 + row;
                float s = lnsum[row*4] + lnsum[row*4+1] + lnsum[row*4+2] + lnsum[row*4+3];
                float q = lnsq [row*4] + lnsq [row*4+1] + lnsq [row*4+2] + lnsq [row*4+3];
                float mu  = s * (1.0f / 256.0f);
                float var = q * (1.0f / 256.0f) - mu * mu;
                float rs  = rsqrtf(var + EPS_);
                float* op = out + (size_t)grow * D_;
#pragma unroll
                for (int nt = 0; nt < 8; ++nt) {
                    int cc = wc * 64 + nt * 8 + t4 * 2;
                    float v0 = (acc[mt][nt][h*2]   - mu) * rs * gamma[cc]   + beta[cc];
                    float v1 = (acc[mt][nt][h*2+1] - mu) * rs * gamma[cc+1] + beta[cc+1];
                    *(float2*)&op[cc] = make_float2(v0, v1);
                }
            }
    } else {
#pragma unroll
        for (int mt = 0; mt < 2; ++mt)
#pragma unroll
            for (int h = 0; h < 2; ++h) {
                int row  = wr * 32 + mt * 16 + g + h * 8;
                int grow = row0 + row;
                const float* rp = (EPI == 2) ? res + (size_t)grow * D_ : nullptr;
                float* op = out + (size_t)grow * D_;
#pragma unroll
                for (int nt = 0; nt < 8; ++nt) {
                    int cc = wc * 64 + nt * 8 + t4 * 2;
                    float v0 = acc[mt][nt][h*2];
                    float v1 = acc[mt][nt][h*2+1];
                    if (EPI == 1) { v0 = fmaxf(v0, 0.0f); v1 = fmaxf(v1, 0.0f); }
                    if (EPI == 2) {
                        float2 rv = *(const float2*)&rp[cc];
                        v0 += rv.x; v1 += rv.y;
                    }
                    *(float2*)&op[cc] = make_float2(v0, v1);
                }
            }
    }
}

// ---------------------------------------------------------------------------
// HMMA flash attention (validated R7, unchanged)
// ---------------------------------------------------------------------------
#define AROWB   272
#define AQ_OFF  0
#define AK_OFF  (64 * AROWB)
#define AV_OFF  (2 * 64 * AROWB)
#define ASM_TOT (3 * 64 * AROWB)
#define QSCALE  0.1803368801111204f       // 0.125 * log2(e)

__global__ __launch_bounds__(128) void attn_kernel(
    const float* __restrict__ q,
    const float* __restrict__ k,
    const float* __restrict__ v,
    float* __restrict__ ctx)
{
    extern __shared__ __align__(16) char asm_[];
    const uint32_t smb = smem_u32(asm_);
    const int tid  = threadIdx.x;
    const int lane = tid & 31;
    const int warp = tid >> 5;
    const int bh   = blockIdx.y;
    const int b    = bh >> 2;
    const int h    = bh & 3;
    const int q0   = blockIdx.x * 64;
    const int g    = lane >> 2;
    const int t4   = lane & 3;

    {
        const int r  = tid >> 1;
        const int hf = tid & 1;
        const float* qp = q + ((size_t)(b * N_ + q0 + r)) * D_ + h * HD_ + hf * 32;
        float f[32];
#pragma unroll
        for (int j = 0; j < 32; ++j) f[j] = qp[j] * QSCALE;
        uint32_t hw[16], lw[16];
#pragma unroll
        for (int w = 0; w < 16; ++w) {
            hw[w] = hi_pair(f[2*w], f[2*w+1]);
            lw[w] = lo_pair(f[2*w], f[2*w+1]);
        }
        char* dh = asm_ + AQ_OFF + r * AROWB + hf * 64;
        char* dl = dh + 128;
#pragma unroll
        for (int g2 = 0; g2 < 4; ++g2) {
            *(uint4*)(dh + g2 * 16) =
                make_uint4(hw[4*g2], hw[4*g2+1], hw[4*g2+2], hw[4*g2+3]);
            *(uint4*)(dl + g2 * 16) =
                make_uint4(lw[4*g2], lw[4*g2+1], lw[4*g2+2], lw[4*g2+3]);
        }
    }

    const uint32_t a_base = smb + AQ_OFF
        + (uint32_t)(warp * 16 + (lane & 15)) * AROWB + (uint32_t)(lane >> 4) * 16;
    const uint32_t kb_base = smb + AK_OFF
        + (uint32_t)(((lane >> 4) << 3) + (lane & 7)) * AROWB
        + (uint32_t)((lane >> 3) & 1) * 16;
    const uint32_t vb_base = smb + AV_OFF
        + (uint32_t)(((lane >> 4) << 3) + (lane & 7)) * AROWB
        + (uint32_t)((lane >> 3) & 1) * 16;

    float acc_o[8][4];
#pragma unroll
    for (int nt = 0; nt < 8; ++nt)
#pragma unroll
        for (int i = 0; i < 4; ++i) acc_o[nt][i] = 0.0f;
    float mrow[2] = {-1e30f, -1e30f};
    float lrow[2] = {0.0f, 0.0f};

    for (int t0 = 0; t0 < N_; t0 += 64) {
        __syncthreads();
        {
            const int r  = tid >> 1;
            const int hf = tid & 1;
            const float* kp = k + ((size_t)(b * N_ + t0 + r)) * D_ + h * HD_ + hf * 32;
            float f[32];
#pragma unroll
            for (int j = 0; j < 32; ++j) f[j] = kp[j];
            uint32_t hw[16], lw[16];
#pragma unroll
            for (int w = 0; w < 16; ++w) {
                hw[w] = hi_pair(f[2*w], f[2*w+1]);
                lw[w] = lo_pair(f[2*w], f[2*w+1]);
            }
            char* dh = asm_ + AK_OFF + r * AROWB + hf * 64;
            char* dl = dh + 128;
#pragma unroll
            for (int g2 = 0; g2 < 4; ++g2) {
                *(uint4*)(dh + g2 * 16) =
                    make_uint4(hw[4*g2], hw[4*g2+1], hw[4*g2+2], hw[4*g2+3]);
                *(uint4*)(dl + g2 * 16) =
                    make_uint4(lw[4*g2], lw[4*g2+1], lw[4*g2+2], lw[4*g2+3]);
            }
        }
        {
            const int p  = tid >> 2;
            const int qd = tid & 3;
            const float* v0p = v + ((size_t)(b * N_ + t0 + 2*p))     * D_ + h * HD_;
            const float* v1p = v + ((size_t)(b * N_ + t0 + 2*p + 1)) * D_ + h * HD_;
#pragma unroll
            for (int j = 0; j < 16; ++j) {
                int hd = qd * 16 + j;
                float f0 = v0p[hd], f1 = v1p[hd];
                *(uint32_t*)(asm_ + AV_OFF + hd * AROWB + p * 4)       = hi_pair(f0, f1);
                *(uint32_t*)(asm_ + AV_OFF + hd * AROWB + 128 + p * 4) = lo_pair(f0, f1);
            }
        }
        __syncthreads();

        float s[8][4];
#pragma unroll
        for (int nt = 0; nt < 8; ++nt)
#pragma unroll
            for (int i = 0; i < 4; ++i) s[nt][i] = 0.0f;
#pragma unroll
        for (int ks = 0; ks < 4; ++ks) {
            uint32_t ah[4], al[4];
            LDMX4(ah[0], ah[1], ah[2], ah[3], a_base + ks * 32);
            LDMX4(al[0], al[1], al[2], al[3], a_base + ks * 32 + 128);
#pragma unroll
            for (int np = 0; np < 4; ++np) {
                uint32_t bh4[4], bl4[4];
                LDMX4(bh4[0], bh4[1], bh4[2], bh4[3],
                      kb_base + np * (16 * AROWB) + ks * 32);
                LDMX4(bl4[0], bl4[1], bl4[2], bl4[3],
                      kb_base + np * (16 * AROWB) + ks * 32 + 128);
                MMA_BF16(s[2*np],     ah, bh4[0], bh4[1]);
                MMA_BF16(s[2*np],     al, bh4[0], bh4[1]);
                MMA_BF16(s[2*np],     ah, bl4[0], bl4[1]);
                MMA_BF16(s[2*np + 1], ah, bh4[2], bh4[3]);
                MMA_BF16(s[2*np + 1], al, bh4[2], bh4[3]);
                MMA_BF16(s[2*np + 1], ah, bl4[2], bl4[3]);
            }
        }

#pragma unroll
        for (int r2 = 0; r2 < 2; ++r2) {
            float mx = -1e30f;
#pragma unroll
            for (int nt = 0; nt < 8; ++nt)
                mx = fmaxf(mx, fmaxf(s[nt][r2*2], s[nt][r2*2+1]));
#pragma unroll
            for (int off = 1; off <= 2; off <<= 1)
                mx = fmaxf(mx, __shfl_xor_sync(0xffffffffu, mx, off));
            float mnew = fmaxf(mrow[r2], mx);
            float corr = fexp2(mrow[r2] - mnew);
            float ps = 0.0f;
#pragma unroll
            for (int nt = 0; nt < 8; ++nt) {
                float p0 = fexp2(s[nt][r2*2]   - mnew);
                float p1 = fexp2(s[nt][r2*2+1] - mnew);
                s[nt][r2*2] = p0; s[nt][r2*2+1] = p1;
                ps += p0 + p1;
            }
#pragma unroll
            for (int off = 1; off <= 2; off <<= 1)
                ps += __shfl_xor_sync(0xffffffffu, ps, off);
            lrow[r2] = lrow[r2] * corr + ps;
            mrow[r2] = mnew;
#pragma unroll
            for (int nt = 0; nt < 8; ++nt) {
                acc_o[nt][r2*2]   *= corr;
                acc_o[nt][r2*2+1] *= corr;
            }
        }

#pragma unroll
        for (int kt = 0; kt < 4; ++kt) {
            uint32_t pah[4], pal[4];
            pah[0] = hi_pair(s[2*kt][0],   s[2*kt][1]);
            pah[1] = hi_pair(s[2*kt][2],   s[2*kt][3]);
            pah[2] = hi_pair(s[2*kt+1][0], s[2*kt+1][1]);
            pah[3] = hi_pair(s[2*kt+1][2], s[2*kt+1][3]);
            pal[0] = lo_pair(s[2*kt][0],   s[2*kt][1]);
            pal[1] = lo_pair(s[2*kt][2],   s[2*kt][3]);
            pal[2] = lo_pair(s[2*kt+1][0], s[2*kt+1][1]);
            pal[3] = lo_pair(s[2*kt+1][2], s[2*kt+1][3]);
#pragma unroll
            for (int np = 0; np < 4; ++np) {
                uint32_t vh4[4], vl4[4];
                LDMX4(vh4[0], vh4[1], vh4[2], vh4[3],
                      vb_base + np * (16 * AROWB) + kt * 32);
                LDMX4(vl4[0], vl4[1], vl4[2], vl4[3],
                      vb_base + np * (16 * AROWB) + kt * 32 + 128);
                MMA_BF16(acc_o[2*np],     pah, vh4[0], vh4[1]);
                MMA_BF16(acc_o[2*np],     pal, vh4[0], vh4[1]);
                MMA_BF16(acc_o[2*np],     pah, vl4[0], vl4[1]);
                MMA_BF16(acc_o[2*np + 1], pah, vh4[2], vh4[3]);
                MMA_BF16(acc_o[2*np + 1], pal, vh4[2], vh4[3]);
                MMA_BF16(acc_o[2*np + 1], pah, vl4[2], vl4[3]);
            }
        }
    }

    float inv0 = 1.0f / lrow[0];
    float inv1 = 1.0f / lrow[1];
#pragma unroll
    for (int r2 = 0; r2 < 2; ++r2) {
        int grow = b * N_ + q0 + warp * 16 + g + r2 * 8;
        float inv = r2 ? inv1 : inv0;
        float* cp = ctx + (size_t)grow * D_ + h * HD_;
#pragma unroll
        for (int nt = 0; nt < 8; ++nt) {
            int cc = nt * 8 + t4 * 2;
            *(float2*)&cp[cc] = make_float2(acc_o[nt][r2*2] * inv,
                                            acc_o[nt][r2*2+1] * inv);
        }
    }
}

// ---------------------------------------------------------------------------
// mean-pool + classifier
// ---------------------------------------------------------------------------
__global__ __launch_bounds__(256) void pool_cls_kernel(
    const float* __restrict__ xm,
    const float* __restrict__ Wc,
    const float* __restrict__ bc,
    float* __restrict__ out)
{
    __shared__ float pooled[D_];
    const int b = blockIdx.x;
    const int t = threadIdx.x;
    float s = 0.0f;
    const float* p = xm + (size_t)b * N_ * D_ + t;
#pragma unroll 8
    for (int n = 0; n < N_; ++n) s += p[(size_t)n * D_];
    pooled[t] = s * (1.0f / (float)N_);
    __syncthreads();
    if (t < 2) {
        float a = bc[t];
        for (int c = 0; c < D_; ++c) a = fmaf(pooled[c], Wc[t * D_ + c], a);
        out[b * 2 + t] = a;
    }
}

// ---------------------------------------------------------------------------
// Launch
// ---------------------------------------------------------------------------
static float* sym(const void* s) {
    void* p = nullptr;
    cudaGetSymbolAddress(&p, s);
    return (float*)p;
}

extern "C" void kernel_launch(void* const* d_in, const int* in_sizes, int n_in,
                              void* d_out, int out_size)
{
    const float* x   = (const float*)d_in[0];
    const float* y   = (const float*)d_in[1];
    const float* Wr  = (const float*)d_in[3];
    const float* br  = (const float*)d_in[4];
    const float* Wf  = (const float*)d_in[5];
    const float* bf  = (const float*)d_in[6];
    const float* g_x = (const float*)d_in[7];
    const float* b_x = (const float*)d_in[8];
    const float* g_y = (const float*)d_in[9];
    const float* b_y = (const float*)d_in[10];
    const float* Wq  = (const float*)d_in[11];
    const float* bq  = (const float*)d_in[12];
    const float* Wk  = (const float*)d_in[13];
    const float* bk  = (const float*)d_in[14];
    const float* Wv  = (const float*)d_in[15];
    const float* bv  = (const float*)d_in[16];
    const float* Wo  = (const float*)d_in[17];
    const float* bo  = (const float*)d_in[18];
    const float* g_m = (const float*)d_in[19];
    const float* b_m = (const float*)d_in[20];
    const float* W1  = (const float*)d_in[21];
    const float* b1  = (const float*)d_in[22];
    const float* W2  = (const float*)d_in[23];
    const float* b2  = (const float*)d_in[24];
    const float* Wc  = (const float*)d_in[25];
    const float* bc  = (const float*)d_in[26];
    float* out = (float*)d_out;

    float* xp   = sym(g_xp);
    float* yp   = sym(g_yp);
    float* qb   = sym(g_q);
    float* kb   = sym(g_k);
    float* vb   = sym(g_v);
    float* ctx  = sym(g_ctx);
    float* xres = sym(g_xres);
    float* hid  = sym(g_hid);
    float* xmlp = sym(g_xmlp);
    float* pe   = sym(g_pe);
    uint32_t* wb;
    {
        void* p = nullptr;
        cudaGetSymbolAddress(&p, g_wbuf);
        wb = (uint32_t*)p;
    }

    static bool attr_set = false;
    if (!attr_set) {
        cudaFuncSetAttribute(attn_kernel,
                             cudaFuncAttributeMaxDynamicSharedMemorySize, ASM_TOT);
        cudaFuncSetAttribute(hmma_gemm<0>,
                             cudaFuncAttributeMaxDynamicSharedMemorySize, SM_TOT);
        cudaFuncSetAttribute(hmma_gemm<1>,
                             cudaFuncAttributeMaxDynamicSharedMemorySize, SM_TOT);
        cudaFuncSetAttribute(hmma_gemm<2>,
                             cudaFuncAttributeMaxDynamicSharedMemorySize, SM_TOT);
        cudaFuncSetAttribute(hmma_gemm<3>,
                             cudaFuncAttributeMaxDynamicSharedMemorySize, SM_TOT);
        attr_set = true;
    }

    dim3 gg(M_ / 64);     // 512 CTAs
    dim3 bb(256);

    pe_fill_kernel<<<N_ * D_ / 256, 256>>>();
    wconv_all<<<(WB_TOT + 255) / 256, 256>>>(Wr, Wf, Wq, Wk, Wv, Wo, W1, W2);

    // xp = LN(x @ Wr^T + br + pe)
    hmma_gemm<3><<<gg, bb, SM_TOT>>>(x, 769, 25, wb + WR_OFF, 800,
                                     br, g_x, b_x, nullptr, pe, xp);
    // yp = LN(y @ Wf^T + bf + pe)
    hmma_gemm<3><<<gg, bb, SM_TOT>>>(y, 674, 22, wb + WF_OFF, 704,
                                     bf, g_y, b_y, nullptr, pe, yp);
    // q,k,v
    hmma_gemm<0><<<gg, bb, SM_TOT>>>(xp, 256, 8, wb + WQ_OFF, 256,
                                     bq, nullptr, nullptr, nullptr, nullptr, qb);
    hmma_gemm<0><<<gg, bb, SM_TOT>>>(yp, 256, 8, wb + WK_OFF, 256,
                                     bk, nullptr, nullptr, nullptr, nullptr, kb);
    hmma_gemm<0><<<gg, bb, SM_TOT>>>(yp, 256, 8, wb + WV_OFF, 256,
                                     bv, nullptr, nullptr, nullptr, nullptr, vb);
    // attention (HMMA)
    dim3 ag(N_ / 64, B_ * H_);
    attn_kernel<<<ag, dim3(128), ASM_TOT>>>(qb, kb, vb, ctx);
    // x_res = LN(xp + ctx @ Wo^T + bo)
    hmma_gemm<3><<<gg, bb, SM_TOT>>>(ctx, 256, 8, wb + WO_OFF, 256,
                                     bo, g_m, b_m, xp, nullptr, xres);
    // hid = relu(x_res @ W1^T + b1)
    hmma_gemm<1><<<gg, bb, SM_TOT>>>(xres, 256, 8, wb + W1_OFF, 256,
                                     b1, nullptr, nullptr, nullptr, nullptr, hid);
    // xmlp = x_res + hid @ W2^T + b2
    hmma_gemm<2><<<gg, bb, SM_TOT>>>(hid, 256, 8, wb + W2_OFF, 256,
                                     b2, nullptr, nullptr, xres, nullptr, xmlp);
    // pool + classifier
    pool_cls_kernel<<<B_, bb>>>(xmlp, Wc, bc, out);
}

// round 9
// speedup vs baseline: 3.6285x; 1.0152x over previous
#include <cuda_runtime.h>
#include <cuda_bf16.h>
#include <math.h>
#include <stdint.h>

// ---------------------------------------------------------------------------
// Model dims
// ---------------------------------------------------------------------------
#define B_      64
#define N_      512
#define D_      256
#define H_      4
#define HD_     64
#define M_      (B_ * N_)         // 32768 rows
#define EPS_    1e-5f

// ---------------------------------------------------------------------------
// Scratch
// ---------------------------------------------------------------------------
__device__ float g_xp  [M_ * D_];
__device__ float g_yp  [M_ * D_];
__device__ float g_q   [M_ * D_];
__device__ float g_k   [M_ * D_];
__device__ float g_v   [M_ * D_];
__device__ float g_ctx [M_ * D_];
__device__ float g_xres[M_ * D_];
__device__ float g_hid [M_ * D_];
__device__ float g_xmlp[M_ * D_];
__device__ float g_pe  [N_ * D_];

// bf16 hi/lo weight scratch
#define WR_OFF  0
#define WF_OFF  (WR_OFF + 256 * 800)
#define WQ_OFF  (WF_OFF + 256 * 704)
#define WK_OFF  (WQ_OFF + 256 * 256)
#define WV_OFF  (WK_OFF + 256 * 256)
#define WO_OFF  (WV_OFF + 256 * 256)
#define W1_OFF  (WO_OFF + 256 * 256)
#define W2_OFF  (W1_OFF + 256 * 256)
#define WB_TOT  (W2_OFF + 256 * 256)
__device__ uint32_t g_wbuf[WB_TOT];

// ---------------------------------------------------------------------------
// hi = truncation to bf16 (exact); lo = rn-bf16(x - hi)
// ---------------------------------------------------------------------------
__device__ __forceinline__ uint32_t hi_pair(float x0, float x1) {
    uint32_t a = __float_as_uint(x0), b = __float_as_uint(x1);
    return (b & 0xffff0000u) | (a >> 16);
}
__device__ __forceinline__ uint32_t lo_pair(float x0, float x1) {
    float l0 = x0 - __uint_as_float(__float_as_uint(x0) & 0xffff0000u);
    float l1 = x1 - __uint_as_float(__float_as_uint(x1) & 0xffff0000u);
    uint32_t a = (uint32_t)__bfloat16_as_ushort(__float2bfloat16(l0));
    uint32_t b = (uint32_t)__bfloat16_as_ushort(__float2bfloat16(l1));
    return (b << 16) | a;
}

__device__ __forceinline__ uint32_t smem_u32(const void* p) {
    uint32_t a;
    asm("{ .reg .u64 t; cvta.to.shared.u64 t, %1; cvt.u32.u64 %0, t; }"
        : "=r"(a) : "l"(p));
    return a;
}

#define LDMX4(r0, r1, r2, r3, addr) \
    asm volatile("ldmatrix.sync.aligned.m8n8.x4.shared.b16 {%0,%1,%2,%3}, [%4];" \
                 : "=r"(r0), "=r"(r1), "=r"(r2), "=r"(r3) : "r"(addr))

#define MMA_BF16(c, a, b0, b1) \
    asm volatile("mma.sync.aligned.m16n8k16.row.col.f32.bf16.bf16.f32 " \
                 "{%0,%1,%2,%3}, {%4,%5,%6,%7}, {%8,%9}, {%0,%1,%2,%3};" \
                 : "+f"((c)[0]), "+f"((c)[1]), "+f"((c)[2]), "+f"((c)[3]) \
                 : "r"((a)[0]), "r"((a)[1]), "r"((a)[2]), "r"((a)[3]), \
                   "r"(b0), "r"(b1))

#define CPASYNC16(dst, src) \
    asm volatile("cp.async.cg.shared.global [%0], [%1], 16;" \
                 :: "r"(dst), "l"(src))
#define CPASYNC_COMMIT()  asm volatile("cp.async.commit_group;" ::: "memory")
#define CPASYNC_WAIT0()   asm volatile("cp.async.wait_group 0;" ::: "memory")

// fast 2^x for x <= 0; rel err ~1.5e-5; no MUFU
__device__ __forceinline__ float fexp2(float x) {
    x = fmaxf(x, -80.0f);
    float n = floorf(x);
    float f = x - n;
    float p = 1.5404e-4f;
    p = fmaf(p, f, 1.333356e-3f);
    p = fmaf(p, f, 9.618130e-3f);
    p = fmaf(p, f, 5.550411e-2f);
    p = fmaf(p, f, 2.402265e-1f);
    p = fmaf(p, f, 6.931472e-1f);
    p = fmaf(p, f, 1.0f);
    return __int_as_float(__float_as_int(p) + ((int)n << 23));
}

// ---------------------------------------------------------------------------
// PE table fill
// ---------------------------------------------------------------------------
__global__ void pe_fill_kernel() {
    int idx = blockIdx.x * blockDim.x + threadIdx.x;
    int pos = idx >> 8;
    int c   = idx & 255;
    int i2  = c & ~1;
    float div = expf(-logf(10000.0f) * (float)i2 / (float)D_);
    float ang = (float)pos * div;
    g_pe[idx] = (c & 1) ? cosf(ang) : sinf(ang);
}

// ---------------------------------------------------------------------------
// All-weight hi/lo conversion in one launch
// ---------------------------------------------------------------------------
__global__ void wconv_all(const float* __restrict__ Wr, const float* __restrict__ Wf,
                          const float* __restrict__ Wq, const float* __restrict__ Wk,
                          const float* __restrict__ Wv, const float* __restrict__ Wo,
                          const float* __restrict__ W1, const float* __restrict__ W2) {
    int idx = blockIdx.x * blockDim.x + threadIdx.x;
    if (idx >= WB_TOT) return;
    const float* W; int K, rowU32, base;
    if      (idx < WF_OFF) { W = Wr; K = 769; rowU32 = 800; base = WR_OFF; }
    else if (idx < WQ_OFF) { W = Wf; K = 674; rowU32 = 704; base = WF_OFF; }
    else if (idx < WK_OFF) { W = Wq; K = 256; rowU32 = 256; base = WQ_OFF; }
    else if (idx < WV_OFF) { W = Wk; K = 256; rowU32 = 256; base = WK_OFF; }
    else if (idx < WO_OFF) { W = Wv; K = 256; rowU32 = 256; base = WV_OFF; }
    else if (idx < W1_OFF) { W = Wo; K = 256; rowU32 = 256; base = WO_OFF; }
    else if (idx < W2_OFF) { W = W1; K = 256; rowU32 = 256; base = W1_OFF; }
    else                   { W = W2; K = 256; rowU32 = 256; base = W2_OFF; }
    int j   = idx - base;
    int row = j / rowU32;
    int jj  = j - row * rowU32;
    int c   = jj >> 5;
    int t   = jj & 31;
    int e0  = c * 32 + ((t & 15) << 1);
    float v0 = (e0     < K) ? W[(size_t)row * K + e0]     : 0.0f;
    float v1 = (e0 + 1 < K) ? W[(size_t)row * K + e0 + 1] : 0.0f;
    g_wbuf[idx] = (t < 16) ? hi_pair(v0, v1) : lo_pair(v0, v1);
}

// ---------------------------------------------------------------------------
// HMMA GEMM (bf16x3), pipelined + RAW-free MMA ordering.
// CTA tile 64x256, 8 warps (2x4), warp tile 32x64 (mt=2). Double-buffered
// smem; B via cp.async; A via LDG prefetch. MMAs issued in term groups over
// np-pairs: same-accumulator reuse distance = 8.
// EPI: 0=+bias 1=relu(+bias) 2=+bias+res 3=LN(+bias[+pe][+res])
// ---------------------------------------------------------------------------
#define ROWB   144
#define ABUF   (64 * ROWB)
#define BBUF   (256 * ROWB)
#define BUFSZ  (ABUF + BBUF)
#define SM_TOT (2 * BUFSZ)

template <int EPI>
__global__ __launch_bounds__(256, 2) void hmma_gemm(
    const float* __restrict__ A, int K, int NC,
    const uint32_t* __restrict__ Wbf, int rowU32,
    const float* __restrict__ bias,
    const float* __restrict__ gamma,
    const float* __restrict__ beta,
    const float* __restrict__ res,
    const float* __restrict__ pe,
    float* __restrict__ out)
{
    extern __shared__ __align__(16) char sm[];
    const uint32_t smb = smem_u32(sm);
    const int tid  = threadIdx.x;
    const int lane = tid & 31;
    const int warp = tid >> 5;
    const int wr   = warp >> 2;
    const int wc   = warp & 3;
    const int row0 = blockIdx.x * 64;

    const int arow = tid >> 2;
    const int aq   = tid & 3;
    const float* Ap = A + (size_t)(row0 + arow) * K + aq * 8;
    const uint32_t* Wp = Wbf + (size_t)tid * rowU32;

    float acc[2][8][4];
#pragma unroll
    for (int mt = 0; mt < 2; ++mt)
#pragma unroll
        for (int nt = 0; nt < 8; ++nt)
#pragma unroll
            for (int i = 0; i < 4; ++i) acc[mt][nt][i] = 0.0f;

    const uint32_t a_rel = (uint32_t)(wr * 32 + (lane & 15)) * ROWB
                         + (uint32_t)(lane >> 4) * 16;
    const uint32_t b_rel = ABUF
                         + (uint32_t)(wc * 64 + ((lane >> 4) << 3) + (lane & 7)) * ROWB
                         + (uint32_t)((lane >> 3) & 1) * 16;

    auto ldgA = [&](int c, float* f) {
#pragma unroll
        for (int j = 0; j < 8; ++j) {
            int kg = c * 32 + aq * 8 + j;
            f[j] = (kg < K) ? Ap[c * 32 + j] : 0.0f;
        }
    };
    auto stsA = [&](const float* f, int p) {
        uint32_t hw[4], lw[4];
#pragma unroll
        for (int w = 0; w < 4; ++w) {
            hw[w] = hi_pair(f[2*w], f[2*w+1]);
            lw[w] = lo_pair(f[2*w], f[2*w+1]);
        }
        char* dh = sm + p * BUFSZ + arow * ROWB + aq * 16;
        *(uint4*)dh        = make_uint4(hw[0], hw[1], hw[2], hw[3]);
        *(uint4*)(dh + 64) = make_uint4(lw[0], lw[1], lw[2], lw[3]);
    };
    auto cpB = [&](int c, int p) {
        uint32_t dst = smb + p * BUFSZ + ABUF + tid * ROWB;
        const char* src = (const char*)(Wp + c * 32);
#pragma unroll
        for (int g2 = 0; g2 < 8; ++g2)
            CPASYNC16(dst + g2 * 16, src + g2 * 16);
    };

    {
        float f0[8];
        ldgA(0, f0);
        cpB(0, 0);
        CPASYNC_COMMIT();
        stsA(f0, 0);
        CPASYNC_WAIT0();
    }
    __syncthreads();

    int p = 0;
    for (int c = 0; c < NC; ++c) {
        const bool have = (c + 1 < NC);
        float fn[8];
        if (have) {
            cpB(c + 1, p ^ 1);
            CPASYNC_COMMIT();
            ldgA(c + 1, fn);
        }
        const uint32_t ab = smb + p * BUFSZ + a_rel;
        const uint32_t bb = smb + p * BUFSZ + b_rel;
#pragma unroll
        for (int ks = 0; ks < 2; ++ks) {
            uint32_t ah[2][4], al[2][4];
#pragma unroll
            for (int mt = 0; mt < 2; ++mt) {
                LDMX4(ah[mt][0], ah[mt][1], ah[mt][2], ah[mt][3],
                      ab + mt * (16 * ROWB) + ks * 32);
                LDMX4(al[mt][0], al[mt][1], al[mt][2], al[mt][3],
                      ab + mt * (16 * ROWB) + ks * 32 + 64);
            }
#pragma unroll
            for (int npp = 0; npp < 2; ++npp) {
                const int np0 = npp * 2, np1 = npp * 2 + 1;
                uint32_t bh0[4], bl0[4], bh1[4], bl1[4];
                LDMX4(bh0[0], bh0[1], bh0[2], bh0[3],
                      bb + np0 * (16 * ROWB) + ks * 32);
                LDMX4(bl0[0], bl0[1], bl0[2], bl0[3],
                      bb + np0 * (16 * ROWB) + ks * 32 + 64);
                LDMX4(bh1[0], bh1[1], bh1[2], bh1[3],
                      bb + np1 * (16 * ROWB) + ks * 32);
                LDMX4(bl1[0], bl1[1], bl1[2], bl1[3],
                      bb + np1 * (16 * ROWB) + ks * 32 + 64);
                // term 1: A_hi * B_hi  (8 distinct accs)
                MMA_BF16(acc[0][2*np0],   ah[0], bh0[0], bh0[1]);
                MMA_BF16(acc[1][2*np0],   ah[1], bh0[0], bh0[1]);
                MMA_BF16(acc[0][2*np0+1], ah[0], bh0[2], bh0[3]);
                MMA_BF16(acc[1][2*np0+1], ah[1], bh0[2], bh0[3]);
                MMA_BF16(acc[0][2*np1],   ah[0], bh1[0], bh1[1]);
                MMA_BF16(acc[1][2*np1],   ah[1], bh1[0], bh1[1]);
                MMA_BF16(acc[0][2*np1+1], ah[0], bh1[2], bh1[3]);
                MMA_BF16(acc[1][2*np1+1], ah[1], bh1[2], bh1[3]);
                // term 2: A_lo * B_hi
                MMA_BF16(acc[0][2*np0],   al[0], bh0[0], bh0[1]);
                MMA_BF16(acc[1][2*np0],   al[1], bh0[0], bh0[1]);
                MMA_BF16(acc[0][2*np0+1], al[0], bh0[2], bh0[3]);
                MMA_BF16(acc[1][2*np0+1], al[1], bh0[2], bh0[3]);
                MMA_BF16(acc[0][2*np1],   al[0], bh1[0], bh1[1]);
                MMA_BF16(acc[1][2*np1],   al[1], bh1[0], bh1[1]);
                MMA_BF16(acc[0][2*np1+1], al[0], bh1[2], bh1[3]);
                MMA_BF16(acc[1][2*np1+1], al[1], bh1[2], bh1[3]);
                // term 3: A_hi * B_lo
                MMA_BF16(acc[0][2*np0],   ah[0], bl0[0], bl0[1]);
                MMA_BF16(acc[1][2*np0],   ah[1], bl0[0], bl0[1]);
                MMA_BF16(acc[0][2*np0+1], ah[0], bl0[2], bl0[3]);
                MMA_BF16(acc[1][2*np0+1], ah[1], bl0[2], bl0[3]);
                MMA_BF16(acc[0][2*np1],   ah[0], bl1[0], bl1[1]);
                MMA_BF16(acc[1][2*np1],   ah[1], bl1[0], bl1[1]);
                MMA_BF16(acc[0][2*np1+1], ah[0], bl1[2], bl1[3]);
                MMA_BF16(acc[1][2*np1+1], ah[1], bl1[2], bl1[3]);
            }
        }
        if (have) stsA(fn, p ^ 1);
        CPASYNC_WAIT0();
        __syncthreads();
        p ^= 1;
    }

    // ---------------- epilogue ----------------
    const int g  = lane >> 2;
    const int t4 = lane & 3;

#pragma unroll
    for (int nt = 0; nt < 8; ++nt) {
        int cc = wc * 64 + nt * 8 + t4 * 2;
        float b0 = bias[cc], b1 = bias[cc + 1];
#pragma unroll
        for (int mt = 0; mt < 2; ++mt) {
            acc[mt][nt][0] += b0; acc[mt][nt][1] += b1;
            acc[mt][nt][2] += b0; acc[mt][nt][3] += b1;
        }
    }
    if (EPI == 3) {
#pragma unroll
        for (int mt = 0; mt < 2; ++mt)
#pragma unroll
            for (int h = 0; h < 2; ++h) {
                int row  = wr * 32 + mt * 16 + g + h * 8;
                int grow = row0 + row;
                if (pe) {
                    const float* pp = pe + (size_t)(grow & (N_ - 1)) * D_;
#pragma unroll
                    for (int nt = 0; nt < 8; ++nt) {
                        int cc = wc * 64 + nt * 8 + t4 * 2;
                        float2 pv = *(const float2*)&pp[cc];
                        acc[mt][nt][h*2]   += pv.x;
                        acc[mt][nt][h*2+1] += pv.y;
                    }
                }
                if (res) {
                    const float* rp = res + (size_t)grow * D_;
#pragma unroll
                    for (int nt = 0; nt < 8; ++nt) {
                        int cc = wc * 64 + nt * 8 + t4 * 2;
                        float2 rv = *(const float2*)&rp[cc];
                        acc[mt][nt][h*2]   += rv.x;
                        acc[mt][nt][h*2+1] += rv.y;
                    }
                }
            }

        float* lnsum = (float*)sm;
        float* lnsq  = (float*)sm + 256;
#pragma unroll
        for (int mt = 0; mt < 2; ++mt)
#pragma unroll
            for (int h = 0; h < 2; ++h) {
                float s = 0.0f, q = 0.0f;
#pragma unroll
                for (int nt = 0; nt < 8; ++nt) {
                    float v0 = acc[mt][nt][h*2], v1 = acc[mt][nt][h*2+1];
                    s += v0 + v1;
                    q = fmaf(v0, v0, q); q = fmaf(v1, v1, q);
                }
#pragma unroll
                for (int off = 1; off <= 2; off <<= 1) {
                    s += __shfl_xor_sync(0xffffffffu, s, off);
                    q += __shfl_xor_sync(0xffffffffu, q, off);
                }
                if (t4 == 0) {
                    int row = wr * 32 + mt * 16 + g + h * 8;
                    lnsum[row * 4 + wc] = s;
                    lnsq [row * 4 + wc] = q;
                }
            }
        __syncthreads();

#pragma unroll
        for (int mt = 0; mt < 2; ++mt)
#pragma unroll
            for (int h = 0; h < 2; ++h) {
                int row  = wr * 32 + mt * 16 + g + h * 8;
                int grow = row0 + row;
                float s = lnsum[row*4] + lnsum[row*4+1] + lnsum[row*4+2] + lnsum[row*4+3];
                float q = lnsq [row*4] + lnsq [row*4+1] + lnsq [row*4+2] + lnsq [row*4+3];
                float mu  = s * (1.0f / 256.0f);
                float var = q * (1.0f / 256.0f) - mu * mu;
                float rs  = rsqrtf(var + EPS_);
                float* op = out + (size_t)grow * D_;
#pragma unroll
                for (int nt = 0; nt < 8; ++nt) {
                    int cc = wc * 64 + nt * 8 + t4 * 2;
                    float v0 = (acc[mt][nt][h*2]   - mu) * rs * gamma[cc]   + beta[cc];
                    float v1 = (acc[mt][nt][h*2+1] - mu) * rs * gamma[cc+1] + beta[cc+1];
                    *(float2*)&op[cc] = make_float2(v0, v1);
                }
            }
    } else {
#pragma unroll
        for (int mt = 0; mt < 2; ++mt)
#pragma unroll
            for (int h = 0; h < 2; ++h) {
                int row  = wr * 32 + mt * 16 + g + h * 8;
                int grow = row0 + row;
                const float* rp = (EPI == 2) ? res + (size_t)grow * D_ : nullptr;
                float* op = out + (size_t)grow * D_;
#pragma unroll
                for (int nt = 0; nt < 8; ++nt) {
                    int cc = wc * 64 + nt * 8 + t4 * 2;
                    float v0 = acc[mt][nt][h*2];
                    float v1 = acc[mt][nt][h*2+1];
                    if (EPI == 1) { v0 = fmaxf(v0, 0.0f); v1 = fmaxf(v1, 0.0f); }
                    if (EPI == 2) {
                        float2 rv = *(const float2*)&rp[cc];
                        v0 += rv.x; v1 += rv.y;
                    }
                    *(float2*)&op[cc] = make_float2(v0, v1);
                }
            }
    }
}

// ---------------------------------------------------------------------------
// HMMA flash attention, RAW-free MMA ordering (term groups over np-pairs)
// ---------------------------------------------------------------------------
#define AROWB   272
#define AQ_OFF  0
#define AK_OFF  (64 * AROWB)
#define AV_OFF  (2 * 64 * AROWB)
#define ASM_TOT (3 * 64 * AROWB)
#define QSCALE  0.1803368801111204f       // 0.125 * log2(e)

__global__ __launch_bounds__(128) void attn_kernel(
    const float* __restrict__ q,
    const float* __restrict__ k,
    const float* __restrict__ v,
    float* __restrict__ ctx)
{
    extern __shared__ __align__(16) char asm_[];
    const uint32_t smb = smem_u32(asm_);
    const int tid  = threadIdx.x;
    const int lane = tid & 31;
    const int warp = tid >> 5;
    const int bh   = blockIdx.y;
    const int b    = bh >> 2;
    const int h    = bh & 3;
    const int q0   = blockIdx.x * 64;
    const int g    = lane >> 2;
    const int t4   = lane & 3;

    {
        const int r  = tid >> 1;
        const int hf = tid & 1;
        const float* qp = q + ((size_t)(b * N_ + q0 + r)) * D_ + h * HD_ + hf * 32;
        float f[32];
#pragma unroll
        for (int j = 0; j < 32; ++j) f[j] = qp[j] * QSCALE;
        uint32_t hw[16], lw[16];
#pragma unroll
        for (int w = 0; w < 16; ++w) {
            hw[w] = hi_pair(f[2*w], f[2*w+1]);
            lw[w] = lo_pair(f[2*w], f[2*w+1]);
        }
        char* dh = asm_ + AQ_OFF + r * AROWB + hf * 64;
        char* dl = dh + 128;
#pragma unroll
        for (int g2 = 0; g2 < 4; ++g2) {
            *(uint4*)(dh + g2 * 16) =
                make_uint4(hw[4*g2], hw[4*g2+1], hw[4*g2+2], hw[4*g2+3]);
            *(uint4*)(dl + g2 * 16) =
                make_uint4(lw[4*g2], lw[4*g2+1], lw[4*g2+2], lw[4*g2+3]);
        }
    }

    const uint32_t a_base = smb + AQ_OFF
        + (uint32_t)(warp * 16 + (lane & 15)) * AROWB + (uint32_t)(lane >> 4) * 16;
    const uint32_t kb_base = smb + AK_OFF
        + (uint32_t)(((lane >> 4) << 3) + (lane & 7)) * AROWB
        + (uint32_t)((lane >> 3) & 1) * 16;
    const uint32_t vb_base = smb + AV_OFF
        + (uint32_t)(((lane >> 4) << 3) + (lane & 7)) * AROWB
        + (uint32_t)((lane >> 3) & 1) * 16;

    float acc_o[8][4];
#pragma unroll
    for (int nt = 0; nt < 8; ++nt)
#pragma unroll
        for (int i = 0; i < 4; ++i) acc_o[nt][i] = 0.0f;
    float mrow[2] = {-1e30f, -1e30f};
    float lrow[2] = {0.0f, 0.0f};

    for (int t0 = 0; t0 < N_; t0 += 64) {
        __syncthreads();
        {
            const int r  = tid >> 1;
            const int hf = tid & 1;
            const float* kp = k + ((size_t)(b * N_ + t0 + r)) * D_ + h * HD_ + hf * 32;
            float f[32];
#pragma unroll
            for (int j = 0; j < 32; ++j) f[j] = kp[j];
            uint32_t hw[16], lw[16];
#pragma unroll
            for (int w = 0; w < 16; ++w) {
                hw[w] = hi_pair(f[2*w], f[2*w+1]);
                lw[w] = lo_pair(f[2*w], f[2*w+1]);
            }
            char* dh = asm_ + AK_OFF + r * AROWB + hf * 64;
            char* dl = dh + 128;
#pragma unroll
            for (int g2 = 0; g2 < 4; ++g2) {
                *(uint4*)(dh + g2 * 16) =
                    make_uint4(hw[4*g2], hw[4*g2+1], hw[4*g2+2], hw[4*g2+3]);
                *(uint4*)(dl + g2 * 16) =
                    make_uint4(lw[4*g2], lw[4*g2+1], lw[4*g2+2], lw[4*g2+3]);
            }
        }
        {
            const int p  = tid >> 2;
            const int qd = tid & 3;
            const float* v0p = v + ((size_t)(b * N_ + t0 + 2*p))     * D_ + h * HD_;
            const float* v1p = v + ((size_t)(b * N_ + t0 + 2*p + 1)) * D_ + h * HD_;
#pragma unroll
            for (int j = 0; j < 16; ++j) {
                int hd = qd * 16 + j;
                float f0 = v0p[hd], f1 = v1p[hd];
                *(uint32_t*)(asm_ + AV_OFF + hd * AROWB + p * 4)       = hi_pair(f0, f1);
                *(uint32_t*)(asm_ + AV_OFF + hd * AROWB + 128 + p * 4) = lo_pair(f0, f1);
            }
        }
        __syncthreads();

        // ---- S = Q K^T (term-grouped MMA order)
        float s[8][4];
#pragma unroll
        for (int nt = 0; nt < 8; ++nt)
#pragma unroll
            for (int i = 0; i < 4; ++i) s[nt][i] = 0.0f;
#pragma unroll
        for (int ks = 0; ks < 4; ++ks) {
            uint32_t ah[4], al[4];
            LDMX4(ah[0], ah[1], ah[2], ah[3], a_base + ks * 32);
            LDMX4(al[0], al[1], al[2], al[3], a_base + ks * 32 + 128);
#pragma unroll
            for (int npp = 0; npp < 2; ++npp) {
                const int np0 = npp * 2, np1 = npp * 2 + 1;
                uint32_t bh0[4], bl0[4], bh1[4], bl1[4];
                LDMX4(bh0[0], bh0[1], bh0[2], bh0[3],
                      kb_base + np0 * (16 * AROWB) + ks * 32);
                LDMX4(bl0[0], bl0[1], bl0[2], bl0[3],
                      kb_base + np0 * (16 * AROWB) + ks * 32 + 128);
                LDMX4(bh1[0], bh1[1], bh1[2], bh1[3],
                      kb_base + np1 * (16 * AROWB) + ks * 32);
                LDMX4(bl1[0], bl1[1], bl1[2], bl1[3],
                      kb_base + np1 * (16 * AROWB) + ks * 32 + 128);
                // term 1
                MMA_BF16(s[2*np0],     ah, bh0[0], bh0[1]);
                MMA_BF16(s[2*np0 + 1], ah, bh0[2], bh0[3]);
                MMA_BF16(s[2*np1],     ah, bh1[0], bh1[1]);
                MMA_BF16(s[2*np1 + 1], ah, bh1[2], bh1[3]);
                // term 2
                MMA_BF16(s[2*np0],     al, bh0[0], bh0[1]);
                MMA_BF16(s[2*np0 + 1], al, bh0[2], bh0[3]);
                MMA_BF16(s[2*np1],     al, bh1[0], bh1[1]);
                MMA_BF16(s[2*np1 + 1], al, bh1[2], bh1[3]);
                // term 3
                MMA_BF16(s[2*np0],     ah, bl0[0], bl0[1]);
                MMA_BF16(s[2*np0 + 1], ah, bl0[2], bl0[3]);
                MMA_BF16(s[2*np1],     ah, bl1[0], bl1[1]);
                MMA_BF16(s[2*np1 + 1], ah, bl1[2], bl1[3]);
            }
        }

#pragma unroll
        for (int r2 = 0; r2 < 2; ++r2) {
            float mx = -1e30f;
#pragma unroll
            for (int nt = 0; nt < 8; ++nt)
                mx = fmaxf(mx, fmaxf(s[nt][r2*2], s[nt][r2*2+1]));
#pragma unroll
            for (int off = 1; off <= 2; off <<= 1)
                mx = fmaxf(mx, __shfl_xor_sync(0xffffffffu, mx, off));
            float mnew = fmaxf(mrow[r2], mx);
            float corr = fexp2(mrow[r2] - mnew);
            float ps = 0.0f;
#pragma unroll
            for (int nt = 0; nt < 8; ++nt) {
                float p0 = fexp2(s[nt][r2*2]   - mnew);
                float p1 = fexp2(s[nt][r2*2+1] - mnew);
                s[nt][r2*2] = p0; s[nt][r2*2+1] = p1;
                ps += p0 + p1;
            }
#pragma unroll
            for (int off = 1; off <= 2; off <<= 1)
                ps += __shfl_xor_sync(0xffffffffu, ps, off);
            lrow[r2] = lrow[r2] * corr + ps;
            mrow[r2] = mnew;
#pragma unroll
            for (int nt = 0; nt < 8; ++nt) {
                acc_o[nt][r2*2]   *= corr;
                acc_o[nt][r2*2+1] *= corr;
            }
        }

        // ---- O += P V (term-grouped)
#pragma unroll
        for (int kt = 0; kt < 4; ++kt) {
            uint32_t pah[4], pal[4];
            pah[0] = hi_pair(s[2*kt][0],   s[2*kt][1]);
            pah[1] = hi_pair(s[2*kt][2],   s[2*kt][3]);
            pah[2] = hi_pair(s[2*kt+1][0], s[2*kt+1][1]);
            pah[3] = hi_pair(s[2*kt+1][2], s[2*kt+1][3]);
            pal[0] = lo_pair(s[2*kt][0],   s[2*kt][1]);
            pal[1] = lo_pair(s[2*kt][2],   s[2*kt][3]);
            pal[2] = lo_pair(s[2*kt+1][0], s[2*kt+1][1]);
            pal[3] = lo_pair(s[2*kt+1][2], s[2*kt+1][3]);
#pragma unroll
            for (int npp = 0; npp < 2; ++npp) {
                const int np0 = npp * 2, np1 = npp * 2 + 1;
                uint32_t vh0[4], vl0[4], vh1[4], vl1[4];
                LDMX4(vh0[0], vh0[1], vh0[2], vh0[3],
                      vb_base + np0 * (16 * AROWB) + kt * 32);
                LDMX4(vl0[0], vl0[1], vl0[2], vl0[3],
                      vb_base + np0 * (16 * AROWB) + kt * 32 + 128);
                LDMX4(vh1[0], vh1[1], vh1[2], vh1[3],
                      vb_base + np1 * (16 * AROWB) + kt * 32);
                LDMX4(vl1[0], vl1[1], vl1[2], vl1[3],
                      vb_base + np1 * (16 * AROWB) + kt * 32 + 128);
                // term 1
                MMA_BF16(acc_o[2*np0],     pah, vh0[0], vh0[1]);
                MMA_BF16(acc_o[2*np0 + 1], pah, vh0[2], vh0[3]);
                MMA_BF16(acc_o[2*np1],     pah, vh1[0], vh1[1]);
                MMA_BF16(acc_o[2*np1 + 1], pah, vh1[2], vh1[3]);
                // term 2
                MMA_BF16(acc_o[2*np0],     pal, vh0[0], vh0[1]);
                MMA_BF16(acc_o[2*np0 + 1], pal, vh0[2], vh0[3]);
                MMA_BF16(acc_o[2*np1],     pal, vh1[0], vh1[1]);
                MMA_BF16(acc_o[2*np1 + 1], pal, vh1[2], vh1[3]);
                // term 3
                MMA_BF16(acc_o[2*np0],     pah, vl0[0], vl0[1]);
                MMA_BF16(acc_o[2*np0 + 1], pah, vl0[2], vl0[3]);
                MMA_BF16(acc_o[2*np1],     pah, vl1[0], vl1[1]);
                MMA_BF16(acc_o[2*np1 + 1], pah, vl1[2], vl1[3]);
            }
        }
    }

    float inv0 = 1.0f / lrow[0];
    float inv1 = 1.0f / lrow[1];
#pragma unroll
    for (int r2 = 0; r2 < 2; ++r2) {
        int grow = b * N_ + q0 + warp * 16 + g + r2 * 8;
        float inv = r2 ? inv1 : inv0;
        float* cp = ctx + (size_t)grow * D_ + h * HD_;
#pragma unroll
        for (int nt = 0; nt < 8; ++nt) {
            int cc = nt * 8 + t4 * 2;
            *(float2*)&cp[cc] = make_float2(acc_o[nt][r2*2] * inv,
                                            acc_o[nt][r2*2+1] * inv);
        }
    }
}

// ---------------------------------------------------------------------------
// mean-pool + classifier
// ---------------------------------------------------------------------------
__global__ __launch_bounds__(256) void pool_cls_kernel(
    const float* __restrict__ xm,
    const float* __restrict__ Wc,
    const float* __restrict__ bc,
    float* __restrict__ out)
{
    __shared__ float pooled[D_];
    const int b = blockIdx.x;
    const int t = threadIdx.x;
    float s = 0.0f;
    const float* p = xm + (size_t)b * N_ * D_ + t;
#pragma unroll 8
    for (int n = 0; n < N_; ++n) s += p[(size_t)n * D_];
    pooled[t] = s * (1.0f / (float)N_);
    __syncthreads();
    if (t < 2) {
        float a = bc[t];
        for (int c = 0; c < D_; ++c) a = fmaf(pooled[c], Wc[t * D_ + c], a);
        out[b * 2 + t] = a;
    }
}

// ---------------------------------------------------------------------------
// Launch
// ---------------------------------------------------------------------------
static float* sym(const void* s) {
    void* p = nullptr;
    cudaGetSymbolAddress(&p, s);
    return (float*)p;
}

extern "C" void kernel_launch(void* const* d_in, const int* in_sizes, int n_in,
                              void* d_out, int out_size)
{
    const float* x   = (const float*)d_in[0];
    const float* y   = (const float*)d_in[1];
    const float* Wr  = (const float*)d_in[3];
    const float* br  = (const float*)d_in[4];
    const float* Wf  = (const float*)d_in[5];
    const float* bf  = (const float*)d_in[6];
    const float* g_x = (const float*)d_in[7];
    const float* b_x = (const float*)d_in[8];
    const float* g_y = (const float*)d_in[9];
    const float* b_y = (const float*)d_in[10];
    const float* Wq  = (const float*)d_in[11];
    const float* bq  = (const float*)d_in[12];
    const float* Wk  = (const float*)d_in[13];
    const float* bk  = (const float*)d_in[14];
    const float* Wv  = (const float*)d_in[15];
    const float* bv  = (const float*)d_in[16];
    const float* Wo  = (const float*)d_in[17];
    const float* bo  = (const float*)d_in[18];
    const float* g_m = (const float*)d_in[19];
    const float* b_m = (const float*)d_in[20];
    const float* W1  = (const float*)d_in[21];
    const float* b1  = (const float*)d_in[22];
    const float* W2  = (const float*)d_in[23];
    const float* b2  = (const float*)d_in[24];
    const float* Wc  = (const float*)d_in[25];
    const float* bc  = (const float*)d_in[26];
    float* out = (float*)d_out;

    float* xp   = sym(g_xp);
    float* yp   = sym(g_yp);
    float* qb   = sym(g_q);
    float* kb   = sym(g_k);
    float* vb   = sym(g_v);
    float* ctx  = sym(g_ctx);
    float* xres = sym(g_xres);
    float* hid  = sym(g_hid);
    float* xmlp = sym(g_xmlp);
    float* pe   = sym(g_pe);
    uint32_t* wb;
    {
        void* p = nullptr;
        cudaGetSymbolAddress(&p, g_wbuf);
        wb = (uint32_t*)p;
    }

    static bool attr_set = false;
    if (!attr_set) {
        cudaFuncSetAttribute(attn_kernel,
                             cudaFuncAttributeMaxDynamicSharedMemorySize, ASM_TOT);
        cudaFuncSetAttribute(hmma_gemm<0>,
                             cudaFuncAttributeMaxDynamicSharedMemorySize, SM_TOT);
        cudaFuncSetAttribute(hmma_gemm<1>,
                             cudaFuncAttributeMaxDynamicSharedMemorySize, SM_TOT);
        cudaFuncSetAttribute(hmma_gemm<2>,
                             cudaFuncAttributeMaxDynamicSharedMemorySize, SM_TOT);
        cudaFuncSetAttribute(hmma_gemm<3>,
                             cudaFuncAttributeMaxDynamicSharedMemorySize, SM_TOT);
        attr_set = true;
    }

    dim3 gg(M_ / 64);     // 512 CTAs
    dim3 bb(256);

    pe_fill_kernel<<<N_ * D_ / 256, 256>>>();
    wconv_all<<<(WB_TOT + 255) / 256, 256>>>(Wr, Wf, Wq, Wk, Wv, Wo, W1, W2);

    // xp = LN(x @ Wr^T + br + pe)
    hmma_gemm<3><<<gg, bb, SM_TOT>>>(x, 769, 25, wb + WR_OFF, 800,
                                     br, g_x, b_x, nullptr, pe, xp);
    // yp = LN(y @ Wf^T + bf + pe)
    hmma_gemm<3><<<gg, bb, SM_TOT>>>(y, 674, 22, wb + WF_OFF, 704,
                                     bf, g_y, b_y, nullptr, pe, yp);
    // q,k,v
    hmma_gemm<0><<<gg, bb, SM_TOT>>>(xp, 256, 8, wb + WQ_OFF, 256,
                                     bq, nullptr, nullptr, nullptr, nullptr, qb);
    hmma_gemm<0><<<gg, bb, SM_TOT>>>(yp, 256, 8, wb + WK_OFF, 256,
                                     bk, nullptr, nullptr, nullptr, nullptr, kb);
    hmma_gemm<0><<<gg, bb, SM_TOT>>>(yp, 256, 8, wb + WV_OFF, 256,
                                     bv, nullptr, nullptr, nullptr, nullptr, vb);
    // attention (HMMA)
    dim3 ag(N_ / 64, B_ * H_);
    attn_kernel<<<ag, dim3(128), ASM_TOT>>>(qb, kb, vb, ctx);
    // x_res = LN(xp + ctx @ Wo^T + bo)
    hmma_gemm<3><<<gg, bb, SM_TOT>>>(ctx, 256, 8, wb + WO_OFF, 256,
                                     bo, g_m, b_m, xp, nullptr, xres);
    // hid = relu(x_res @ W1^T + b1)
    hmma_gemm<1><<<gg, bb, SM_TOT>>>(xres, 256, 8, wb + W1_OFF, 256,
                                     b1, nullptr, nullptr, nullptr, nullptr, hid);
    // xmlp = x_res + hid @ W2^T + b2
    hmma_gemm<2><<<gg, bb, SM_TOT>>>(hid, 256, 8, wb + W2_OFF, 256,
                                     b2, nullptr, nullptr, xres, nullptr, xmlp);
    // pool + classifier
    pool_cls_kernel<<<B_, bb>>>(xmlp, Wc, bc, out);
}

// round 10
// speedup vs baseline: 4.5466x; 1.2530x over previous
#include <cuda_runtime.h>
#include <cuda_bf16.h>
#include <math.h>
#include <stdint.h>

// ---------------------------------------------------------------------------
// Model dims
// ---------------------------------------------------------------------------
#define B_      64
#define N_      512
#define D_      256
#define H_      4
#define HD_     64
#define M_      (B_ * N_)         // 32768 rows
#define EPS_    1e-5f

// ---------------------------------------------------------------------------
// Scratch
// ---------------------------------------------------------------------------
__device__ float g_xp  [M_ * D_];
__device__ float g_yp  [M_ * D_];
__device__ float g_q   [M_ * D_];
__device__ float g_k   [M_ * D_];
__device__ float g_v   [M_ * D_];
__device__ float g_ctx [M_ * D_];
__device__ float g_xres[M_ * D_];
__device__ float g_hid [M_ * D_];
__device__ float g_xmlp[M_ * D_];
__device__ float g_pe  [N_ * D_];

// bf16 hi/lo weight scratch
#define WR_OFF  0
#define WF_OFF  (WR_OFF + 256 * 800)
#define WQ_OFF  (WF_OFF + 256 * 704)
#define WK_OFF  (WQ_OFF + 256 * 256)
#define WV_OFF  (WK_OFF + 256 * 256)
#define WO_OFF  (WV_OFF + 256 * 256)
#define W1_OFF  (WO_OFF + 256 * 256)
#define W2_OFF  (W1_OFF + 256 * 256)
#define WB_TOT  (W2_OFF + 256 * 256)
__device__ uint32_t g_wbuf[WB_TOT];

// ---------------------------------------------------------------------------
// hi = truncation to bf16 (exact); lo = rn-bf16(x - hi)
// ---------------------------------------------------------------------------
__device__ __forceinline__ uint32_t hi_pair(float x0, float x1) {
    uint32_t a = __float_as_uint(x0), b = __float_as_uint(x1);
    return (b & 0xffff0000u) | (a >> 16);
}
__device__ __forceinline__ uint32_t lo_pair(float x0, float x1) {
    float l0 = x0 - __uint_as_float(__float_as_uint(x0) & 0xffff0000u);
    float l1 = x1 - __uint_as_float(__float_as_uint(x1) & 0xffff0000u);
    uint32_t a = (uint32_t)__bfloat16_as_ushort(__float2bfloat16(l0));
    uint32_t b = (uint32_t)__bfloat16_as_ushort(__float2bfloat16(l1));
    return (b << 16) | a;
}

__device__ __forceinline__ uint32_t smem_u32(const void* p) {
    uint32_t a;
    asm("{ .reg .u64 t; cvta.to.shared.u64 t, %1; cvt.u32.u64 %0, t; }"
        : "=r"(a) : "l"(p));
    return a;
}

#define LDMX4(r0, r1, r2, r3, addr) \
    asm volatile("ldmatrix.sync.aligned.m8n8.x4.shared.b16 {%0,%1,%2,%3}, [%4];" \
                 : "=r"(r0), "=r"(r1), "=r"(r2), "=r"(r3) : "r"(addr))

#define MMA_BF16(c, a, b0, b1) \
    asm volatile("mma.sync.aligned.m16n8k16.row.col.f32.bf16.bf16.f32 " \
                 "{%0,%1,%2,%3}, {%4,%5,%6,%7}, {%8,%9}, {%0,%1,%2,%3};" \
                 : "+f"((c)[0]), "+f"((c)[1]), "+f"((c)[2]), "+f"((c)[3]) \
                 : "r"((a)[0]), "r"((a)[1]), "r"((a)[2]), "r"((a)[3]), \
                   "r"(b0), "r"(b1))

#define CPASYNC16(dst, src) \
    asm volatile("cp.async.cg.shared.global [%0], [%1], 16;" \
                 :: "r"(dst), "l"(src))
#define CPASYNC_COMMIT()  asm volatile("cp.async.commit_group;" ::: "memory")
#define CPASYNC_WAIT0()   asm volatile("cp.async.wait_group 0;" ::: "memory")

// fast 2^x for x <= 0; rel err ~1.5e-5; no MUFU
__device__ __forceinline__ float fexp2(float x) {
    x = fmaxf(x, -80.0f);
    float n = floorf(x);
    float f = x - n;
    float p = 1.5404e-4f;
    p = fmaf(p, f, 1.333356e-3f);
    p = fmaf(p, f, 9.618130e-3f);
    p = fmaf(p, f, 5.550411e-2f);
    p = fmaf(p, f, 2.402265e-1f);
    p = fmaf(p, f, 6.931472e-1f);
    p = fmaf(p, f, 1.0f);
    return __int_as_float(__float_as_int(p) + ((int)n << 23));
}

// ---------------------------------------------------------------------------
// Prologue: weight hi/lo conversion + PE table, one launch
// ---------------------------------------------------------------------------
__global__ void prep_kernel(const float* __restrict__ Wr, const float* __restrict__ Wf,
                            const float* __restrict__ Wq, const float* __restrict__ Wk,
                            const float* __restrict__ Wv, const float* __restrict__ Wo,
                            const float* __restrict__ W1, const float* __restrict__ W2) {
    int idx = blockIdx.x * blockDim.x + threadIdx.x;
    if (idx < WB_TOT) {
        const float* W; int K, rowU32, base;
        if      (idx < WF_OFF) { W = Wr; K = 769; rowU32 = 800; base = WR_OFF; }
        else if (idx < WQ_OFF) { W = Wf; K = 674; rowU32 = 704; base = WF_OFF; }
        else if (idx < WK_OFF) { W = Wq; K = 256; rowU32 = 256; base = WQ_OFF; }
        else if (idx < WV_OFF) { W = Wk; K = 256; rowU32 = 256; base = WK_OFF; }
        else if (idx < WO_OFF) { W = Wv; K = 256; rowU32 = 256; base = WV_OFF; }
        else if (idx < W1_OFF) { W = Wo; K = 256; rowU32 = 256; base = WO_OFF; }
        else if (idx < W2_OFF) { W = W1; K = 256; rowU32 = 256; base = W1_OFF; }
        else                   { W = W2; K = 256; rowU32 = 256; base = W2_OFF; }
        int j   = idx - base;
        int row = j / rowU32;
        int jj  = j - row * rowU32;
        int c   = jj >> 5;
        int t   = jj & 31;
        int e0  = c * 32 + ((t & 15) << 1);
        float v0 = (e0     < K) ? W[(size_t)row * K + e0]     : 0.0f;
        float v1 = (e0 + 1 < K) ? W[(size_t)row * K + e0 + 1] : 0.0f;
        g_wbuf[idx] = (t < 16) ? hi_pair(v0, v1) : lo_pair(v0, v1);
    } else if (idx < WB_TOT + N_ * D_) {
        int j   = idx - WB_TOT;
        int pos = j >> 8;
        int c   = j & 255;
        int i2  = c & ~1;
        float div = expf(-logf(10000.0f) * (float)i2 / (float)D_);
        float ang = (float)pos * div;
        g_pe[j] = (c & 1) ? cosf(ang) : sinf(ang);
    }
}

// ---------------------------------------------------------------------------
// HMMA GEMM (bf16x3), pipelined. CTA tile 64x256, 8 warps (2x4), warp 32x64.
// gridDim.y selects weight/bias/out set (for fused K+V launch).
// EPI: 0=+bias 1=relu(+bias) 2=+bias+res 3=LN(+bias[+pe][+res])
// ---------------------------------------------------------------------------
#define ROWB   144
#define ABUF   (64 * ROWB)
#define BBUF   (256 * ROWB)
#define BUFSZ  (ABUF + BBUF)
#define SM_TOT (2 * BUFSZ)

template <int EPI>
__global__ __launch_bounds__(256, 2) void hmma_gemm(
    const float* __restrict__ A, int K, int NC,
    const uint32_t* __restrict__ Wbf, int rowU32, int wstride,
    const float* __restrict__ bias, const float* __restrict__ bias2,
    const float* __restrict__ gamma,
    const float* __restrict__ beta,
    const float* __restrict__ res,
    const float* __restrict__ pe,
    float* __restrict__ out, float* __restrict__ out2)
{
    extern __shared__ __align__(16) char sm[];
    const uint32_t smb = smem_u32(sm);
    const int tid  = threadIdx.x;
    const int lane = tid & 31;
    const int warp = tid >> 5;
    const int wr   = warp >> 2;
    const int wc   = warp & 3;
    const int row0 = blockIdx.x * 64;

    const float* biasS = blockIdx.y ? bias2 : bias;
    float*       outS  = blockIdx.y ? out2  : out;

    const int arow = tid >> 2;
    const int aq   = tid & 3;
    const float* Ap = A + (size_t)(row0 + arow) * K + aq * 8;
    const uint32_t* Wp = Wbf + (size_t)blockIdx.y * wstride + (size_t)tid * rowU32;

    float acc[2][8][4];
#pragma unroll
    for (int mt = 0; mt < 2; ++mt)
#pragma unroll
        for (int nt = 0; nt < 8; ++nt)
#pragma unroll
            for (int i = 0; i < 4; ++i) acc[mt][nt][i] = 0.0f;

    const uint32_t a_rel = (uint32_t)(wr * 32 + (lane & 15)) * ROWB
                         + (uint32_t)(lane >> 4) * 16;
    const uint32_t b_rel = ABUF
                         + (uint32_t)(wc * 64 + ((lane >> 4) << 3) + (lane & 7)) * ROWB
                         + (uint32_t)((lane >> 3) & 1) * 16;

    auto ldgA = [&](int c, float* f) {
#pragma unroll
        for (int j = 0; j < 8; ++j) {
            int kg = c * 32 + aq * 8 + j;
            f[j] = (kg < K) ? Ap[c * 32 + j] : 0.0f;
        }
    };
    auto stsA = [&](const float* f, int p) {
        uint32_t hw[4], lw[4];
#pragma unroll
        for (int w = 0; w < 4; ++w) {
            hw[w] = hi_pair(f[2*w], f[2*w+1]);
            lw[w] = lo_pair(f[2*w], f[2*w+1]);
        }
        char* dh = sm + p * BUFSZ + arow * ROWB + aq * 16;
        *(uint4*)dh        = make_uint4(hw[0], hw[1], hw[2], hw[3]);
        *(uint4*)(dh + 64) = make_uint4(lw[0], lw[1], lw[2], lw[3]);
    };
    auto cpB = [&](int c, int p) {
        uint32_t dst = smb + p * BUFSZ + ABUF + tid * ROWB;
        const char* src = (const char*)(Wp + c * 32);
#pragma unroll
        for (int g2 = 0; g2 < 8; ++g2)
            CPASYNC16(dst + g2 * 16, src + g2 * 16);
    };

    {
        float f0[8];
        ldgA(0, f0);
        cpB(0, 0);
        CPASYNC_COMMIT();
        stsA(f0, 0);
        CPASYNC_WAIT0();
    }
    __syncthreads();

    int p = 0;
    for (int c = 0; c < NC; ++c) {
        const bool have = (c + 1 < NC);
        float fn[8];
        if (have) {
            cpB(c + 1, p ^ 1);
            CPASYNC_COMMIT();
            ldgA(c + 1, fn);
        }
        const uint32_t ab = smb + p * BUFSZ + a_rel;
        const uint32_t bb = smb + p * BUFSZ + b_rel;
#pragma unroll
        for (int ks = 0; ks < 2; ++ks) {
            uint32_t ah[2][4], al[2][4];
#pragma unroll
            for (int mt = 0; mt < 2; ++mt) {
                LDMX4(ah[mt][0], ah[mt][1], ah[mt][2], ah[mt][3],
                      ab + mt * (16 * ROWB) + ks * 32);
                LDMX4(al[mt][0], al[mt][1], al[mt][2], al[mt][3],
                      ab + mt * (16 * ROWB) + ks * 32 + 64);
            }
#pragma unroll
            for (int npp = 0; npp < 2; ++npp) {
                const int np0 = npp * 2, np1 = npp * 2 + 1;
                uint32_t bh0[4], bl0[4], bh1[4], bl1[4];
                LDMX4(bh0[0], bh0[1], bh0[2], bh0[3],
                      bb + np0 * (16 * ROWB) + ks * 32);
                LDMX4(bl0[0], bl0[1], bl0[2], bl0[3],
                      bb + np0 * (16 * ROWB) + ks * 32 + 64);
                LDMX4(bh1[0], bh1[1], bh1[2], bh1[3],
                      bb + np1 * (16 * ROWB) + ks * 32);
                LDMX4(bl1[0], bl1[1], bl1[2], bl1[3],
                      bb + np1 * (16 * ROWB) + ks * 32 + 64);
                MMA_BF16(acc[0][2*np0],   ah[0], bh0[0], bh0[1]);
                MMA_BF16(acc[1][2*np0],   ah[1], bh0[0], bh0[1]);
                MMA_BF16(acc[0][2*np0+1], ah[0], bh0[2], bh0[3]);
                MMA_BF16(acc[1][2*np0+1], ah[1], bh0[2], bh0[3]);
                MMA_BF16(acc[0][2*np1],   ah[0], bh1[0], bh1[1]);
                MMA_BF16(acc[1][2*np1],   ah[1], bh1[0], bh1[1]);
                MMA_BF16(acc[0][2*np1+1], ah[0], bh1[2], bh1[3]);
                MMA_BF16(acc[1][2*np1+1], ah[1], bh1[2], bh1[3]);
                MMA_BF16(acc[0][2*np0],   al[0], bh0[0], bh0[1]);
                MMA_BF16(acc[1][2*np0],   al[1], bh0[0], bh0[1]);
                MMA_BF16(acc[0][2*np0+1], al[0], bh0[2], bh0[3]);
                MMA_BF16(acc[1][2*np0+1], al[1], bh0[2], bh0[3]);
                MMA_BF16(acc[0][2*np1],   al[0], bh1[0], bh1[1]);
                MMA_BF16(acc[1][2*np1],   al[1], bh1[0], bh1[1]);
                MMA_BF16(acc[0][2*np1+1], al[0], bh1[2], bh1[3]);
                MMA_BF16(acc[1][2*np1+1], al[1], bh1[2], bh1[3]);
                MMA_BF16(acc[0][2*np0],   ah[0], bl0[0], bl0[1]);
                MMA_BF16(acc[1][2*np0],   ah[1], bl0[0], bl0[1]);
                MMA_BF16(acc[0][2*np0+1], ah[0], bl0[2], bl0[3]);
                MMA_BF16(acc[1][2*np0+1], ah[1], bl0[2], bl0[3]);
                MMA_BF16(acc[0][2*np1],   ah[0], bl1[0], bl1[1]);
                MMA_BF16(acc[1][2*np1],   ah[1], bl1[0], bl1[1]);
                MMA_BF16(acc[0][2*np1+1], ah[0], bl1[2], bl1[3]);
                MMA_BF16(acc[1][2*np1+1], ah[1], bl1[2], bl1[3]);
            }
        }
        if (have) stsA(fn, p ^ 1);
        CPASYNC_WAIT0();
        __syncthreads();
        p ^= 1;
    }

    // ---------------- epilogue ----------------
    const int g  = lane >> 2;
    const int t4 = lane & 3;

#pragma unroll
    for (int nt = 0; nt < 8; ++nt) {
        int cc = wc * 64 + nt * 8 + t4 * 2;
        float b0 = biasS[cc], b1 = biasS[cc + 1];
#pragma unroll
        for (int mt = 0; mt < 2; ++mt) {
            acc[mt][nt][0] += b0; acc[mt][nt][1] += b1;
            acc[mt][nt][2] += b0; acc[mt][nt][3] += b1;
        }
    }
    if (EPI == 3) {
#pragma unroll
        for (int mt = 0; mt < 2; ++mt)
#pragma unroll
            for (int h = 0; h < 2; ++h) {
                int row  = wr * 32 + mt * 16 + g + h * 8;
                int grow = row0 + row;
                if (pe) {
                    const float* pp = pe + (size_t)(grow & (N_ - 1)) * D_;
#pragma unroll
                    for (int nt = 0; nt < 8; ++nt) {
                        int cc = wc * 64 + nt * 8 + t4 * 2;
                        float2 pv = *(const float2*)&pp[cc];
                        acc[mt][nt][h*2]   += pv.x;
                        acc[mt][nt][h*2+1] += pv.y;
                    }
                }
                if (res) {
                    const float* rp = res + (size_t)grow * D_;
#pragma unroll
                    for (int nt = 0; nt < 8; ++nt) {
                        int cc = wc * 64 + nt * 8 + t4 * 2;
                        float2 rv = *(const float2*)&rp[cc];
                        acc[mt][nt][h*2]   += rv.x;
                        acc[mt][nt][h*2+1] += rv.y;
                    }
                }
            }

        float* lnsum = (float*)sm;
        float* lnsq  = (float*)sm + 256;
#pragma unroll
        for (int mt = 0; mt < 2; ++mt)
#pragma unroll
            for (int h = 0; h < 2; ++h) {
                float s = 0.0f, q = 0.0f;
#pragma unroll
                for (int nt = 0; nt < 8; ++nt) {
                    float v0 = acc[mt][nt][h*2], v1 = acc[mt][nt][h*2+1];
                    s += v0 + v1;
                    q = fmaf(v0, v0, q); q = fmaf(v1, v1, q);
                }
#pragma unroll
                for (int off = 1; off <= 2; off <<= 1) {
                    s += __shfl_xor_sync(0xffffffffu, s, off);
                    q += __shfl_xor_sync(0xffffffffu, q, off);
                }
                if (t4 == 0) {
                    int row = wr * 32 + mt * 16 + g + h * 8;
                    lnsum[row * 4 + wc] = s;
                    lnsq [row * 4 + wc] = q;
                }
            }
        __syncthreads();

#pragma unroll
        for (int mt = 0; mt < 2; ++mt)
#pragma unroll
            for (int h = 0; h < 2; ++h) {
                int row  = wr * 32 + mt * 16 + g + h * 8;
                int grow = row0 + row;
                float s = lnsum[row*4] + lnsum[row*4+1] + lnsum[row*4+2] + lnsum[row*4+3];
                float q = lnsq [row*4] + lnsq [row*4+1] + lnsq [row*4+2] + lnsq [row*4+3];
                float mu  = s * (1.0f / 256.0f);
                float var = q * (1.0f / 256.0f) - mu * mu;
                float rs  = rsqrtf(var + EPS_);
                float* op = outS + (size_t)grow * D_;
#pragma unroll
                for (int nt = 0; nt < 8; ++nt) {
                    int cc = wc * 64 + nt * 8 + t4 * 2;
                    float v0 = (acc[mt][nt][h*2]   - mu) * rs * gamma[cc]   + beta[cc];
                    float v1 = (acc[mt][nt][h*2+1] - mu) * rs * gamma[cc+1] + beta[cc+1];
                    *(float2*)&op[cc] = make_float2(v0, v1);
                }
            }
    } else {
#pragma unroll
        for (int mt = 0; mt < 2; ++mt)
#pragma unroll
            for (int h = 0; h < 2; ++h) {
                int row  = wr * 32 + mt * 16 + g + h * 8;
                int grow = row0 + row;
                const float* rp = (EPI == 2) ? res + (size_t)grow * D_ : nullptr;
                float* op = outS + (size_t)grow * D_;
#pragma unroll
                for (int nt = 0; nt < 8; ++nt) {
                    int cc = wc * 64 + nt * 8 + t4 * 2;
                    float v0 = acc[mt][nt][h*2];
                    float v1 = acc[mt][nt][h*2+1];
                    if (EPI == 1) { v0 = fmaxf(v0, 0.0f); v1 = fmaxf(v1, 0.0f); }
                    if (EPI == 2) {
                        float2 rv = *(const float2*)&rp[cc];
                        v0 += rv.x; v1 += rv.y;
                    }
                    *(float2*)&op[cc] = make_float2(v0, v1);
                }
            }
    }
}

// ---------------------------------------------------------------------------
// HMMA flash attention v2: 256 threads, 128 q-rows per CTA (8 warps x 16),
// K/V tile staged once per CTA and shared by all 8 warps. bf16x3 everywhere;
// base-2 online softmax; P built in-register from S.
// ---------------------------------------------------------------------------
#define AROWB   272
#define AQ_OFF  0
#define AK_OFF  (128 * AROWB)
#define AV_OFF  (AK_OFF + 64 * AROWB)
#define ASM_TOT (AV_OFF + 64 * AROWB)     // 69632
#define QSCALE  0.1803368801111204f       // 0.125 * log2(e)

__global__ __launch_bounds__(256, 2) void attn_kernel(
    const float* __restrict__ q,
    const float* __restrict__ k,
    const float* __restrict__ v,
    float* __restrict__ ctx)
{
    extern __shared__ __align__(16) char asm_[];
    const uint32_t smb = smem_u32(asm_);
    const int tid  = threadIdx.x;
    const int lane = tid & 31;
    const int warp = tid >> 5;
    const int bh   = blockIdx.y;
    const int b    = bh >> 2;
    const int h    = bh & 3;
    const int q0   = blockIdx.x * 128;
    const int g    = lane >> 2;
    const int t4   = lane & 3;

    // ---- stage Q (scaled): row = tid>>1 (0..127), half = tid&1 (32 cols)
    {
        const int r  = tid >> 1;
        const int hf = tid & 1;
        const float* qp = q + ((size_t)(b * N_ + q0 + r)) * D_ + h * HD_ + hf * 32;
        float f[32];
#pragma unroll
        for (int j = 0; j < 32; ++j) f[j] = qp[j] * QSCALE;
        uint32_t hw[16], lw[16];
#pragma unroll
        for (int w = 0; w < 16; ++w) {
            hw[w] = hi_pair(f[2*w], f[2*w+1]);
            lw[w] = lo_pair(f[2*w], f[2*w+1]);
        }
        char* dh = asm_ + AQ_OFF + r * AROWB + hf * 64;
        char* dl = dh + 128;
#pragma unroll
        for (int g2 = 0; g2 < 4; ++g2) {
            *(uint4*)(dh + g2 * 16) =
                make_uint4(hw[4*g2], hw[4*g2+1], hw[4*g2+2], hw[4*g2+3]);
            *(uint4*)(dl + g2 * 16) =
                make_uint4(lw[4*g2], lw[4*g2+1], lw[4*g2+2], lw[4*g2+3]);
        }
    }

    const uint32_t a_base = smb + AQ_OFF
        + (uint32_t)(warp * 16 + (lane & 15)) * AROWB + (uint32_t)(lane >> 4) * 16;
    const uint32_t kb_base = smb + AK_OFF
        + (uint32_t)(((lane >> 4) << 3) + (lane & 7)) * AROWB
        + (uint32_t)((lane >> 3) & 1) * 16;
    const uint32_t vb_base = smb + AV_OFF
        + (uint32_t)(((lane >> 4) << 3) + (lane & 7)) * AROWB
        + (uint32_t)((lane >> 3) & 1) * 16;

    float acc_o[8][4];
#pragma unroll
    for (int nt = 0; nt < 8; ++nt)
#pragma unroll
        for (int i = 0; i < 4; ++i) acc_o[nt][i] = 0.0f;
    float mrow[2] = {-1e30f, -1e30f};
    float lrow[2] = {0.0f, 0.0f};

    for (int t0 = 0; t0 < N_; t0 += 64) {
        __syncthreads();
        // ---- stage K: row = tid>>2 (0..63), quarter = tid&3 (16 cols)
        {
            const int r  = tid >> 2;
            const int qd = tid & 3;
            const float* kp = k + ((size_t)(b * N_ + t0 + r)) * D_ + h * HD_ + qd * 16;
            float f[16];
#pragma unroll
            for (int j = 0; j < 16; ++j) f[j] = kp[j];
            uint32_t hw[8], lw[8];
#pragma unroll
            for (int w = 0; w < 8; ++w) {
                hw[w] = hi_pair(f[2*w], f[2*w+1]);
                lw[w] = lo_pair(f[2*w], f[2*w+1]);
            }
            char* dh = asm_ + AK_OFF + r * AROWB + qd * 32;
            char* dl = dh + 128;
#pragma unroll
            for (int g2 = 0; g2 < 2; ++g2) {
                *(uint4*)(dh + g2 * 16) =
                    make_uint4(hw[4*g2], hw[4*g2+1], hw[4*g2+2], hw[4*g2+3]);
                *(uint4*)(dl + g2 * 16) =
                    make_uint4(lw[4*g2], lw[4*g2+1], lw[4*g2+2], lw[4*g2+3]);
            }
        }
        // ---- stage V transposed: lane = kv-pair (0..31), warp owns 8 hd rows
        // store addr word = hd*68 + lane -> conflict-free across the warp
        {
            const float* v0p = v + ((size_t)(b * N_ + t0 + 2*lane))     * D_ + h * HD_ + warp * 8;
            const float* v1p = v + ((size_t)(b * N_ + t0 + 2*lane + 1)) * D_ + h * HD_ + warp * 8;
            float f0[8], f1[8];
            *(float4*)&f0[0] = *(const float4*)&v0p[0];
            *(float4*)&f0[4] = *(const float4*)&v0p[4];
            *(float4*)&f1[0] = *(const float4*)&v1p[0];
            *(float4*)&f1[4] = *(const float4*)&v1p[4];
#pragma unroll
            for (int j = 0; j < 8; ++j) {
                int hd = warp * 8 + j;
                *(uint32_t*)(asm_ + AV_OFF + hd * AROWB + lane * 4)       = hi_pair(f0[j], f1[j]);
                *(uint32_t*)(asm_ + AV_OFF + hd * AROWB + 128 + lane * 4) = lo_pair(f0[j], f1[j]);
            }
        }
        __syncthreads();

        // ---- S = Q K^T
        float s[8][4];
#pragma unroll
        for (int nt = 0; nt < 8; ++nt)
#pragma unroll
            for (int i = 0; i < 4; ++i) s[nt][i] = 0.0f;
#pragma unroll
        for (int ks = 0; ks < 4; ++ks) {
            uint32_t ah[4], al[4];
            LDMX4(ah[0], ah[1], ah[2], ah[3], a_base + ks * 32);
            LDMX4(al[0], al[1], al[2], al[3], a_base + ks * 32 + 128);
#pragma unroll
            for (int npp = 0; npp < 2; ++npp) {
                const int np0 = npp * 2, np1 = npp * 2 + 1;
                uint32_t bh0[4], bl0[4], bh1[4], bl1[4];
                LDMX4(bh0[0], bh0[1], bh0[2], bh0[3],
                      kb_base + np0 * (16 * AROWB) + ks * 32);
                LDMX4(bl0[0], bl0[1], bl0[2], bl0[3],
                      kb_base + np0 * (16 * AROWB) + ks * 32 + 128);
                LDMX4(bh1[0], bh1[1], bh1[2], bh1[3],
                      kb_base + np1 * (16 * AROWB) + ks * 32);
                LDMX4(bl1[0], bl1[1], bl1[2], bl1[3],
                      kb_base + np1 * (16 * AROWB) + ks * 32 + 128);
                MMA_BF16(s[2*np0],     ah, bh0[0], bh0[1]);
                MMA_BF16(s[2*np0 + 1], ah, bh0[2], bh0[3]);
                MMA_BF16(s[2*np1],     ah, bh1[0], bh1[1]);
                MMA_BF16(s[2*np1 + 1], ah, bh1[2], bh1[3]);
                MMA_BF16(s[2*np0],     al, bh0[0], bh0[1]);
                MMA_BF16(s[2*np0 + 1], al, bh0[2], bh0[3]);
                MMA_BF16(s[2*np1],     al, bh1[0], bh1[1]);
                MMA_BF16(s[2*np1 + 1], al, bh1[2], bh1[3]);
                MMA_BF16(s[2*np0],     ah, bl0[0], bl0[1]);
                MMA_BF16(s[2*np0 + 1], ah, bl0[2], bl0[3]);
                MMA_BF16(s[2*np1],     ah, bl1[0], bl1[1]);
                MMA_BF16(s[2*np1 + 1], ah, bl1[2], bl1[3]);
            }
        }

        // ---- online softmax (base 2)
#pragma unroll
        for (int r2 = 0; r2 < 2; ++r2) {
            float mx = -1e30f;
#pragma unroll
            for (int nt = 0; nt < 8; ++nt)
                mx = fmaxf(mx, fmaxf(s[nt][r2*2], s[nt][r2*2+1]));
#pragma unroll
            for (int off = 1; off <= 2; off <<= 1)
                mx = fmaxf(mx, __shfl_xor_sync(0xffffffffu, mx, off));
            float mnew = fmaxf(mrow[r2], mx);
            float corr = fexp2(mrow[r2] - mnew);
            float ps = 0.0f;
#pragma unroll
            for (int nt = 0; nt < 8; ++nt) {
                float p0 = fexp2(s[nt][r2*2]   - mnew);
                float p1 = fexp2(s[nt][r2*2+1] - mnew);
                s[nt][r2*2] = p0; s[nt][r2*2+1] = p1;
                ps += p0 + p1;
            }
#pragma unroll
            for (int off = 1; off <= 2; off <<= 1)
                ps += __shfl_xor_sync(0xffffffffu, ps, off);
            lrow[r2] = lrow[r2] * corr + ps;
            mrow[r2] = mnew;
#pragma unroll
            for (int nt = 0; nt < 8; ++nt) {
                acc_o[nt][r2*2]   *= corr;
                acc_o[nt][r2*2+1] *= corr;
            }
        }

        // ---- O += P V
#pragma unroll
        for (int kt = 0; kt < 4; ++kt) {
            uint32_t pah[4], pal[4];
            pah[0] = hi_pair(s[2*kt][0],   s[2*kt][1]);
            pah[1] = hi_pair(s[2*kt][2],   s[2*kt][3]);
            pah[2] = hi_pair(s[2*kt+1][0], s[2*kt+1][1]);
            pah[3] = hi_pair(s[2*kt+1][2], s[2*kt+1][3]);
            pal[0] = lo_pair(s[2*kt][0],   s[2*kt][1]);
            pal[1] = lo_pair(s[2*kt][2],   s[2*kt][3]);
            pal[2] = lo_pair(s[2*kt+1][0], s[2*kt+1][1]);
            pal[3] = lo_pair(s[2*kt+1][2], s[2*kt+1][3]);
#pragma unroll
            for (int npp = 0; npp < 2; ++npp) {
                const int np0 = npp * 2, np1 = npp * 2 + 1;
                uint32_t vh0[4], vl0[4], vh1[4], vl1[4];
                LDMX4(vh0[0], vh0[1], vh0[2], vh0[3],
                      vb_base + np0 * (16 * AROWB) + kt * 32);
                LDMX4(vl0[0], vl0[1], vl0[2], vl0[3],
                      vb_base + np0 * (16 * AROWB) + kt * 32 + 128);
                LDMX4(vh1[0], vh1[1], vh1[2], vh1[3],
                      vb_base + np1 * (16 * AROWB) + kt * 32);
                LDMX4(vl1[0], vl1[1], vl1[2], vl1[3],
                      vb_base + np1 * (16 * AROWB) + kt * 32 + 128);
                MMA_BF16(acc_o[2*np0],     pah, vh0[0], vh0[1]);
                MMA_BF16(acc_o[2*np0 + 1], pah, vh0[2], vh0[3]);
                MMA_BF16(acc_o[2*np1],     pah, vh1[0], vh1[1]);
                MMA_BF16(acc_o[2*np1 + 1], pah, vh1[2], vh1[3]);
                MMA_BF16(acc_o[2*np0],     pal, vh0[0], vh0[1]);
                MMA_BF16(acc_o[2*np0 + 1], pal, vh0[2], vh0[3]);
                MMA_BF16(acc_o[2*np1],     pal, vh1[0], vh1[1]);
                MMA_BF16(acc_o[2*np1 + 1], pal, vh1[2], vh1[3]);
                MMA_BF16(acc_o[2*np0],     pah, vl0[0], vl0[1]);
                MMA_BF16(acc_o[2*np0 + 1], pah, vl0[2], vl0[3]);
                MMA_BF16(acc_o[2*np1],     pah, vl1[0], vl1[1]);
                MMA_BF16(acc_o[2*np1 + 1], pah, vl1[2], vl1[3]);
            }
        }
    }

    float inv0 = 1.0f / lrow[0];
    float inv1 = 1.0f / lrow[1];
#pragma unroll
    for (int r2 = 0; r2 < 2; ++r2) {
        int grow = b * N_ + q0 + warp * 16 + g + r2 * 8;
        float inv = r2 ? inv1 : inv0;
        float* cp = ctx + (size_t)grow * D_ + h * HD_;
#pragma unroll
        for (int nt = 0; nt < 8; ++nt) {
            int cc = nt * 8 + t4 * 2;
            *(float2*)&cp[cc] = make_float2(acc_o[nt][r2*2] * inv,
                                            acc_o[nt][r2*2+1] * inv);
        }
    }
}

// ---------------------------------------------------------------------------
// mean-pool + classifier
// ---------------------------------------------------------------------------
__global__ __launch_bounds__(256) void pool_cls_kernel(
    const float* __restrict__ xm,
    const float* __restrict__ Wc,
    const float* __restrict__ bc,
    float* __restrict__ out)
{
    __shared__ float pooled[D_];
    const int b = blockIdx.x;
    const int t = threadIdx.x;
    float s = 0.0f;
    const float* p = xm + (size_t)b * N_ * D_ + t;
#pragma unroll 8
    for (int n = 0; n < N_; ++n) s += p[(size_t)n * D_];
    pooled[t] = s * (1.0f / (float)N_);
    __syncthreads();
    if (t < 2) {
        float a = bc[t];
        for (int c = 0; c < D_; ++c) a = fmaf(pooled[c], Wc[t * D_ + c], a);
        out[b * 2 + t] = a;
    }
}

// ---------------------------------------------------------------------------
// Launch
// ---------------------------------------------------------------------------
static float* sym(const void* s) {
    void* p = nullptr;
    cudaGetSymbolAddress(&p, s);
    return (float*)p;
}

extern "C" void kernel_launch(void* const* d_in, const int* in_sizes, int n_in,
                              void* d_out, int out_size)
{
    const float* x   = (const float*)d_in[0];
    const float* y   = (const float*)d_in[1];
    const float* Wr  = (const float*)d_in[3];
    const float* br  = (const float*)d_in[4];
    const float* Wf  = (const float*)d_in[5];
    const float* bf  = (const float*)d_in[6];
    const float* g_x = (const float*)d_in[7];
    const float* b_x = (const float*)d_in[8];
    const float* g_y = (const float*)d_in[9];
    const float* b_y = (const float*)d_in[10];
    const float* Wq  = (const float*)d_in[11];
    const float* bq  = (const float*)d_in[12];
    const float* Wk  = (const float*)d_in[13];
    const float* bk  = (const float*)d_in[14];
    const float* Wv  = (const float*)d_in[15];
    const float* bv  = (const float*)d_in[16];
    const float* Wo  = (const float*)d_in[17];
    const float* bo  = (const float*)d_in[18];
    const float* g_m = (const float*)d_in[19];
    const float* b_m = (const float*)d_in[20];
    const float* W1  = (const float*)d_in[21];
    const float* b1  = (const float*)d_in[22];
    const float* W2  = (const float*)d_in[23];
    const float* b2  = (const float*)d_in[24];
    const float* Wc  = (const float*)d_in[25];
    const float* bc  = (const float*)d_in[26];
    float* out = (float*)d_out;

    float* xp   = sym(g_xp);
    float* yp   = sym(g_yp);
    float* qb   = sym(g_q);
    float* kb   = sym(g_k);
    float* vb   = sym(g_v);
    float* ctx  = sym(g_ctx);
    float* xres = sym(g_xres);
    float* hid  = sym(g_hid);
    float* xmlp = sym(g_xmlp);
    float* pe   = sym(g_pe);
    uint32_t* wb;
    {
        void* p = nullptr;
        cudaGetSymbolAddress(&p, g_wbuf);
        wb = (uint32_t*)p;
    }

    static bool attr_set = false;
    if (!attr_set) {
        cudaFuncSetAttribute(attn_kernel,
                             cudaFuncAttributeMaxDynamicSharedMemorySize, ASM_TOT);
        cudaFuncSetAttribute(hmma_gemm<0>,
                             cudaFuncAttributeMaxDynamicSharedMemorySize, SM_TOT);
        cudaFuncSetAttribute(hmma_gemm<1>,
                             cudaFuncAttributeMaxDynamicSharedMemorySize, SM_TOT);
        cudaFuncSetAttribute(hmma_gemm<2>,
                             cudaFuncAttributeMaxDynamicSharedMemorySize, SM_TOT);
        cudaFuncSetAttribute(hmma_gemm<3>,
                             cudaFuncAttributeMaxDynamicSharedMemorySize, SM_TOT);
        attr_set = true;
    }

    dim3 gg(M_ / 64);     // 512 CTAs
    dim3 bb(256);

    prep_kernel<<<(WB_TOT + N_ * D_ + 255) / 256, 256>>>(Wr, Wf, Wq, Wk, Wv, Wo, W1, W2);

    // xp = LN(x @ Wr^T + br + pe)
    hmma_gemm<3><<<gg, bb, SM_TOT>>>(x, 769, 25, wb + WR_OFF, 800, 0,
                                     br, nullptr, g_x, b_x, nullptr, pe, xp, nullptr);
    // yp = LN(y @ Wf^T + bf + pe)
    hmma_gemm<3><<<gg, bb, SM_TOT>>>(y, 674, 22, wb + WF_OFF, 704, 0,
                                     bf, nullptr, g_y, b_y, nullptr, pe, yp, nullptr);
    // q
    hmma_gemm<0><<<gg, bb, SM_TOT>>>(xp, 256, 8, wb + WQ_OFF, 256, 0,
                                     bq, nullptr, nullptr, nullptr, nullptr, nullptr,
                                     qb, nullptr);
    // k + v fused (gridDim.y = 2)
    hmma_gemm<0><<<dim3(M_ / 64, 2), bb, SM_TOT>>>(yp, 256, 8, wb + WK_OFF, 256,
                                     256 * 256,
                                     bk, bv, nullptr, nullptr, nullptr, nullptr,
                                     kb, vb);
    // attention (HMMA, 128 q-rows/CTA)
    dim3 ag(N_ / 128, B_ * H_);
    attn_kernel<<<ag, bb, ASM_TOT>>>(qb, kb, vb, ctx);
    // x_res = LN(xp + ctx @ Wo^T + bo)
    hmma_gemm<3><<<gg, bb, SM_TOT>>>(ctx, 256, 8, wb + WO_OFF, 256, 0,
                                     bo, nullptr, g_m, b_m, xp, nullptr, xres, nullptr);
    // hid = relu(x_res @ W1^T + b1)
    hmma_gemm<1><<<gg, bb, SM_TOT>>>(xres, 256, 8, wb + W1_OFF, 256, 0,
                                     b1, nullptr, nullptr, nullptr, nullptr, nullptr,
                                     hid, nullptr);
    // xmlp = x_res + hid @ W2^T + b2
    hmma_gemm<2><<<gg, bb, SM_TOT>>>(hid, 256, 8, wb + W2_OFF, 256, 0,
                                     b2, nullptr, nullptr, nullptr, xres, nullptr,
                                     xmlp, nullptr);
    // pool + classifier
    pool_cls_kernel<<<B_, bb>>>(xmlp, Wc, bc, out);
}

// round 11
// speedup vs baseline: 4.8627x; 1.0695x over previous
#include <cuda_runtime.h>
#include <cuda_bf16.h>
#include <math.h>
#include <stdint.h>

// ---------------------------------------------------------------------------
// Model dims
// ---------------------------------------------------------------------------
#define B_      64
#define N_      512
#define D_      256
#define H_      4
#define HD_     64
#define M_      (B_ * N_)         // 32768 rows
#define EPS_    1e-5f

// ---------------------------------------------------------------------------
// Scratch
// ---------------------------------------------------------------------------
__device__ float g_xp  [M_ * D_];
__device__ float g_yp  [M_ * D_];
__device__ float g_q   [M_ * D_];
__device__ float g_k   [M_ * D_];
__device__ float g_v   [M_ * D_];
__device__ float g_ctx [M_ * D_];
__device__ float g_xres[M_ * D_];
__device__ float g_hid [M_ * D_];
__device__ float g_xmlp[M_ * D_];
__device__ float g_pe  [N_ * D_];

// bf16 hi/lo weight scratch
#define WR_OFF  0
#define WF_OFF  (WR_OFF + 256 * 800)
#define WQ_OFF  (WF_OFF + 256 * 704)
#define WK_OFF  (WQ_OFF + 256 * 256)
#define WV_OFF  (WK_OFF + 256 * 256)
#define WO_OFF  (WV_OFF + 256 * 256)
#define W1_OFF  (WO_OFF + 256 * 256)
#define W2_OFF  (W1_OFF + 256 * 256)
#define WB_TOT  (W2_OFF + 256 * 256)
__device__ uint32_t g_wbuf[WB_TOT];

// ---------------------------------------------------------------------------
// hi = truncation to bf16 (exact); lo = rn-bf16(x - hi)
// ---------------------------------------------------------------------------
__device__ __forceinline__ uint32_t hi_pair(float x0, float x1) {
    uint32_t a = __float_as_uint(x0), b = __float_as_uint(x1);
    return (b & 0xffff0000u) | (a >> 16);
}
__device__ __forceinline__ uint32_t lo_pair(float x0, float x1) {
    float l0 = x0 - __uint_as_float(__float_as_uint(x0) & 0xffff0000u);
    float l1 = x1 - __uint_as_float(__float_as_uint(x1) & 0xffff0000u);
    uint32_t a = (uint32_t)__bfloat16_as_ushort(__float2bfloat16(l0));
    uint32_t b = (uint32_t)__bfloat16_as_ushort(__float2bfloat16(l1));
    return (b << 16) | a;
}

__device__ __forceinline__ uint32_t smem_u32(const void* p) {
    uint32_t a;
    asm("{ .reg .u64 t; cvta.to.shared.u64 t, %1; cvt.u32.u64 %0, t; }"
        : "=r"(a) : "l"(p));
    return a;
}

#define LDMX4(r0, r1, r2, r3, addr) \
    asm volatile("ldmatrix.sync.aligned.m8n8.x4.shared.b16 {%0,%1,%2,%3}, [%4];" \
                 : "=r"(r0), "=r"(r1), "=r"(r2), "=r"(r3) : "r"(addr))

#define MMA_BF16(c, a, b0, b1) \
    asm volatile("mma.sync.aligned.m16n8k16.row.col.f32.bf16.bf16.f32 " \
                 "{%0,%1,%2,%3}, {%4,%5,%6,%7}, {%8,%9}, {%0,%1,%2,%3};" \
                 : "+f"((c)[0]), "+f"((c)[1]), "+f"((c)[2]), "+f"((c)[3]) \
                 : "r"((a)[0]), "r"((a)[1]), "r"((a)[2]), "r"((a)[3]), \
                   "r"(b0), "r"(b1))

#define CPASYNC16(dst, src) \
    asm volatile("cp.async.cg.shared.global [%0], [%1], 16;" \
                 :: "r"(dst), "l"(src))
#define CPASYNC_COMMIT()  asm volatile("cp.async.commit_group;" ::: "memory")
#define CPASYNC_WAIT0()   asm volatile("cp.async.wait_group 0;" ::: "memory")

// fast 2^x for x <= 0; rel err ~1.5e-5; no MUFU
__device__ __forceinline__ float fexp2(float x) {
    x = fmaxf(x, -80.0f);
    float n = floorf(x);
    float f = x - n;
    float p = 1.5404e-4f;
    p = fmaf(p, f, 1.333356e-3f);
    p = fmaf(p, f, 9.618130e-3f);
    p = fmaf(p, f, 5.550411e-2f);
    p = fmaf(p, f, 2.402265e-1f);
    p = fmaf(p, f, 6.931472e-1f);
    p = fmaf(p, f, 1.0f);
    return __int_as_float(__float_as_int(p) + ((int)n << 23));
}

// ---------------------------------------------------------------------------
// Prologue: weight hi/lo conversion + PE table, one launch
// ---------------------------------------------------------------------------
__global__ void prep_kernel(const float* __restrict__ Wr, const float* __restrict__ Wf,
                            const float* __restrict__ Wq, const float* __restrict__ Wk,
                            const float* __restrict__ Wv, const float* __restrict__ Wo,
                            const float* __restrict__ W1, const float* __restrict__ W2) {
    int idx = blockIdx.x * blockDim.x + threadIdx.x;
    if (idx < WB_TOT) {
        const float* W; int K, rowU32, base;
        if      (idx < WF_OFF) { W = Wr; K = 769; rowU32 = 800; base = WR_OFF; }
        else if (idx < WQ_OFF) { W = Wf; K = 674; rowU32 = 704; base = WF_OFF; }
        else if (idx < WK_OFF) { W = Wq; K = 256; rowU32 = 256; base = WQ_OFF; }
        else if (idx < WV_OFF) { W = Wk; K = 256; rowU32 = 256; base = WK_OFF; }
        else if (idx < WO_OFF) { W = Wv; K = 256; rowU32 = 256; base = WV_OFF; }
        else if (idx < W1_OFF) { W = Wo; K = 256; rowU32 = 256; base = WO_OFF; }
        else if (idx < W2_OFF) { W = W1; K = 256; rowU32 = 256; base = W1_OFF; }
        else                   { W = W2; K = 256; rowU32 = 256; base = W2_OFF; }
        int j   = idx - base;
        int row = j / rowU32;
        int jj  = j - row * rowU32;
        int c   = jj >> 5;
        int t   = jj & 31;
        int e0  = c * 32 + ((t & 15) << 1);
        float v0 = (e0     < K) ? W[(size_t)row * K + e0]     : 0.0f;
        float v1 = (e0 + 1 < K) ? W[(size_t)row * K + e0 + 1] : 0.0f;
        g_wbuf[idx] = (t < 16) ? hi_pair(v0, v1) : lo_pair(v0, v1);
    } else if (idx < WB_TOT + N_ * D_) {
        int j   = idx - WB_TOT;
        int pos = j >> 8;
        int c   = j & 255;
        int i2  = c & ~1;
        float div = expf(-logf(10000.0f) * (float)i2 / (float)D_);
        float ang = (float)pos * div;
        g_pe[j] = (c & 1) ? cosf(ang) : sinf(ang);
    }
}

#define ROWB   144

// ---------------------------------------------------------------------------
// hmma_gemm: 64x256 tile, LN-capable (EPI 3 users: Wr, Wf, Wo). Unchanged.
// ---------------------------------------------------------------------------
#define ABUF   (64 * ROWB)
#define BBUF   (256 * ROWB)
#define BUFSZ  (ABUF + BBUF)
#define SM_TOT (2 * BUFSZ)

template <int EPI>
__global__ __launch_bounds__(256, 2) void hmma_gemm(
    const float* __restrict__ A, int K, int NC,
    const uint32_t* __restrict__ Wbf, int rowU32,
    const float* __restrict__ bias,
    const float* __restrict__ gamma,
    const float* __restrict__ beta,
    const float* __restrict__ res,
    const float* __restrict__ pe,
    float* __restrict__ out)
{
    extern __shared__ __align__(16) char sm[];
    const uint32_t smb = smem_u32(sm);
    const int tid  = threadIdx.x;
    const int lane = tid & 31;
    const int warp = tid >> 5;
    const int wr   = warp >> 2;
    const int wc   = warp & 3;
    const int row0 = blockIdx.x * 64;

    const int arow = tid >> 2;
    const int aq   = tid & 3;
    const float* Ap = A + (size_t)(row0 + arow) * K + aq * 8;
    const uint32_t* Wp = Wbf + (size_t)tid * rowU32;

    float acc[2][8][4];
#pragma unroll
    for (int mt = 0; mt < 2; ++mt)
#pragma unroll
        for (int nt = 0; nt < 8; ++nt)
#pragma unroll
            for (int i = 0; i < 4; ++i) acc[mt][nt][i] = 0.0f;

    const uint32_t a_rel = (uint32_t)(wr * 32 + (lane & 15)) * ROWB
                         + (uint32_t)(lane >> 4) * 16;
    const uint32_t b_rel = ABUF
                         + (uint32_t)(wc * 64 + ((lane >> 4) << 3) + (lane & 7)) * ROWB
                         + (uint32_t)((lane >> 3) & 1) * 16;

    auto ldgA = [&](int c, float* f) {
#pragma unroll
        for (int j = 0; j < 8; ++j) {
            int kg = c * 32 + aq * 8 + j;
            f[j] = (kg < K) ? Ap[c * 32 + j] : 0.0f;
        }
    };
    auto stsA = [&](const float* f, int p) {
        uint32_t hw[4], lw[4];
#pragma unroll
        for (int w = 0; w < 4; ++w) {
            hw[w] = hi_pair(f[2*w], f[2*w+1]);
            lw[w] = lo_pair(f[2*w], f[2*w+1]);
        }
        char* dh = sm + p * BUFSZ + arow * ROWB + aq * 16;
        *(uint4*)dh        = make_uint4(hw[0], hw[1], hw[2], hw[3]);
        *(uint4*)(dh + 64) = make_uint4(lw[0], lw[1], lw[2], lw[3]);
    };
    auto cpB = [&](int c, int p) {
        uint32_t dst = smb + p * BUFSZ + ABUF + tid * ROWB;
        const char* src = (const char*)(Wp + c * 32);
#pragma unroll
        for (int g2 = 0; g2 < 8; ++g2)
            CPASYNC16(dst + g2 * 16, src + g2 * 16);
    };

    {
        float f0[8];
        ldgA(0, f0);
        cpB(0, 0);
        CPASYNC_COMMIT();
        stsA(f0, 0);
        CPASYNC_WAIT0();
    }
    __syncthreads();

    int p = 0;
    for (int c = 0; c < NC; ++c) {
        const bool have = (c + 1 < NC);
        float fn[8];
        if (have) {
            cpB(c + 1, p ^ 1);
            CPASYNC_COMMIT();
            ldgA(c + 1, fn);
        }
        const uint32_t ab = smb + p * BUFSZ + a_rel;
        const uint32_t bb = smb + p * BUFSZ + b_rel;
#pragma unroll
        for (int ks = 0; ks < 2; ++ks) {
            uint32_t ah[2][4], al[2][4];
#pragma unroll
            for (int mt = 0; mt < 2; ++mt) {
                LDMX4(ah[mt][0], ah[mt][1], ah[mt][2], ah[mt][3],
                      ab + mt * (16 * ROWB) + ks * 32);
                LDMX4(al[mt][0], al[mt][1], al[mt][2], al[mt][3],
                      ab + mt * (16 * ROWB) + ks * 32 + 64);
            }
#pragma unroll
            for (int npp = 0; npp < 2; ++npp) {
                const int np0 = npp * 2, np1 = npp * 2 + 1;
                uint32_t bh0[4], bl0[4], bh1[4], bl1[4];
                LDMX4(bh0[0], bh0[1], bh0[2], bh0[3],
                      bb + np0 * (16 * ROWB) + ks * 32);
                LDMX4(bl0[0], bl0[1], bl0[2], bl0[3],
                      bb + np0 * (16 * ROWB) + ks * 32 + 64);
                LDMX4(bh1[0], bh1[1], bh1[2], bh1[3],
                      bb + np1 * (16 * ROWB) + ks * 32);
                LDMX4(bl1[0], bl1[1], bl1[2], bl1[3],
                      bb + np1 * (16 * ROWB) + ks * 32 + 64);
                MMA_BF16(acc[0][2*np0],   ah[0], bh0[0], bh0[1]);
                MMA_BF16(acc[1][2*np0],   ah[1], bh0[0], bh0[1]);
                MMA_BF16(acc[0][2*np0+1], ah[0], bh0[2], bh0[3]);
                MMA_BF16(acc[1][2*np0+1], ah[1], bh0[2], bh0[3]);
                MMA_BF16(acc[0][2*np1],   ah[0], bh1[0], bh1[1]);
                MMA_BF16(acc[1][2*np1],   ah[1], bh1[0], bh1[1]);
                MMA_BF16(acc[0][2*np1+1], ah[0], bh1[2], bh1[3]);
                MMA_BF16(acc[1][2*np1+1], ah[1], bh1[2], bh1[3]);
                MMA_BF16(acc[0][2*np0],   al[0], bh0[0], bh0[1]);
                MMA_BF16(acc[1][2*np0],   al[1], bh0[0], bh0[1]);
                MMA_BF16(acc[0][2*np0+1], al[0], bh0[2], bh0[3]);
                MMA_BF16(acc[1][2*np0+1], al[1], bh0[2], bh0[3]);
                MMA_BF16(acc[0][2*np1],   al[0], bh1[0], bh1[1]);
                MMA_BF16(acc[1][2*np1],   al[1], bh1[0], bh1[1]);
                MMA_BF16(acc[0][2*np1+1], al[0], bh1[2], bh1[3]);
                MMA_BF16(acc[1][2*np1+1], al[1], bh1[2], bh1[3]);
                MMA_BF16(acc[0][2*np0],   ah[0], bl0[0], bl0[1]);
                MMA_BF16(acc[1][2*np0],   ah[1], bl0[0], bl0[1]);
                MMA_BF16(acc[0][2*np0+1], ah[0], bl0[2], bl0[3]);
                MMA_BF16(acc[1][2*np0+1], ah[1], bl0[2], bl0[3]);
                MMA_BF16(acc[0][2*np1],   ah[0], bl1[0], bl1[1]);
                MMA_BF16(acc[1][2*np1],   ah[1], bl1[0], bl1[1]);
                MMA_BF16(acc[0][2*np1+1], ah[0], bl1[2], bl1[3]);
                MMA_BF16(acc[1][2*np1+1], ah[1], bl1[2], bl1[3]);
            }
        }
        if (have) stsA(fn, p ^ 1);
        CPASYNC_WAIT0();
        __syncthreads();
        p ^= 1;
    }

    const int g  = lane >> 2;
    const int t4 = lane & 3;

#pragma unroll
    for (int nt = 0; nt < 8; ++nt) {
        int cc = wc * 64 + nt * 8 + t4 * 2;
        float b0 = bias[cc], b1 = bias[cc + 1];
#pragma unroll
        for (int mt = 0; mt < 2; ++mt) {
            acc[mt][nt][0] += b0; acc[mt][nt][1] += b1;
            acc[mt][nt][2] += b0; acc[mt][nt][3] += b1;
        }
    }
    if (EPI == 3) {
#pragma unroll
        for (int mt = 0; mt < 2; ++mt)
#pragma unroll
            for (int h = 0; h < 2; ++h) {
                int row  = wr * 32 + mt * 16 + g + h * 8;
                int grow = row0 + row;
                if (pe) {
                    const float* pp = pe + (size_t)(grow & (N_ - 1)) * D_;
#pragma unroll
                    for (int nt = 0; nt < 8; ++nt) {
                        int cc = wc * 64 + nt * 8 + t4 * 2;
                        float2 pv = *(const float2*)&pp[cc];
                        acc[mt][nt][h*2]   += pv.x;
                        acc[mt][nt][h*2+1] += pv.y;
                    }
                }
                if (res) {
                    const float* rp = res + (size_t)grow * D_;
#pragma unroll
                    for (int nt = 0; nt < 8; ++nt) {
                        int cc = wc * 64 + nt * 8 + t4 * 2;
                        float2 rv = *(const float2*)&rp[cc];
                        acc[mt][nt][h*2]   += rv.x;
                        acc[mt][nt][h*2+1] += rv.y;
                    }
                }
            }

        float* lnsum = (float*)sm;
        float* lnsq  = (float*)sm + 256;
#pragma unroll
        for (int mt = 0; mt < 2; ++mt)
#pragma unroll
            for (int h = 0; h < 2; ++h) {
                float s = 0.0f, q = 0.0f;
#pragma unroll
                for (int nt = 0; nt < 8; ++nt) {
                    float v0 = acc[mt][nt][h*2], v1 = acc[mt][nt][h*2+1];
                    s += v0 + v1;
                    q = fmaf(v0, v0, q); q = fmaf(v1, v1, q);
                }
#pragma unroll
                for (int off = 1; off <= 2; off <<= 1) {
                    s += __shfl_xor_sync(0xffffffffu, s, off);
                    q += __shfl_xor_sync(0xffffffffu, q, off);
                }
                if (t4 == 0) {
                    int row = wr * 32 + mt * 16 + g + h * 8;
                    lnsum[row * 4 + wc] = s;
                    lnsq [row * 4 + wc] = q;
                }
            }
        __syncthreads();

#pragma unroll
        for (int mt = 0; mt < 2; ++mt)
#pragma unroll
            for (int h = 0; h < 2; ++h) {
                int row  = wr * 32 + mt * 16 + g + h * 8;
                int grow = row0 + row;
                float s = lnsum[row*4] + lnsum[row*4+1] + lnsum[row*4+2] + lnsum[row*4+3];
                float q = lnsq [row*4] + lnsq [row*4+1] + lnsq [row*4+2] + lnsq [row*4+3];
                float mu  = s * (1.0f / 256.0f);
                float var = q * (1.0f / 256.0f) - mu * mu;
                float rs  = rsqrtf(var + EPS_);
                float* op = out + (size_t)grow * D_;
#pragma unroll
                for (int nt = 0; nt < 8; ++nt) {
                    int cc = wc * 64 + nt * 8 + t4 * 2;
                    float v0 = (acc[mt][nt][h*2]   - mu) * rs * gamma[cc]   + beta[cc];
                    float v1 = (acc[mt][nt][h*2+1] - mu) * rs * gamma[cc+1] + beta[cc+1];
                    *(float2*)&op[cc] = make_float2(v0, v1);
                }
            }
    } else {
#pragma unroll
        for (int mt = 0; mt < 2; ++mt)
#pragma unroll
            for (int h = 0; h < 2; ++h) {
                int row  = wr * 32 + mt * 16 + g + h * 8;
                int grow = row0 + row;
                const float* rp = (EPI == 2) ? res + (size_t)grow * D_ : nullptr;
                float* op = out + (size_t)grow * D_;
#pragma unroll
                for (int nt = 0; nt < 8; ++nt) {
                    int cc = wc * 64 + nt * 8 + t4 * 2;
                    float v0 = acc[mt][nt][h*2];
                    float v1 = acc[mt][nt][h*2+1];
                    if (EPI == 1) { v0 = fmaxf(v0, 0.0f); v1 = fmaxf(v1, 0.0f); }
                    if (EPI == 2) {
                        float2 rv = *(const float2*)&rp[cc];
                        v0 += rv.x; v1 += rv.y;
                    }
                    *(float2*)&op[cc] = make_float2(v0, v1);
                }
            }
    }
}

// ---------------------------------------------------------------------------
// hmma_gemm_n128: 64x128 tile, 3 CTAs/SM (24 warps), warp tile 32x32.
// K=256 GEMMs only (no LN). blockIdx.x = rowblk*2 + colhalf.
// gridDim.y selects weight/bias/out set (fused K+V).
// EPI: 0=+bias 1=relu(+bias) 2=+bias+res
// ---------------------------------------------------------------------------
#define ABUF_S   (64 * ROWB)
#define BBUF_S   (128 * ROWB)
#define BUFSZ_S  (ABUF_S + BBUF_S)        // 27648
#define SM_TOT_S (2 * BUFSZ_S)            // 55296

template <int EPI>
__global__ __launch_bounds__(256, 3) void hmma_gemm_n128(
    const float* __restrict__ A, int NC,
    const uint32_t* __restrict__ Wbf, int wstride,
    const float* __restrict__ bias, const float* __restrict__ bias2,
    const float* __restrict__ res,
    float* __restrict__ out, float* __restrict__ out2)
{
    const int K = 256;
    extern __shared__ __align__(16) char sm[];
    const uint32_t smb = smem_u32(sm);
    const int tid  = threadIdx.x;
    const int lane = tid & 31;
    const int warp = tid >> 5;
    const int wr   = warp >> 2;          // 0..1
    const int wc   = warp & 3;           // 0..3 (32-col blocks)
    const int ch   = blockIdx.x & 1;     // column half
    const int row0 = (blockIdx.x >> 1) * 64;

    const float* biasS = blockIdx.y ? bias2 : bias;
    float*       outS  = blockIdx.y ? out2  : out;

    const int arow = tid >> 2;
    const int aq   = tid & 3;
    const float* Ap = A + (size_t)(row0 + arow) * K + aq * 8;
    // B staging: row = tid>>1 (0..127 of this col-half), hf = tid&1
    const int brow = tid >> 1;
    const int bhf  = tid & 1;
    const uint32_t* Wp = Wbf + (size_t)blockIdx.y * wstride
                       + (size_t)(ch * 128 + brow) * 256;

    float acc[2][4][4];
#pragma unroll
    for (int mt = 0; mt < 2; ++mt)
#pragma unroll
        for (int nt = 0; nt < 4; ++nt)
#pragma unroll
            for (int i = 0; i < 4; ++i) acc[mt][nt][i] = 0.0f;

    const uint32_t a_rel = (uint32_t)(wr * 32 + (lane & 15)) * ROWB
                         + (uint32_t)(lane >> 4) * 16;
    const uint32_t b_rel = ABUF_S
                         + (uint32_t)(wc * 32 + ((lane >> 4) << 3) + (lane & 7)) * ROWB
                         + (uint32_t)((lane >> 3) & 1) * 16;

    auto ldgA = [&](int c, float* f) {
#pragma unroll
        for (int j = 0; j < 8; ++j) f[j] = Ap[c * 32 + j];
    };
    auto stsA = [&](const float* f, int p) {
        uint32_t hw[4], lw[4];
#pragma unroll
        for (int w = 0; w < 4; ++w) {
            hw[w] = hi_pair(f[2*w], f[2*w+1]);
            lw[w] = lo_pair(f[2*w], f[2*w+1]);
        }
        char* dh = sm + p * BUFSZ_S + arow * ROWB + aq * 16;
        *(uint4*)dh        = make_uint4(hw[0], hw[1], hw[2], hw[3]);
        *(uint4*)(dh + 64) = make_uint4(lw[0], lw[1], lw[2], lw[3]);
    };
    auto cpB = [&](int c, int p) {
        uint32_t dst = smb + p * BUFSZ_S + ABUF_S + brow * ROWB + bhf * 64;
        const char* src = (const char*)(Wp + c * 32 + bhf * 16);
#pragma unroll
        for (int g2 = 0; g2 < 4; ++g2)
            CPASYNC16(dst + g2 * 16, src + g2 * 16);
    };

    {
        float f0[8];
        ldgA(0, f0);
        cpB(0, 0);
        CPASYNC_COMMIT();
        stsA(f0, 0);
        CPASYNC_WAIT0();
    }
    __syncthreads();

    int p = 0;
    for (int c = 0; c < NC; ++c) {
        const bool have = (c + 1 < NC);
        float fn[8];
        if (have) {
            cpB(c + 1, p ^ 1);
            CPASYNC_COMMIT();
            ldgA(c + 1, fn);
        }
        const uint32_t ab = smb + p * BUFSZ_S + a_rel;
        const uint32_t bb = smb + p * BUFSZ_S + b_rel;
#pragma unroll
        for (int ks = 0; ks < 2; ++ks) {
            uint32_t ah[2][4], al[2][4];
#pragma unroll
            for (int mt = 0; mt < 2; ++mt) {
                LDMX4(ah[mt][0], ah[mt][1], ah[mt][2], ah[mt][3],
                      ab + mt * (16 * ROWB) + ks * 32);
                LDMX4(al[mt][0], al[mt][1], al[mt][2], al[mt][3],
                      ab + mt * (16 * ROWB) + ks * 32 + 64);
            }
            // np covers the warp's 32 B-rows in two 16-row fragments
            uint32_t bh0[4], bl0[4], bh1[4], bl1[4];
            LDMX4(bh0[0], bh0[1], bh0[2], bh0[3], bb + ks * 32);
            LDMX4(bl0[0], bl0[1], bl0[2], bl0[3], bb + ks * 32 + 64);
            LDMX4(bh1[0], bh1[1], bh1[2], bh1[3], bb + 16 * ROWB + ks * 32);
            LDMX4(bl1[0], bl1[1], bl1[2], bl1[3], bb + 16 * ROWB + ks * 32 + 64);
            // term 1 (8 distinct accs)
            MMA_BF16(acc[0][0], ah[0], bh0[0], bh0[1]);
            MMA_BF16(acc[1][0], ah[1], bh0[0], bh0[1]);
            MMA_BF16(acc[0][1], ah[0], bh0[2], bh0[3]);
            MMA_BF16(acc[1][1], ah[1], bh0[2], bh0[3]);
            MMA_BF16(acc[0][2], ah[0], bh1[0], bh1[1]);
            MMA_BF16(acc[1][2], ah[1], bh1[0], bh1[1]);
            MMA_BF16(acc[0][3], ah[0], bh1[2], bh1[3]);
            MMA_BF16(acc[1][3], ah[1], bh1[2], bh1[3]);
            // term 2
            MMA_BF16(acc[0][0], al[0], bh0[0], bh0[1]);
            MMA_BF16(acc[1][0], al[1], bh0[0], bh0[1]);
            MMA_BF16(acc[0][1], al[0], bh0[2], bh0[3]);
            MMA_BF16(acc[1][1], al[1], bh0[2], bh0[3]);
            MMA_BF16(acc[0][2], al[0], bh1[0], bh1[1]);
            MMA_BF16(acc[1][2], al[1], bh1[0], bh1[1]);
            MMA_BF16(acc[0][3], al[0], bh1[2], bh1[3]);
            MMA_BF16(acc[1][3], al[1], bh1[2], bh1[3]);
            // term 3
            MMA_BF16(acc[0][0], ah[0], bl0[0], bl0[1]);
            MMA_BF16(acc[1][0], ah[1], bl0[0], bl0[1]);
            MMA_BF16(acc[0][1], ah[0], bl0[2], bl0[3]);
            MMA_BF16(acc[1][1], ah[1], bl0[2], bl0[3]);
            MMA_BF16(acc[0][2], ah[0], bl1[0], bl1[1]);
            MMA_BF16(acc[1][2], ah[1], bl1[0], bl1[1]);
            MMA_BF16(acc[0][3], ah[0], bl1[2], bl1[3]);
            MMA_BF16(acc[1][3], ah[1], bl1[2], bl1[3]);
        }
        if (have) stsA(fn, p ^ 1);
        CPASYNC_WAIT0();
        __syncthreads();
        p ^= 1;
    }

    // ---------------- epilogue (no LN) ----------------
    const int g  = lane >> 2;
    const int t4 = lane & 3;
#pragma unroll
    for (int mt = 0; mt < 2; ++mt)
#pragma unroll
        for (int h = 0; h < 2; ++h) {
            int row  = wr * 32 + mt * 16 + g + h * 8;
            int grow = row0 + row;
            const float* rp = (EPI == 2) ? res + (size_t)grow * D_ : nullptr;
            float* op = outS + (size_t)grow * D_;
#pragma unroll
            for (int nt = 0; nt < 4; ++nt) {
                int cc = ch * 128 + wc * 32 + nt * 8 + t4 * 2;
                float v0 = acc[mt][nt][h*2]   + biasS[cc];
                float v1 = acc[mt][nt][h*2+1] + biasS[cc + 1];
                if (EPI == 1) { v0 = fmaxf(v0, 0.0f); v1 = fmaxf(v1, 0.0f); }
                if (EPI == 2) {
                    float2 rv = *(const float2*)&rp[cc];
                    v0 += rv.x; v1 += rv.y;
                }
                *(float2*)&op[cc] = make_float2(v0, v1);
            }
        }
}

// ---------------------------------------------------------------------------
// HMMA flash attention v2 (validated R10, unchanged)
// ---------------------------------------------------------------------------
#define AROWB   272
#define AQ_OFF  0
#define AK_OFF  (128 * AROWB)
#define AV_OFF  (AK_OFF + 64 * AROWB)
#define ASM_TOT (AV_OFF + 64 * AROWB)     // 69632
#define QSCALE  0.1803368801111204f       // 0.125 * log2(e)

__global__ __launch_bounds__(256, 2) void attn_kernel(
    const float* __restrict__ q,
    const float* __restrict__ k,
    const float* __restrict__ v,
    float* __restrict__ ctx)
{
    extern __shared__ __align__(16) char asm_[];
    const uint32_t smb = smem_u32(asm_);
    const int tid  = threadIdx.x;
    const int lane = tid & 31;
    const int warp = tid >> 5;
    const int bh   = blockIdx.y;
    const int b    = bh >> 2;
    const int h    = bh & 3;
    const int q0   = blockIdx.x * 128;
    const int g    = lane >> 2;
    const int t4   = lane & 3;

    {
        const int r  = tid >> 1;
        const int hf = tid & 1;
        const float* qp = q + ((size_t)(b * N_ + q0 + r)) * D_ + h * HD_ + hf * 32;
        float f[32];
#pragma unroll
        for (int j = 0; j < 32; ++j) f[j] = qp[j] * QSCALE;
        uint32_t hw[16], lw[16];
#pragma unroll
        for (int w = 0; w < 16; ++w) {
            hw[w] = hi_pair(f[2*w], f[2*w+1]);
            lw[w] = lo_pair(f[2*w], f[2*w+1]);
        }
        char* dh = asm_ + AQ_OFF + r * AROWB + hf * 64;
        char* dl = dh + 128;
#pragma unroll
        for (int g2 = 0; g2 < 4; ++g2) {
            *(uint4*)(dh + g2 * 16) =
                make_uint4(hw[4*g2], hw[4*g2+1], hw[4*g2+2], hw[4*g2+3]);
            *(uint4*)(dl + g2 * 16) =
                make_uint4(lw[4*g2], lw[4*g2+1], lw[4*g2+2], lw[4*g2+3]);
        }
    }

    const uint32_t a_base = smb + AQ_OFF
        + (uint32_t)(warp * 16 + (lane & 15)) * AROWB + (uint32_t)(lane >> 4) * 16;
    const uint32_t kb_base = smb + AK_OFF
        + (uint32_t)(((lane >> 4) << 3) + (lane & 7)) * AROWB
        + (uint32_t)((lane >> 3) & 1) * 16;
    const uint32_t vb_base = smb + AV_OFF
        + (uint32_t)(((lane >> 4) << 3) + (lane & 7)) * AROWB
        + (uint32_t)((lane >> 3) & 1) * 16;

    float acc_o[8][4];
#pragma unroll
    for (int nt = 0; nt < 8; ++nt)
#pragma unroll
        for (int i = 0; i < 4; ++i) acc_o[nt][i] = 0.0f;
    float mrow[2] = {-1e30f, -1e30f};
    float lrow[2] = {0.0f, 0.0f};

    for (int t0 = 0; t0 < N_; t0 += 64) {
        __syncthreads();
        {
            const int r  = tid >> 2;
            const int qd = tid & 3;
            const float* kp = k + ((size_t)(b * N_ + t0 + r)) * D_ + h * HD_ + qd * 16;
            float f[16];
#pragma unroll
            for (int j = 0; j < 16; ++j) f[j] = kp[j];
            uint32_t hw[8], lw[8];
#pragma unroll
            for (int w = 0; w < 8; ++w) {
                hw[w] = hi_pair(f[2*w], f[2*w+1]);
                lw[w] = lo_pair(f[2*w], f[2*w+1]);
            }
            char* dh = asm_ + AK_OFF + r * AROWB + qd * 32;
            char* dl = dh + 128;
#pragma unroll
            for (int g2 = 0; g2 < 2; ++g2) {
                *(uint4*)(dh + g2 * 16) =
                    make_uint4(hw[4*g2], hw[4*g2+1], hw[4*g2+2], hw[4*g2+3]);
                *(uint4*)(dl + g2 * 16) =
                    make_uint4(lw[4*g2], lw[4*g2+1], lw[4*g2+2], lw[4*g2+3]);
            }
        }
        {
            const float* v0p = v + ((size_t)(b * N_ + t0 + 2*lane))     * D_ + h * HD_ + warp * 8;
            const float* v1p = v + ((size_t)(b * N_ + t0 + 2*lane + 1)) * D_ + h * HD_ + warp * 8;
            float f0[8], f1[8];
            *(float4*)&f0[0] = *(const float4*)&v0p[0];
            *(float4*)&f0[4] = *(const float4*)&v0p[4];
            *(float4*)&f1[0] = *(const float4*)&v1p[0];
            *(float4*)&f1[4] = *(const float4*)&v1p[4];
#pragma unroll
            for (int j = 0; j < 8; ++j) {
                int hd = warp * 8 + j;
                *(uint32_t*)(asm_ + AV_OFF + hd * AROWB + lane * 4)       = hi_pair(f0[j], f1[j]);
                *(uint32_t*)(asm_ + AV_OFF + hd * AROWB + 128 + lane * 4) = lo_pair(f0[j], f1[j]);
            }
        }
        __syncthreads();

        float s[8][4];
#pragma unroll
        for (int nt = 0; nt < 8; ++nt)
#pragma unroll
            for (int i = 0; i < 4; ++i) s[nt][i] = 0.0f;
#pragma unroll
        for (int ks = 0; ks < 4; ++ks) {
            uint32_t ah[4], al[4];
            LDMX4(ah[0], ah[1], ah[2], ah[3], a_base + ks * 32);
            LDMX4(al[0], al[1], al[2], al[3], a_base + ks * 32 + 128);
#pragma unroll
            for (int npp = 0; npp < 2; ++npp) {
                const int np0 = npp * 2, np1 = npp * 2 + 1;
                uint32_t bh0[4], bl0[4], bh1[4], bl1[4];
                LDMX4(bh0[0], bh0[1], bh0[2], bh0[3],
                      kb_base + np0 * (16 * AROWB) + ks * 32);
                LDMX4(bl0[0], bl0[1], bl0[2], bl0[3],
                      kb_base + np0 * (16 * AROWB) + ks * 32 + 128);
                LDMX4(bh1[0], bh1[1], bh1[2], bh1[3],
                      kb_base + np1 * (16 * AROWB) + ks * 32);
                LDMX4(bl1[0], bl1[1], bl1[2], bl1[3],
                      kb_base + np1 * (16 * AROWB) + ks * 32 + 128);
                MMA_BF16(s[2*np0],     ah, bh0[0], bh0[1]);
                MMA_BF16(s[2*np0 + 1], ah, bh0[2], bh0[3]);
                MMA_BF16(s[2*np1],     ah, bh1[0], bh1[1]);
                MMA_BF16(s[2*np1 + 1], ah, bh1[2], bh1[3]);
                MMA_BF16(s[2*np0],     al, bh0[0], bh0[1]);
                MMA_BF16(s[2*np0 + 1], al, bh0[2], bh0[3]);
                MMA_BF16(s[2*np1],     al, bh1[0], bh1[1]);
                MMA_BF16(s[2*np1 + 1], al, bh1[2], bh1[3]);
                MMA_BF16(s[2*np0],     ah, bl0[0], bl0[1]);
                MMA_BF16(s[2*np0 + 1], ah, bl0[2], bl0[3]);
                MMA_BF16(s[2*np1],     ah, bl1[0], bl1[1]);
                MMA_BF16(s[2*np1 + 1], ah, bl1[2], bl1[3]);
            }
        }

#pragma unroll
        for (int r2 = 0; r2 < 2; ++r2) {
            float mx = -1e30f;
#pragma unroll
            for (int nt = 0; nt < 8; ++nt)
                mx = fmaxf(mx, fmaxf(s[nt][r2*2], s[nt][r2*2+1]));
#pragma unroll
            for (int off = 1; off <= 2; off <<= 1)
                mx = fmaxf(mx, __shfl_xor_sync(0xffffffffu, mx, off));
            float mnew = fmaxf(mrow[r2], mx);
            float corr = fexp2(mrow[r2] - mnew);
            float ps = 0.0f;
#pragma unroll
            for (int nt = 0; nt < 8; ++nt) {
                float p0 = fexp2(s[nt][r2*2]   - mnew);
                float p1 = fexp2(s[nt][r2*2+1] - mnew);
                s[nt][r2*2] = p0; s[nt][r2*2+1] = p1;
                ps += p0 + p1;
            }
#pragma unroll
            for (int off = 1; off <= 2; off <<= 1)
                ps += __shfl_xor_sync(0xffffffffu, ps, off);
            lrow[r2] = lrow[r2] * corr + ps;
            mrow[r2] = mnew;
#pragma unroll
            for (int nt = 0; nt < 8; ++nt) {
                acc_o[nt][r2*2]   *= corr;
                acc_o[nt][r2*2+1] *= corr;
            }
        }

#pragma unroll
        for (int kt = 0; kt < 4; ++kt) {
            uint32_t pah[4], pal[4];
            pah[0] = hi_pair(s[2*kt][0],   s[2*kt][1]);
            pah[1] = hi_pair(s[2*kt][2],   s[2*kt][3]);
            pah[2] = hi_pair(s[2*kt+1][0], s[2*kt+1][1]);
            pah[3] = hi_pair(s[2*kt+1][2], s[2*kt+1][3]);
            pal[0] = lo_pair(s[2*kt][0],   s[2*kt][1]);
            pal[1] = lo_pair(s[2*kt][2],   s[2*kt][3]);
            pal[2] = lo_pair(s[2*kt+1][0], s[2*kt+1][1]);
            pal[3] = lo_pair(s[2*kt+1][2], s[2*kt+1][3]);
#pragma unroll
            for (int npp = 0; npp < 2; ++npp) {
                const int np0 = npp * 2, np1 = npp * 2 + 1;
                uint32_t vh0[4], vl0[4], vh1[4], vl1[4];
                LDMX4(vh0[0], vh0[1], vh0[2], vh0[3],
                      vb_base + np0 * (16 * AROWB) + kt * 32);
                LDMX4(vl0[0], vl0[1], vl0[2], vl0[3],
                      vb_base + np0 * (16 * AROWB) + kt * 32 + 128);
                LDMX4(vh1[0], vh1[1], vh1[2], vh1[3],
                      vb_base + np1 * (16 * AROWB) + kt * 32);
                LDMX4(vl1[0], vl1[1], vl1[2], vl1[3],
                      vb_base + np1 * (16 * AROWB) + kt * 32 + 128);
                MMA_BF16(acc_o[2*np0],     pah, vh0[0], vh0[1]);
                MMA_BF16(acc_o[2*np0 + 1], pah, vh0[2], vh0[3]);
                MMA_BF16(acc_o[2*np1],     pah, vh1[0], vh1[1]);
                MMA_BF16(acc_o[2*np1 + 1], pah, vh1[2], vh1[3]);
                MMA_BF16(acc_o[2*np0],     pal, vh0[0], vh0[1]);
                MMA_BF16(acc_o[2*np0 + 1], pal, vh0[2], vh0[3]);
                MMA_BF16(acc_o[2*np1],     pal, vh1[0], vh1[1]);
                MMA_BF16(acc_o[2*np1 + 1], pal, vh1[2], vh1[3]);
                MMA_BF16(acc_o[2*np0],     pah, vl0[0], vl0[1]);
                MMA_BF16(acc_o[2*np0 + 1], pah, vl0[2], vl0[3]);
                MMA_BF16(acc_o[2*np1],     pah, vl1[0], vl1[1]);
                MMA_BF16(acc_o[2*np1 + 1], pah, vl1[2], vl1[3]);
            }
        }
    }

    float inv0 = 1.0f / lrow[0];
    float inv1 = 1.0f / lrow[1];
#pragma unroll
    for (int r2 = 0; r2 < 2; ++r2) {
        int grow = b * N_ + q0 + warp * 16 + g + r2 * 8;
        float inv = r2 ? inv1 : inv0;
        float* cp = ctx + (size_t)grow * D_ + h * HD_;
#pragma unroll
        for (int nt = 0; nt < 8; ++nt) {
            int cc = nt * 8 + t4 * 2;
            *(float2*)&cp[cc] = make_float2(acc_o[nt][r2*2] * inv,
                                            acc_o[nt][r2*2+1] * inv);
        }
    }
}

// ---------------------------------------------------------------------------
// mean-pool + classifier
// ---------------------------------------------------------------------------
__global__ __launch_bounds__(256) void pool_cls_kernel(
    const float* __restrict__ xm,
    const float* __restrict__ Wc,
    const float* __restrict__ bc,
    float* __restrict__ out)
{
    __shared__ float pooled[D_];
    const int b = blockIdx.x;
    const int t = threadIdx.x;
    float s = 0.0f;
    const float* p = xm + (size_t)b * N_ * D_ + t;
#pragma unroll 8
    for (int n = 0; n < N_; ++n) s += p[(size_t)n * D_];
    pooled[t] = s * (1.0f / (float)N_);
    __syncthreads();
    if (t < 2) {
        float a = bc[t];
        for (int c = 0; c < D_; ++c) a = fmaf(pooled[c], Wc[t * D_ + c], a);
        out[b * 2 + t] = a;
    }
}

// ---------------------------------------------------------------------------
// Launch
// ---------------------------------------------------------------------------
static float* sym(const void* s) {
    void* p = nullptr;
    cudaGetSymbolAddress(&p, s);
    return (float*)p;
}

extern "C" void kernel_launch(void* const* d_in, const int* in_sizes, int n_in,
                              void* d_out, int out_size)
{
    const float* x   = (const float*)d_in[0];
    const float* y   = (const float*)d_in[1];
    const float* Wr  = (const float*)d_in[3];
    const float* br  = (const float*)d_in[4];
    const float* Wf  = (const float*)d_in[5];
    const float* bf  = (const float*)d_in[6];
    const float* g_x = (const float*)d_in[7];
    const float* b_x = (const float*)d_in[8];
    const float* g_y = (const float*)d_in[9];
    const float* b_y = (const float*)d_in[10];
    const float* Wq  = (const float*)d_in[11];
    const float* bq  = (const float*)d_in[12];
    const float* Wk  = (const float*)d_in[13];
    const float* bk  = (const float*)d_in[14];
    const float* Wv  = (const float*)d_in[15];
    const float* bv  = (const float*)d_in[16];
    const float* Wo  = (const float*)d_in[17];
    const float* bo  = (const float*)d_in[18];
    const float* g_m = (const float*)d_in[19];
    const float* b_m = (const float*)d_in[20];
    const float* W1  = (const float*)d_in[21];
    const float* b1  = (const float*)d_in[22];
    const float* W2  = (const float*)d_in[23];
    const float* b2  = (const float*)d_in[24];
    const float* Wc  = (const float*)d_in[25];
    const float* bc  = (const float*)d_in[26];
    float* out = (float*)d_out;

    float* xp   = sym(g_xp);
    float* yp   = sym(g_yp);
    float* qb   = sym(g_q);
    float* kb   = sym(g_k);
    float* vb   = sym(g_v);
    float* ctx  = sym(g_ctx);
    float* xres = sym(g_xres);
    float* hid  = sym(g_hid);
    float* xmlp = sym(g_xmlp);
    float* pe   = sym(g_pe);
    uint32_t* wb;
    {
        void* p = nullptr;
        cudaGetSymbolAddress(&p, g_wbuf);
        wb = (uint32_t*)p;
    }

    static bool attr_set = false;
    if (!attr_set) {
        cudaFuncSetAttribute(attn_kernel,
                             cudaFuncAttributeMaxDynamicSharedMemorySize, ASM_TOT);
        cudaFuncSetAttribute(hmma_gemm<3>,
                             cudaFuncAttributeMaxDynamicSharedMemorySize, SM_TOT);
        cudaFuncSetAttribute(hmma_gemm_n128<0>,
                             cudaFuncAttributeMaxDynamicSharedMemorySize, SM_TOT_S);
        cudaFuncSetAttribute(hmma_gemm_n128<1>,
                             cudaFuncAttributeMaxDynamicSharedMemorySize, SM_TOT_S);
        cudaFuncSetAttribute(hmma_gemm_n128<2>,
                             cudaFuncAttributeMaxDynamicSharedMemorySize, SM_TOT_S);
        attr_set = true;
    }

    dim3 gg(M_ / 64);      // 512 CTAs (LN gemms)
    dim3 gs(M_ / 64 * 2);  // 1024 CTAs (n128 gemms)
    dim3 bb(256);

    prep_kernel<<<(WB_TOT + N_ * D_ + 255) / 256, 256>>>(Wr, Wf, Wq, Wk, Wv, Wo, W1, W2);

    // xp = LN(x @ Wr^T + br + pe)
    hmma_gemm<3><<<gg, bb, SM_TOT>>>(x, 769, 25, wb + WR_OFF, 800,
                                     br, g_x, b_x, nullptr, pe, xp);
    // yp = LN(y @ Wf^T + bf + pe)
    hmma_gemm<3><<<gg, bb, SM_TOT>>>(y, 674, 22, wb + WF_OFF, 704,
                                     bf, g_y, b_y, nullptr, pe, yp);
    // q
    hmma_gemm_n128<0><<<gs, bb, SM_TOT_S>>>(xp, 8, wb + WQ_OFF, 0,
                                            bq, nullptr, nullptr, qb, nullptr);
    // k + v fused (gridDim.y = 2)
    hmma_gemm_n128<0><<<dim3(M_ / 64 * 2, 2), bb, SM_TOT_S>>>(yp, 8, wb + WK_OFF,
                                            256 * 256, bk, bv, nullptr, kb, vb);
    // attention
    dim3 ag(N_ / 128, B_ * H_);
    attn_kernel<<<ag, bb, ASM_TOT>>>(qb, kb, vb, ctx);
    // x_res = LN(xp + ctx @ Wo^T + bo)
    hmma_gemm<3><<<gg, bb, SM_TOT>>>(ctx, 256, 8, wb + WO_OFF, 256,
                                     bo, g_m, b_m, xp, nullptr, xres);
    // hid = relu(x_res @ W1^T + b1)
    hmma_gemm_n128<1><<<gs, bb, SM_TOT_S>>>(xres, 8, wb + W1_OFF, 0,
                                            b1, nullptr, nullptr, hid, nullptr);
    // xmlp = x_res + hid @ W2^T + b2
    hmma_gemm_n128<2><<<gs, bb, SM_TOT_S>>>(hid, 8, wb + W2_OFF, 0,
                                            b2, nullptr, xres, xmlp, nullptr);
    // pool + classifier
    pool_cls_kernel<<<B_, bb>>>(xmlp, Wc, bc, out);
}

// round 12
// speedup vs baseline: 5.1601x; 1.0612x over previous
#include <cuda_runtime.h>
#include <cuda_bf16.h>
#include <math.h>
#include <stdint.h>

// ---------------------------------------------------------------------------
// Model dims
// ---------------------------------------------------------------------------
#define B_      64
#define N_      512
#define D_      256
#define H_      4
#define HD_     64
#define M_      (B_ * N_)         // 32768 rows
#define EPS_    1e-5f

// ---------------------------------------------------------------------------
// Scratch
// ---------------------------------------------------------------------------
__device__ float g_xp  [M_ * D_];
__device__ float g_yp  [M_ * D_];
__device__ float g_q   [M_ * D_];
__device__ float g_k   [M_ * D_];
__device__ float g_v   [M_ * D_];
__device__ float g_ctx [M_ * D_];
__device__ float g_xres[M_ * D_];
__device__ float g_hid [M_ * D_];
__device__ float g_xmlp[M_ * D_];
__device__ float g_pe  [N_ * D_];

// bf16 hi/lo weight scratch
#define WR_OFF  0
#define WF_OFF  (WR_OFF + 256 * 800)
#define WQ_OFF  (WF_OFF + 256 * 704)
#define WK_OFF  (WQ_OFF + 256 * 256)
#define WV_OFF  (WK_OFF + 256 * 256)
#define WO_OFF  (WV_OFF + 256 * 256)
#define W1_OFF  (WO_OFF + 256 * 256)
#define W2_OFF  (W1_OFF + 256 * 256)
#define WB_TOT  (W2_OFF + 256 * 256)
__device__ uint32_t g_wbuf[WB_TOT];

// ---------------------------------------------------------------------------
// hi = truncation to bf16 (exact); lo = rn-bf16(x - hi)
// ---------------------------------------------------------------------------
__device__ __forceinline__ uint32_t hi_pair(float x0, float x1) {
    uint32_t a = __float_as_uint(x0), b = __float_as_uint(x1);
    return (b & 0xffff0000u) | (a >> 16);
}
__device__ __forceinline__ uint32_t lo_pair(float x0, float x1) {
    float l0 = x0 - __uint_as_float(__float_as_uint(x0) & 0xffff0000u);
    float l1 = x1 - __uint_as_float(__float_as_uint(x1) & 0xffff0000u);
    uint32_t a = (uint32_t)__bfloat16_as_ushort(__float2bfloat16(l0));
    uint32_t b = (uint32_t)__bfloat16_as_ushort(__float2bfloat16(l1));
    return (b << 16) | a;
}

__device__ __forceinline__ uint32_t smem_u32(const void* p) {
    uint32_t a;
    asm("{ .reg .u64 t; cvta.to.shared.u64 t, %1; cvt.u32.u64 %0, t; }"
        : "=r"(a) : "l"(p));
    return a;
}

#define LDMX4(r0, r1, r2, r3, addr) \
    asm volatile("ldmatrix.sync.aligned.m8n8.x4.shared.b16 {%0,%1,%2,%3}, [%4];" \
                 : "=r"(r0), "=r"(r1), "=r"(r2), "=r"(r3) : "r"(addr))

#define MMA_BF16(c, a, b0, b1) \
    asm volatile("mma.sync.aligned.m16n8k16.row.col.f32.bf16.bf16.f32 " \
                 "{%0,%1,%2,%3}, {%4,%5,%6,%7}, {%8,%9}, {%0,%1,%2,%3};" \
                 : "+f"((c)[0]), "+f"((c)[1]), "+f"((c)[2]), "+f"((c)[3]) \
                 : "r"((a)[0]), "r"((a)[1]), "r"((a)[2]), "r"((a)[3]), \
                   "r"(b0), "r"(b1))

#define CPASYNC16(dst, src) \
    asm volatile("cp.async.cg.shared.global [%0], [%1], 16;" \
                 :: "r"(dst), "l"(src))
#define CPASYNC_COMMIT()  asm volatile("cp.async.commit_group;" ::: "memory")
#define CPASYNC_WAIT0()   asm volatile("cp.async.wait_group 0;" ::: "memory")

// fast 2^x for x <= 0; rel err ~1.5e-5; no MUFU
__device__ __forceinline__ float fexp2(float x) {
    x = fmaxf(x, -80.0f);
    float n = floorf(x);
    float f = x - n;
    float p = 1.5404e-4f;
    p = fmaf(p, f, 1.333356e-3f);
    p = fmaf(p, f, 9.618130e-3f);
    p = fmaf(p, f, 5.550411e-2f);
    p = fmaf(p, f, 2.402265e-1f);
    p = fmaf(p, f, 6.931472e-1f);
    p = fmaf(p, f, 1.0f);
    return __int_as_float(__float_as_int(p) + ((int)n << 23));
}

// ---------------------------------------------------------------------------
// Prologue: weight hi/lo conversion + PE table, one launch
// ---------------------------------------------------------------------------
__global__ void prep_kernel(const float* __restrict__ Wr, const float* __restrict__ Wf,
                            const float* __restrict__ Wq, const float* __restrict__ Wk,
                            const float* __restrict__ Wv, const float* __restrict__ Wo,
                            const float* __restrict__ W1, const float* __restrict__ W2) {
    int idx = blockIdx.x * blockDim.x + threadIdx.x;
    if (idx < WB_TOT) {
        const float* W; int K, rowU32, base;
        if      (idx < WF_OFF) { W = Wr; K = 769; rowU32 = 800; base = WR_OFF; }
        else if (idx < WQ_OFF) { W = Wf; K = 674; rowU32 = 704; base = WF_OFF; }
        else if (idx < WK_OFF) { W = Wq; K = 256; rowU32 = 256; base = WQ_OFF; }
        else if (idx < WV_OFF) { W = Wk; K = 256; rowU32 = 256; base = WK_OFF; }
        else if (idx < WO_OFF) { W = Wv; K = 256; rowU32 = 256; base = WV_OFF; }
        else if (idx < W1_OFF) { W = Wo; K = 256; rowU32 = 256; base = WO_OFF; }
        else if (idx < W2_OFF) { W = W1; K = 256; rowU32 = 256; base = W1_OFF; }
        else                   { W = W2; K = 256; rowU32 = 256; base = W2_OFF; }
        int j   = idx - base;
        int row = j / rowU32;
        int jj  = j - row * rowU32;
        int c   = jj >> 5;
        int t   = jj & 31;
        int e0  = c * 32 + ((t & 15) << 1);
        float v0 = (e0     < K) ? W[(size_t)row * K + e0]     : 0.0f;
        float v1 = (e0 + 1 < K) ? W[(size_t)row * K + e0 + 1] : 0.0f;
        g_wbuf[idx] = (t < 16) ? hi_pair(v0, v1) : lo_pair(v0, v1);
    } else if (idx < WB_TOT + N_ * D_) {
        int j   = idx - WB_TOT;
        int pos = j >> 8;
        int c   = j & 255;
        int i2  = c & ~1;
        float div = expf(-logf(10000.0f) * (float)i2 / (float)D_);
        float ang = (float)pos * div;
        g_pe[j] = (c & 1) ? cosf(ang) : sinf(ang);
    }
}

// ---------------------------------------------------------------------------
// In-place row LayerNorm: warp per 256-col row, 8 rows per CTA
// ---------------------------------------------------------------------------
__global__ __launch_bounds__(256) void ln_kernel(
    float* __restrict__ io,
    const float* __restrict__ gamma,
    const float* __restrict__ beta)
{
    const int row  = blockIdx.x * 8 + (threadIdx.x >> 5);
    const int lane = threadIdx.x & 31;
    float* p = io + (size_t)row * D_ + lane * 8;
    float4 a = *(float4*)p;
    float4 b = *(float4*)(p + 4);
    float s = a.x + a.y + a.z + a.w + b.x + b.y + b.z + b.w;
    float q = a.x*a.x + a.y*a.y + a.z*a.z + a.w*a.w
            + b.x*b.x + b.y*b.y + b.z*b.z + b.w*b.w;
#pragma unroll
    for (int off = 16; off > 0; off >>= 1) {
        s += __shfl_xor_sync(0xffffffffu, s, off);
        q += __shfl_xor_sync(0xffffffffu, q, off);
    }
    float mu  = s * (1.0f / 256.0f);
    float var = q * (1.0f / 256.0f) - mu * mu;
    float rs  = rsqrtf(var + EPS_);
    const float* gp = gamma + lane * 8;
    const float* bp = beta  + lane * 8;
    float4 g0 = *(const float4*)gp,  g1 = *(const float4*)(gp + 4);
    float4 b0 = *(const float4*)bp,  b1 = *(const float4*)(bp + 4);
    a.x = (a.x - mu) * rs * g0.x + b0.x;  a.y = (a.y - mu) * rs * g0.y + b0.y;
    a.z = (a.z - mu) * rs * g0.z + b0.z;  a.w = (a.w - mu) * rs * g0.w + b0.w;
    b.x = (b.x - mu) * rs * g1.x + b1.x;  b.y = (b.y - mu) * rs * g1.y + b1.y;
    b.z = (b.z - mu) * rs * g1.z + b1.z;  b.w = (b.w - mu) * rs * g1.w + b1.w;
    *(float4*)p       = a;
    *(float4*)(p + 4) = b;
}

// ---------------------------------------------------------------------------
// hmma_gemm_n128: 64x128 tile, 3 CTAs/SM, warp tile 32x32, generalized K.
// blockIdx.x = rowblk*2 + colhalf ; gridDim.y selects weight/bias/out set.
// EPI: 0=+bias 1=relu(+bias) 2=+bias+res 4=+bias+pe
// ---------------------------------------------------------------------------
#define ROWB     144
#define ABUF_S   (64 * ROWB)
#define BBUF_S   (128 * ROWB)
#define BUFSZ_S  (ABUF_S + BBUF_S)        // 27648
#define SM_TOT_S (2 * BUFSZ_S)            // 55296

template <int EPI>
__global__ __launch_bounds__(256, 3) void hmma_gemm_n128(
    const float* __restrict__ A, int K, int NC,
    const uint32_t* __restrict__ Wbf, int rowU32, int wstride,
    const float* __restrict__ bias, const float* __restrict__ bias2,
    const float* __restrict__ res,
    const float* __restrict__ pe,
    float* __restrict__ out, float* __restrict__ out2)
{
    extern __shared__ __align__(16) char sm[];
    const uint32_t smb = smem_u32(sm);
    const int tid  = threadIdx.x;
    const int lane = tid & 31;
    const int warp = tid >> 5;
    const int wr   = warp >> 2;          // 0..1
    const int wc   = warp & 3;           // 0..3 (32-col blocks)
    const int ch   = blockIdx.x & 1;     // column half
    const int row0 = (blockIdx.x >> 1) * 64;

    const float* biasS = blockIdx.y ? bias2 : bias;
    float*       outS  = blockIdx.y ? out2  : out;

    const int arow = tid >> 2;
    const int aq   = tid & 3;
    const float* Ap = A + (size_t)(row0 + arow) * K + aq * 8;
    const int brow = tid >> 1;
    const int bhf  = tid & 1;
    const uint32_t* Wp = Wbf + (size_t)blockIdx.y * wstride
                       + (size_t)(ch * 128 + brow) * rowU32;

    float acc[2][4][4];
#pragma unroll
    for (int mt = 0; mt < 2; ++mt)
#pragma unroll
        for (int nt = 0; nt < 4; ++nt)
#pragma unroll
            for (int i = 0; i < 4; ++i) acc[mt][nt][i] = 0.0f;

    const uint32_t a_rel = (uint32_t)(wr * 32 + (lane & 15)) * ROWB
                         + (uint32_t)(lane >> 4) * 16;
    const uint32_t b_rel = ABUF_S
                         + (uint32_t)(wc * 32 + ((lane >> 4) << 3) + (lane & 7)) * ROWB
                         + (uint32_t)((lane >> 3) & 1) * 16;

    auto ldgA = [&](int c, float* f) {
#pragma unroll
        for (int j = 0; j < 8; ++j) {
            int kg = c * 32 + aq * 8 + j;
            f[j] = (kg < K) ? Ap[c * 32 + j] : 0.0f;
        }
    };
    auto stsA = [&](const float* f, int p) {
        uint32_t hw[4], lw[4];
#pragma unroll
        for (int w = 0; w < 4; ++w) {
            hw[w] = hi_pair(f[2*w], f[2*w+1]);
            lw[w] = lo_pair(f[2*w], f[2*w+1]);
        }
        char* dh = sm + p * BUFSZ_S + arow * ROWB + aq * 16;
        *(uint4*)dh        = make_uint4(hw[0], hw[1], hw[2], hw[3]);
        *(uint4*)(dh + 64) = make_uint4(lw[0], lw[1], lw[2], lw[3]);
    };
    auto cpB = [&](int c, int p) {
        uint32_t dst = smb + p * BUFSZ_S + ABUF_S + brow * ROWB + bhf * 64;
        const char* src = (const char*)(Wp + c * 32 + bhf * 16);
#pragma unroll
        for (int g2 = 0; g2 < 4; ++g2)
            CPASYNC16(dst + g2 * 16, src + g2 * 16);
    };

    {
        float f0[8];
        ldgA(0, f0);
        cpB(0, 0);
        CPASYNC_COMMIT();
        stsA(f0, 0);
        CPASYNC_WAIT0();
    }
    __syncthreads();

    int p = 0;
    for (int c = 0; c < NC; ++c) {
        const bool have = (c + 1 < NC);
        float fn[8];
        if (have) {
            cpB(c + 1, p ^ 1);
            CPASYNC_COMMIT();
            ldgA(c + 1, fn);
        }
        const uint32_t ab = smb + p * BUFSZ_S + a_rel;
        const uint32_t bb = smb + p * BUFSZ_S + b_rel;
#pragma unroll
        for (int ks = 0; ks < 2; ++ks) {
            uint32_t ah[2][4], al[2][4];
#pragma unroll
            for (int mt = 0; mt < 2; ++mt) {
                LDMX4(ah[mt][0], ah[mt][1], ah[mt][2], ah[mt][3],
                      ab + mt * (16 * ROWB) + ks * 32);
                LDMX4(al[mt][0], al[mt][1], al[mt][2], al[mt][3],
                      ab + mt * (16 * ROWB) + ks * 32 + 64);
            }
            uint32_t bh0[4], bl0[4], bh1[4], bl1[4];
            LDMX4(bh0[0], bh0[1], bh0[2], bh0[3], bb + ks * 32);
            LDMX4(bl0[0], bl0[1], bl0[2], bl0[3], bb + ks * 32 + 64);
            LDMX4(bh1[0], bh1[1], bh1[2], bh1[3], bb + 16 * ROWB + ks * 32);
            LDMX4(bl1[0], bl1[1], bl1[2], bl1[3], bb + 16 * ROWB + ks * 32 + 64);
            // term 1 (8 distinct accs)
            MMA_BF16(acc[0][0], ah[0], bh0[0], bh0[1]);
            MMA_BF16(acc[1][0], ah[1], bh0[0], bh0[1]);
            MMA_BF16(acc[0][1], ah[0], bh0[2], bh0[3]);
            MMA_BF16(acc[1][1], ah[1], bh0[2], bh0[3]);
            MMA_BF16(acc[0][2], ah[0], bh1[0], bh1[1]);
            MMA_BF16(acc[1][2], ah[1], bh1[0], bh1[1]);
            MMA_BF16(acc[0][3], ah[0], bh1[2], bh1[3]);
            MMA_BF16(acc[1][3], ah[1], bh1[2], bh1[3]);
            // term 2
            MMA_BF16(acc[0][0], al[0], bh0[0], bh0[1]);
            MMA_BF16(acc[1][0], al[1], bh0[0], bh0[1]);
            MMA_BF16(acc[0][1], al[0], bh0[2], bh0[3]);
            MMA_BF16(acc[1][1], al[1], bh0[2], bh0[3]);
            MMA_BF16(acc[0][2], al[0], bh1[0], bh1[1]);
            MMA_BF16(acc[1][2], al[1], bh1[0], bh1[1]);
            MMA_BF16(acc[0][3], al[0], bh1[2], bh1[3]);
            MMA_BF16(acc[1][3], al[1], bh1[2], bh1[3]);
            // term 3
            MMA_BF16(acc[0][0], ah[0], bl0[0], bl0[1]);
            MMA_BF16(acc[1][0], ah[1], bl0[0], bl0[1]);
            MMA_BF16(acc[0][1], ah[0], bl0[2], bl0[3]);
            MMA_BF16(acc[1][1], ah[1], bl0[2], bl0[3]);
            MMA_BF16(acc[0][2], ah[0], bl1[0], bl1[1]);
            MMA_BF16(acc[1][2], ah[1], bl1[0], bl1[1]);
            MMA_BF16(acc[0][3], ah[0], bl1[2], bl1[3]);
            MMA_BF16(acc[1][3], ah[1], bl1[2], bl1[3]);
        }
        if (have) stsA(fn, p ^ 1);
        CPASYNC_WAIT0();
        __syncthreads();
        p ^= 1;
    }

    // ---------------- epilogue ----------------
    const int g  = lane >> 2;
    const int t4 = lane & 3;
#pragma unroll
    for (int mt = 0; mt < 2; ++mt)
#pragma unroll
        for (int h = 0; h < 2; ++h) {
            int row  = wr * 32 + mt * 16 + g + h * 8;
            int grow = row0 + row;
            const float* rp = (EPI == 2) ? res + (size_t)grow * D_ : nullptr;
            const float* pp = (EPI == 4) ? pe + (size_t)(grow & (N_ - 1)) * D_ : nullptr;
            float* op = outS + (size_t)grow * D_;
#pragma unroll
            for (int nt = 0; nt < 4; ++nt) {
                int cc = ch * 128 + wc * 32 + nt * 8 + t4 * 2;
                float v0 = acc[mt][nt][h*2]   + biasS[cc];
                float v1 = acc[mt][nt][h*2+1] + biasS[cc + 1];
                if (EPI == 1) { v0 = fmaxf(v0, 0.0f); v1 = fmaxf(v1, 0.0f); }
                if (EPI == 2) {
                    float2 rv = *(const float2*)&rp[cc];
                    v0 += rv.x; v1 += rv.y;
                }
                if (EPI == 4) {
                    float2 pv = *(const float2*)&pp[cc];
                    v0 += pv.x; v1 += pv.y;
                }
                *(float2*)&op[cc] = make_float2(v0, v1);
            }
        }
}

// ---------------------------------------------------------------------------
// HMMA flash attention v2 (validated R10, unchanged)
// ---------------------------------------------------------------------------
#define AROWB   272
#define AQ_OFF  0
#define AK_OFF  (128 * AROWB)
#define AV_OFF  (AK_OFF + 64 * AROWB)
#define ASM_TOT (AV_OFF + 64 * AROWB)     // 69632
#define QSCALE  0.1803368801111204f       // 0.125 * log2(e)

__global__ __launch_bounds__(256, 2) void attn_kernel(
    const float* __restrict__ q,
    const float* __restrict__ k,
    const float* __restrict__ v,
    float* __restrict__ ctx)
{
    extern __shared__ __align__(16) char asm_[];
    const uint32_t smb = smem_u32(asm_);
    const int tid  = threadIdx.x;
    const int lane = tid & 31;
    const int warp = tid >> 5;
    const int bh   = blockIdx.y;
    const int b    = bh >> 2;
    const int h    = bh & 3;
    const int q0   = blockIdx.x * 128;
    const int g    = lane >> 2;
    const int t4   = lane & 3;

    {
        const int r  = tid >> 1;
        const int hf = tid & 1;
        const float* qp = q + ((size_t)(b * N_ + q0 + r)) * D_ + h * HD_ + hf * 32;
        float f[32];
#pragma unroll
        for (int j = 0; j < 32; ++j) f[j] = qp[j] * QSCALE;
        uint32_t hw[16], lw[16];
#pragma unroll
        for (int w = 0; w < 16; ++w) {
            hw[w] = hi_pair(f[2*w], f[2*w+1]);
            lw[w] = lo_pair(f[2*w], f[2*w+1]);
        }
        char* dh = asm_ + AQ_OFF + r * AROWB + hf * 64;
        char* dl = dh + 128;
#pragma unroll
        for (int g2 = 0; g2 < 4; ++g2) {
            *(uint4*)(dh + g2 * 16) =
                make_uint4(hw[4*g2], hw[4*g2+1], hw[4*g2+2], hw[4*g2+3]);
            *(uint4*)(dl + g2 * 16) =
                make_uint4(lw[4*g2], lw[4*g2+1], lw[4*g2+2], lw[4*g2+3]);
        }
    }

    const uint32_t a_base = smb + AQ_OFF
        + (uint32_t)(warp * 16 + (lane & 15)) * AROWB + (uint32_t)(lane >> 4) * 16;
    const uint32_t kb_base = smb + AK_OFF
        + (uint32_t)(((lane >> 4) << 3) + (lane & 7)) * AROWB
        + (uint32_t)((lane >> 3) & 1) * 16;
    const uint32_t vb_base = smb + AV_OFF
        + (uint32_t)(((lane >> 4) << 3) + (lane & 7)) * AROWB
        + (uint32_t)((lane >> 3) & 1) * 16;

    float acc_o[8][4];
#pragma unroll
    for (int nt = 0; nt < 8; ++nt)
#pragma unroll
        for (int i = 0; i < 4; ++i) acc_o[nt][i] = 0.0f;
    float mrow[2] = {-1e30f, -1e30f};
    float lrow[2] = {0.0f, 0.0f};

    for (int t0 = 0; t0 < N_; t0 += 64) {
        __syncthreads();
        {
            const int r  = tid >> 2;
            const int qd = tid & 3;
            const float* kp = k + ((size_t)(b * N_ + t0 + r)) * D_ + h * HD_ + qd * 16;
            float f[16];
#pragma unroll
            for (int j = 0; j < 16; ++j) f[j] = kp[j];
            uint32_t hw[8], lw[8];
#pragma unroll
            for (int w = 0; w < 8; ++w) {
                hw[w] = hi_pair(f[2*w], f[2*w+1]);
                lw[w] = lo_pair(f[2*w], f[2*w+1]);
            }
            char* dh = asm_ + AK_OFF + r * AROWB + qd * 32;
            char* dl = dh + 128;
#pragma unroll
            for (int g2 = 0; g2 < 2; ++g2) {
                *(uint4*)(dh + g2 * 16) =
                    make_uint4(hw[4*g2], hw[4*g2+1], hw[4*g2+2], hw[4*g2+3]);
                *(uint4*)(dl + g2 * 16) =
                    make_uint4(lw[4*g2], lw[4*g2+1], lw[4*g2+2], lw[4*g2+3]);
            }
        }
        {
            const float* v0p = v + ((size_t)(b * N_ + t0 + 2*lane))     * D_ + h * HD_ + warp * 8;
            const float* v1p = v + ((size_t)(b * N_ + t0 + 2*lane + 1)) * D_ + h * HD_ + warp * 8;
            float f0[8], f1[8];
            *(float4*)&f0[0] = *(const float4*)&v0p[0];
            *(float4*)&f0[4] = *(const float4*)&v0p[4];
            *(float4*)&f1[0] = *(const float4*)&v1p[0];
            *(float4*)&f1[4] = *(const float4*)&v1p[4];
#pragma unroll
            for (int j = 0; j < 8; ++j) {
                int hd = warp * 8 + j;
                *(uint32_t*)(asm_ + AV_OFF + hd * AROWB + lane * 4)       = hi_pair(f0[j], f1[j]);
                *(uint32_t*)(asm_ + AV_OFF + hd * AROWB + 128 + lane * 4) = lo_pair(f0[j], f1[j]);
            }
        }
        __syncthreads();

        float s[8][4];
#pragma unroll
        for (int nt = 0; nt < 8; ++nt)
#pragma unroll
            for (int i = 0; i < 4; ++i) s[nt][i] = 0.0f;
#pragma unroll
        for (int ks = 0; ks < 4; ++ks) {
            uint32_t ah[4], al[4];
            LDMX4(ah[0], ah[1], ah[2], ah[3], a_base + ks * 32);
            LDMX4(al[0], al[1], al[2], al[3], a_base + ks * 32 + 128);
#pragma unroll
            for (int npp = 0; npp < 2; ++npp) {
                const int np0 = npp * 2, np1 = npp * 2 + 1;
                uint32_t bh0[4], bl0[4], bh1[4], bl1[4];
                LDMX4(bh0[0], bh0[1], bh0[2], bh0[3],
                      kb_base + np0 * (16 * AROWB) + ks * 32);
                LDMX4(bl0[0], bl0[1], bl0[2], bl0[3],
                      kb_base + np0 * (16 * AROWB) + ks * 32 + 128);
                LDMX4(bh1[0], bh1[1], bh1[2], bh1[3],
                      kb_base + np1 * (16 * AROWB) + ks * 32);
                LDMX4(bl1[0], bl1[1], bl1[2], bl1[3],
                      kb_base + np1 * (16 * AROWB) + ks * 32 + 128);
                MMA_BF16(s[2*np0],     ah, bh0[0], bh0[1]);
                MMA_BF16(s[2*np0 + 1], ah, bh0[2], bh0[3]);
                MMA_BF16(s[2*np1],     ah, bh1[0], bh1[1]);
                MMA_BF16(s[2*np1 + 1], ah, bh1[2], bh1[3]);
                MMA_BF16(s[2*np0],     al, bh0[0], bh0[1]);
                MMA_BF16(s[2*np0 + 1], al, bh0[2], bh0[3]);
                MMA_BF16(s[2*np1],     al, bh1[0], bh1[1]);
                MMA_BF16(s[2*np1 + 1], al, bh1[2], bh1[3]);
                MMA_BF16(s[2*np0],     ah, bl0[0], bl0[1]);
                MMA_BF16(s[2*np0 + 1], ah, bl0[2], bl0[3]);
                MMA_BF16(s[2*np1],     ah, bl1[0], bl1[1]);
                MMA_BF16(s[2*np1 + 1], ah, bl1[2], bl1[3]);
            }
        }

#pragma unroll
        for (int r2 = 0; r2 < 2; ++r2) {
            float mx = -1e30f;
#pragma unroll
            for (int nt = 0; nt < 8; ++nt)
                mx = fmaxf(mx, fmaxf(s[nt][r2*2], s[nt][r2*2+1]));
#pragma unroll
            for (int off = 1; off <= 2; off <<= 1)
                mx = fmaxf(mx, __shfl_xor_sync(0xffffffffu, mx, off));
            float mnew = fmaxf(mrow[r2], mx);
            float corr = fexp2(mrow[r2] - mnew);
            float ps = 0.0f;
#pragma unroll
            for (int nt = 0; nt < 8; ++nt) {
                float p0 = fexp2(s[nt][r2*2]   - mnew);
                float p1 = fexp2(s[nt][r2*2+1] - mnew);
                s[nt][r2*2] = p0; s[nt][r2*2+1] = p1;
                ps += p0 + p1;
            }
#pragma unroll
            for (int off = 1; off <= 2; off <<= 1)
                ps += __shfl_xor_sync(0xffffffffu, ps, off);
            lrow[r2] = lrow[r2] * corr + ps;
            mrow[r2] = mnew;
#pragma unroll
            for (int nt = 0; nt < 8; ++nt) {
                acc_o[nt][r2*2]   *= corr;
                acc_o[nt][r2*2+1] *= corr;
            }
        }

#pragma unroll
        for (int kt = 0; kt < 4; ++kt) {
            uint32_t pah[4], pal[4];
            pah[0] = hi_pair(s[2*kt][0],   s[2*kt][1]);
            pah[1] = hi_pair(s[2*kt][2],   s[2*kt][3]);
            pah[2] = hi_pair(s[2*kt+1][0], s[2*kt+1][1]);
            pah[3] = hi_pair(s[2*kt+1][2], s[2*kt+1][3]);
            pal[0] = lo_pair(s[2*kt][0],   s[2*kt][1]);
            pal[1] = lo_pair(s[2*kt][2],   s[2*kt][3]);
            pal[2] = lo_pair(s[2*kt+1][0], s[2*kt+1][1]);
            pal[3] = lo_pair(s[2*kt+1][2], s[2*kt+1][3]);
#pragma unroll
            for (int npp = 0; npp < 2; ++npp) {
                const int np0 = npp * 2, np1 = npp * 2 + 1;
                uint32_t vh0[4], vl0[4], vh1[4], vl1[4];
                LDMX4(vh0[0], vh0[1], vh0[2], vh0[3],
                      vb_base + np0 * (16 * AROWB) + kt * 32);
                LDMX4(vl0[0], vl0[1], vl0[2], vl0[3],
                      vb_base + np0 * (16 * AROWB) + kt * 32 + 128);
                LDMX4(vh1[0], vh1[1], vh1[2], vh1[3],
                      vb_base + np1 * (16 * AROWB) + kt * 32);
                LDMX4(vl1[0], vl1[1], vl1[2], vl1[3],
                      vb_base + np1 * (16 * AROWB) + kt * 32 + 128);
                MMA_BF16(acc_o[2*np0],     pah, vh0[0], vh0[1]);
                MMA_BF16(acc_o[2*np0 + 1], pah, vh0[2], vh0[3]);
                MMA_BF16(acc_o[2*np1],     pah, vh1[0], vh1[1]);
                MMA_BF16(acc_o[2*np1 + 1], pah, vh1[2], vh1[3]);
                MMA_BF16(acc_o[2*np0],     pal, vh0[0], vh0[1]);
                MMA_BF16(acc_o[2*np0 + 1], pal, vh0[2], vh0[3]);
                MMA_BF16(acc_o[2*np1],     pal, vh1[0], vh1[1]);
                MMA_BF16(acc_o[2*np1 + 1], pal, vh1[2], vh1[3]);
                MMA_BF16(acc_o[2*np0],     pah, vl0[0], vl0[1]);
                MMA_BF16(acc_o[2*np0 + 1], pah, vl0[2], vl0[3]);
                MMA_BF16(acc_o[2*np1],     pah, vl1[0], vl1[1]);
                MMA_BF16(acc_o[2*np1 + 1], pah, vl1[2], vl1[3]);
            }
        }
    }

    float inv0 = 1.0f / lrow[0];
    float inv1 = 1.0f / lrow[1];
#pragma unroll
    for (int r2 = 0; r2 < 2; ++r2) {
        int grow = b * N_ + q0 + warp * 16 + g + r2 * 8;
        float inv = r2 ? inv1 : inv0;
        float* cp = ctx + (size_t)grow * D_ + h * HD_;
#pragma unroll
        for (int nt = 0; nt < 8; ++nt) {
            int cc = nt * 8 + t4 * 2;
            *(float2*)&cp[cc] = make_float2(acc_o[nt][r2*2] * inv,
                                            acc_o[nt][r2*2+1] * inv);
        }
    }
}

// ---------------------------------------------------------------------------
// mean-pool + classifier
// ---------------------------------------------------------------------------
__global__ __launch_bounds__(256) void pool_cls_kernel(
    const float* __restrict__ xm,
    const float* __restrict__ Wc,
    const float* __restrict__ bc,
    float* __restrict__ out)
{
    __shared__ float pooled[D_];
    const int b = blockIdx.x;
    const int t = threadIdx.x;
    float s = 0.0f;
    const float* p = xm + (size_t)b * N_ * D_ + t;
#pragma unroll 8
    for (int n = 0; n < N_; ++n) s += p[(size_t)n * D_];
    pooled[t] = s * (1.0f / (float)N_);
    __syncthreads();
    if (t < 2) {
        float a = bc[t];
        for (int c = 0; c < D_; ++c) a = fmaf(pooled[c], Wc[t * D_ + c], a);
        out[b * 2 + t] = a;
    }
}

// ---------------------------------------------------------------------------
// Launch
// ---------------------------------------------------------------------------
static float* sym(const void* s) {
    void* p = nullptr;
    cudaGetSymbolAddress(&p, s);
    return (float*)p;
}

extern "C" void kernel_launch(void* const* d_in, const int* in_sizes, int n_in,
                              void* d_out, int out_size)
{
    const float* x   = (const float*)d_in[0];
    const float* y   = (const float*)d_in[1];
    const float* Wr  = (const float*)d_in[3];
    const float* br  = (const float*)d_in[4];
    const float* Wf  = (const float*)d_in[5];
    const float* bf  = (const float*)d_in[6];
    const float* g_x = (const float*)d_in[7];
    const float* b_x = (const float*)d_in[8];
    const float* g_y = (const float*)d_in[9];
    const float* b_y = (const float*)d_in[10];
    const float* Wq  = (const float*)d_in[11];
    const float* bq  = (const float*)d_in[12];
    const float* Wk  = (const float*)d_in[13];
    const float* bk  = (const float*)d_in[14];
    const float* Wv  = (const float*)d_in[15];
    const float* bv  = (const float*)d_in[16];
    const float* Wo  = (const float*)d_in[17];
    const float* bo  = (const float*)d_in[18];
    const float* g_m = (const float*)d_in[19];
    const float* b_m = (const float*)d_in[20];
    const float* W1  = (const float*)d_in[21];
    const float* b1  = (const float*)d_in[22];
    const float* W2  = (const float*)d_in[23];
    const float* b2  = (const float*)d_in[24];
    const float* Wc  = (const float*)d_in[25];
    const float* bc  = (const float*)d_in[26];
    float* out = (float*)d_out;

    float* xp   = sym(g_xp);
    float* yp   = sym(g_yp);
    float* qb   = sym(g_q);
    float* kb   = sym(g_k);
    float* vb   = sym(g_v);
    float* ctx  = sym(g_ctx);
    float* xres = sym(g_xres);
    float* hid  = sym(g_hid);
    float* xmlp = sym(g_xmlp);
    float* pe   = sym(g_pe);
    uint32_t* wb;
    {
        void* p = nullptr;
        cudaGetSymbolAddress(&p, g_wbuf);
        wb = (uint32_t*)p;
    }

    static bool attr_set = false;
    if (!attr_set) {
        cudaFuncSetAttribute(attn_kernel,
                             cudaFuncAttributeMaxDynamicSharedMemorySize, ASM_TOT);
        cudaFuncSetAttribute(hmma_gemm_n128<0>,
                             cudaFuncAttributeMaxDynamicSharedMemorySize, SM_TOT_S);
        cudaFuncSetAttribute(hmma_gemm_n128<1>,
                             cudaFuncAttributeMaxDynamicSharedMemorySize, SM_TOT_S);
        cudaFuncSetAttribute(hmma_gemm_n128<2>,
                             cudaFuncAttributeMaxDynamicSharedMemorySize, SM_TOT_S);
        cudaFuncSetAttribute(hmma_gemm_n128<4>,
                             cudaFuncAttributeMaxDynamicSharedMemorySize, SM_TOT_S);
        attr_set = true;
    }

    dim3 gs(M_ / 64 * 2);  // 1024 CTAs
    dim3 bb(256);
    dim3 lg(M_ / 8);       // 4096 CTAs (LN)

    prep_kernel<<<(WB_TOT + N_ * D_ + 255) / 256, 256>>>(Wr, Wf, Wq, Wk, Wv, Wo, W1, W2);

    // xp_pre = x @ Wr^T + br + pe ; then LN in place
    hmma_gemm_n128<4><<<gs, bb, SM_TOT_S>>>(x, 769, 25, wb + WR_OFF, 800, 0,
                                            br, nullptr, nullptr, pe, xp, nullptr);
    ln_kernel<<<lg, bb>>>(xp, g_x, b_x);
    // yp_pre = y @ Wf^T + bf + pe ; LN
    hmma_gemm_n128<4><<<gs, bb, SM_TOT_S>>>(y, 674, 22, wb + WF_OFF, 704, 0,
                                            bf, nullptr, nullptr, pe, yp, nullptr);
    ln_kernel<<<lg, bb>>>(yp, g_y, b_y);
    // q
    hmma_gemm_n128<0><<<gs, bb, SM_TOT_S>>>(xp, 256, 8, wb + WQ_OFF, 256, 0,
                                            bq, nullptr, nullptr, nullptr, qb, nullptr);
    // k + v fused (gridDim.y = 2)
    hmma_gemm_n128<0><<<dim3(M_ / 64 * 2, 2), bb, SM_TOT_S>>>(yp, 256, 8, wb + WK_OFF,
                                            256, 256 * 256,
                                            bk, bv, nullptr, nullptr, kb, vb);
    // attention
    dim3 ag(N_ / 128, B_ * H_);
    attn_kernel<<<ag, bb, ASM_TOT>>>(qb, kb, vb, ctx);
    // xres_pre = xp + ctx @ Wo^T + bo ; LN
    hmma_gemm_n128<2><<<gs, bb, SM_TOT_S>>>(ctx, 256, 8, wb + WO_OFF, 256, 0,
                                            bo, nullptr, xp, nullptr, xres, nullptr);
    ln_kernel<<<lg, bb>>>(xres, g_m, b_m);
    // hid = relu(xres @ W1^T + b1)
    hmma_gemm_n128<1><<<gs, bb, SM_TOT_S>>>(xres, 256, 8, wb + W1_OFF, 256, 0,
                                            b1, nullptr, nullptr, nullptr, hid, nullptr);
    // xmlp = xres + hid @ W2^T + b2
    hmma_gemm_n128<2><<<gs, bb, SM_TOT_S>>>(hid, 256, 8, wb + W2_OFF, 256, 0,
                                            b2, nullptr, xres, nullptr, xmlp, nullptr);
    // pool + classifier
    pool_cls_kernel<<<B_, bb>>>(xmlp, Wc, bc, out);
}

// round 14
// speedup vs baseline: 5.5624x; 1.0780x over previous
#include <cuda_runtime.h>
#include <cuda_bf16.h>
#include <math.h>
#include <stdint.h>

// ---------------------------------------------------------------------------
// Model dims
// ---------------------------------------------------------------------------
#define B_      64
#define N_      512
#define D_      256
#define H_      4
#define HD_     64
#define M_      (B_ * N_)         // 32768 rows
#define EPS_    1e-5f

// ---------------------------------------------------------------------------
// Scratch: fp32 staging + pair-plane (hi 128 words | lo 128 words per row)
// ---------------------------------------------------------------------------
__device__ float    g_xp  [M_ * D_];
__device__ float    g_yp  [M_ * D_];
__device__ float    g_v   [M_ * D_];
__device__ float    g_xres[M_ * D_];
__device__ float    g_xmlp[M_ * D_];
__device__ float    g_pe  [N_ * D_];
__device__ uint32_t g_xpP [M_ * D_];
__device__ uint32_t g_ypP [M_ * D_];
__device__ uint32_t g_qP  [M_ * D_];
__device__ uint32_t g_kP  [M_ * D_];
__device__ uint32_t g_ctxP[M_ * D_];
__device__ uint32_t g_xrsP[M_ * D_];
__device__ uint32_t g_hidP[M_ * D_];

// bf16 hi/lo weight scratch (chunk-interleaved: 16 hi words, 16 lo words / 32k)
#define WR_OFF  0
#define WF_OFF  (WR_OFF + 256 * 800)
#define WQ_OFF  (WF_OFF + 256 * 704)
#define WK_OFF  (WQ_OFF + 256 * 256)
#define WV_OFF  (WK_OFF + 256 * 256)
#define WO_OFF  (WV_OFF + 256 * 256)
#define W1_OFF  (WO_OFF + 256 * 256)
#define W2_OFF  (W1_OFF + 256 * 256)
#define WB_TOT  (W2_OFF + 256 * 256)
__device__ uint32_t g_wbuf[WB_TOT];

// ---------------------------------------------------------------------------
__device__ __forceinline__ uint32_t hi_pair(float x0, float x1) {
    uint32_t a = __float_as_uint(x0), b = __float_as_uint(x1);
    return (b & 0xffff0000u) | (a >> 16);
}
__device__ __forceinline__ uint32_t lo_pair(float x0, float x1) {
    float l0 = x0 - __uint_as_float(__float_as_uint(x0) & 0xffff0000u);
    float l1 = x1 - __uint_as_float(__float_as_uint(x1) & 0xffff0000u);
    uint32_t a = (uint32_t)__bfloat16_as_ushort(__float2bfloat16(l0));
    uint32_t b = (uint32_t)__bfloat16_as_ushort(__float2bfloat16(l1));
    return (b << 16) | a;
}

__device__ __forceinline__ uint32_t smem_u32(const void* p) {
    uint32_t a;
    asm("{ .reg .u64 t; cvta.to.shared.u64 t, %1; cvt.u32.u64 %0, t; }"
        : "=r"(a) : "l"(p));
    return a;
}

#define LDMX4(r0, r1, r2, r3, addr) \
    asm volatile("ldmatrix.sync.aligned.m8n8.x4.shared.b16 {%0,%1,%2,%3}, [%4];" \
                 : "=r"(r0), "=r"(r1), "=r"(r2), "=r"(r3) : "r"(addr))

#define MMA_BF16(c, a, b0, b1) \
    asm volatile("mma.sync.aligned.m16n8k16.row.col.f32.bf16.bf16.f32 " \
                 "{%0,%1,%2,%3}, {%4,%5,%6,%7}, {%8,%9}, {%0,%1,%2,%3};" \
                 : "+f"((c)[0]), "+f"((c)[1]), "+f"((c)[2]), "+f"((c)[3]) \
                 : "r"((a)[0]), "r"((a)[1]), "r"((a)[2]), "r"((a)[3]), \
                   "r"(b0), "r"(b1))

#define CPASYNC16(dst, src) \
    asm volatile("cp.async.cg.shared.global [%0], [%1], 16;" \
                 :: "r"(dst), "l"(src))
#define CPASYNC_COMMIT()  asm volatile("cp.async.commit_group;" ::: "memory")
#define CPASYNC_WAIT0()   asm volatile("cp.async.wait_group 0;" ::: "memory")

// fast 2^x for x <= 0; rel err ~1.5e-5; no MUFU
__device__ __forceinline__ float fexp2(float x) {
    x = fmaxf(x, -80.0f);
    float n = floorf(x);
    float f = x - n;
    float p = 1.5404e-4f;
    p = fmaf(p, f, 1.333356e-3f);
    p = fmaf(p, f, 9.618130e-3f);
    p = fmaf(p, f, 5.550411e-2f);
    p = fmaf(p, f, 2.402265e-1f);
    p = fmaf(p, f, 6.931472e-1f);
    p = fmaf(p, f, 1.0f);
    return __int_as_float(__float_as_int(p) + ((int)n << 23));
}

// ---------------------------------------------------------------------------
// Prologue: weight hi/lo conversion + PE table
// ---------------------------------------------------------------------------
__global__ void prep_kernel(const float* __restrict__ Wr, const float* __restrict__ Wf,
                            const float* __restrict__ Wq, const float* __restrict__ Wk,
                            const float* __restrict__ Wv, const float* __restrict__ Wo,
                            const float* __restrict__ W1, const float* __restrict__ W2) {
    int idx = blockIdx.x * blockDim.x + threadIdx.x;
    if (idx < WB_TOT) {
        const float* W; int K, rowU32, base;
        if      (idx < WF_OFF) { W = Wr; K = 769; rowU32 = 800; base = WR_OFF; }
        else if (idx < WQ_OFF) { W = Wf; K = 674; rowU32 = 704; base = WF_OFF; }
        else if (idx < WK_OFF) { W = Wq; K = 256; rowU32 = 256; base = WQ_OFF; }
        else if (idx < WV_OFF) { W = Wk; K = 256; rowU32 = 256; base = WK_OFF; }
        else if (idx < WO_OFF) { W = Wv; K = 256; rowU32 = 256; base = WV_OFF; }
        else if (idx < W1_OFF) { W = Wo; K = 256; rowU32 = 256; base = WO_OFF; }
        else if (idx < W2_OFF) { W = W1; K = 256; rowU32 = 256; base = W1_OFF; }
        else                   { W = W2; K = 256; rowU32 = 256; base = W2_OFF; }
        int j   = idx - base;
        int row = j / rowU32;
        int jj  = j - row * rowU32;
        int c   = jj >> 5;
        int t   = jj & 31;
        int e0  = c * 32 + ((t & 15) << 1);
        float v0 = (e0     < K) ? W[(size_t)row * K + e0]     : 0.0f;
        float v1 = (e0 + 1 < K) ? W[(size_t)row * K + e0 + 1] : 0.0f;
        g_wbuf[idx] = (t < 16) ? hi_pair(v0, v1) : lo_pair(v0, v1);
    } else if (idx < WB_TOT + N_ * D_) {
        int j   = idx - WB_TOT;
        int pos = j >> 8;
        int c   = j & 255;
        int i2  = c & ~1;
        float div = expf(-logf(10000.0f) * (float)i2 / (float)D_);
        float ang = (float)pos * div;
        g_pe[j] = (c & 1) ? cosf(ang) : sinf(ang);
    }
}

// ---------------------------------------------------------------------------
// Row LayerNorm: warp per 256-col row. Optional fp32 write-back + pair output.
// ---------------------------------------------------------------------------
__global__ __launch_bounds__(256) void ln_kernel(
    float* __restrict__ io,
    const float* __restrict__ gamma,
    const float* __restrict__ beta,
    int writeF,
    uint32_t* __restrict__ outP)
{
    const int row  = blockIdx.x * 8 + (threadIdx.x >> 5);
    const int lane = threadIdx.x & 31;
    float* p = io + (size_t)row * D_ + lane * 8;
    float4 a = *(float4*)p;
    float4 b = *(float4*)(p + 4);
    float s = a.x + a.y + a.z + a.w + b.x + b.y + b.z + b.w;
    float q = a.x*a.x + a.y*a.y + a.z*a.z + a.w*a.w
            + b.x*b.x + b.y*b.y + b.z*b.z + b.w*b.w;
#pragma unroll
    for (int off = 16; off > 0; off >>= 1) {
        s += __shfl_xor_sync(0xffffffffu, s, off);
        q += __shfl_xor_sync(0xffffffffu, q, off);
    }
    float mu  = s * (1.0f / 256.0f);
    float var = q * (1.0f / 256.0f) - mu * mu;
    float rs  = rsqrtf(var + EPS_);
    const float* gp = gamma + lane * 8;
    const float* bp = beta  + lane * 8;
    float4 g0 = *(const float4*)gp,  g1 = *(const float4*)(gp + 4);
    float4 b0 = *(const float4*)bp,  b1 = *(const float4*)(bp + 4);
    a.x = (a.x - mu) * rs * g0.x + b0.x;  a.y = (a.y - mu) * rs * g0.y + b0.y;
    a.z = (a.z - mu) * rs * g0.z + b0.z;  a.w = (a.w - mu) * rs * g0.w + b0.w;
    b.x = (b.x - mu) * rs * g1.x + b1.x;  b.y = (b.y - mu) * rs * g1.y + b1.y;
    b.z = (b.z - mu) * rs * g1.z + b1.z;  b.w = (b.w - mu) * rs * g1.w + b1.w;
    if (writeF) {
        *(float4*)p       = a;
        *(float4*)(p + 4) = b;
    }
    uint4 hw = make_uint4(hi_pair(a.x, a.y), hi_pair(a.z, a.w),
                          hi_pair(b.x, b.y), hi_pair(b.z, b.w));
    uint4 lw = make_uint4(lo_pair(a.x, a.y), lo_pair(a.z, a.w),
                          lo_pair(b.x, b.y), lo_pair(b.z, b.w));
    *(uint4*)(outP + (size_t)row * 256 + lane * 4)       = hw;
    *(uint4*)(outP + (size_t)row * 256 + 128 + lane * 4) = lw;
}

// ---------------------------------------------------------------------------
// hmma_gemm_n128: 64x128 tile, 3 CTAs/SM, warp tile 32x32, generalized K.
// APAIR=1: A staged via cp.async from pair-plane buffer. gridDim.y picks set.
// EPI: 0=+bias 1=relu(+bias) 2=+bias+res 4=+bias+pe
// ---------------------------------------------------------------------------
#define ROWB     144
#define ABUF_S   (64 * ROWB)
#define BBUF_S   (128 * ROWB)
#define BUFSZ_S  (ABUF_S + BBUF_S)
#define SM_TOT_S (2 * BUFSZ_S)

template <int EPI, int APAIR>
__global__ __launch_bounds__(256, 3) void hmma_gemm_n128(
    const float* __restrict__ A, const uint32_t* __restrict__ Ap,
    int K, int NC,
    const uint32_t* __restrict__ Wbf, int rowU32, int wstride,
    const float* __restrict__ bias, const float* __restrict__ bias2,
    const float* __restrict__ res,
    const float* __restrict__ pe, float scale,
    float* __restrict__ outF, float* __restrict__ outF2,
    uint32_t* __restrict__ outP, uint32_t* __restrict__ outP2)
{
    extern __shared__ __align__(16) char sm[];
    const uint32_t smb = smem_u32(sm);
    const int tid  = threadIdx.x;
    const int lane = tid & 31;
    const int warp = tid >> 5;
    const int wr   = warp >> 2;
    const int wc   = warp & 3;
    const int ch   = blockIdx.x & 1;
    const int row0 = (blockIdx.x >> 1) * 64;

    const float* biasS = blockIdx.y ? bias2 : bias;
    float*       oF    = blockIdx.y ? outF2 : outF;
    uint32_t*    oP    = blockIdx.y ? outP2 : outP;

    const int arow = tid >> 2;
    const int aq   = tid & 3;
    const float*    Apf = A  ? A  + (size_t)(row0 + arow) * K + aq * 8 : nullptr;
    const uint32_t* App = Ap ? Ap + (size_t)(row0 + arow) * K : nullptr;
    const int brow = tid >> 1;
    const int bhf  = tid & 1;
    const uint32_t* Wp = Wbf + (size_t)blockIdx.y * wstride
                       + (size_t)(ch * 128 + brow) * rowU32;

    float acc[2][4][4];
#pragma unroll
    for (int mt = 0; mt < 2; ++mt)
#pragma unroll
        for (int nt = 0; nt < 4; ++nt)
#pragma unroll
            for (int i = 0; i < 4; ++i) acc[mt][nt][i] = 0.0f;

    const uint32_t a_rel = (uint32_t)(wr * 32 + (lane & 15)) * ROWB
                         + (uint32_t)(lane >> 4) * 16;
    const uint32_t b_rel = ABUF_S
                         + (uint32_t)(wc * 32 + ((lane >> 4) << 3) + (lane & 7)) * ROWB
                         + (uint32_t)((lane >> 3) & 1) * 16;

    auto ldgA = [&](int c, float* f) {
#pragma unroll
        for (int j = 0; j < 8; ++j) {
            int kg = c * 32 + aq * 8 + j;
            f[j] = (kg < K) ? Apf[c * 32 + j] : 0.0f;
        }
    };
    auto stsA = [&](const float* f, int p) {
        uint32_t hw[4], lw[4];
#pragma unroll
        for (int w = 0; w < 4; ++w) {
            hw[w] = hi_pair(f[2*w], f[2*w+1]);
            lw[w] = lo_pair(f[2*w], f[2*w+1]);
        }
        char* dh = sm + p * BUFSZ_S + arow * ROWB + aq * 16;
        *(uint4*)dh        = make_uint4(hw[0], hw[1], hw[2], hw[3]);
        *(uint4*)(dh + 64) = make_uint4(lw[0], lw[1], lw[2], lw[3]);
    };
    auto cpA = [&](int c, int p) {
        uint32_t dst = smb + p * BUFSZ_S + arow * ROWB + aq * 16;
        const char* srcH = (const char*)(App + c * 16 + aq * 4);
        const char* srcL = (const char*)(App + (K >> 1) + c * 16 + aq * 4);
        CPASYNC16(dst, srcH);
        CPASYNC16(dst + 64, srcL);
    };
    auto cpB = [&](int c, int p) {
        uint32_t dst = smb + p * BUFSZ_S + ABUF_S + brow * ROWB + bhf * 64;
        const char* src = (const char*)(Wp + c * 32 + bhf * 16);
#pragma unroll
        for (int g2 = 0; g2 < 4; ++g2)
            CPASYNC16(dst + g2 * 16, src + g2 * 16);
    };

    if (APAIR) {
        cpA(0, 0); cpB(0, 0);
        CPASYNC_COMMIT();
        CPASYNC_WAIT0();
    } else {
        float f0[8];
        ldgA(0, f0);
        cpB(0, 0);
        CPASYNC_COMMIT();
        stsA(f0, 0);
        CPASYNC_WAIT0();
    }
    __syncthreads();

    int p = 0;
    for (int c = 0; c < NC; ++c) {
        const bool have = (c + 1 < NC);
        float fn[8];
        if (have) {
            if (APAIR) { cpA(c + 1, p ^ 1); cpB(c + 1, p ^ 1); CPASYNC_COMMIT(); }
            else       { cpB(c + 1, p ^ 1); CPASYNC_COMMIT(); ldgA(c + 1, fn); }
        }
        const uint32_t ab = smb + p * BUFSZ_S + a_rel;
        const uint32_t bb = smb + p * BUFSZ_S + b_rel;
#pragma unroll
        for (int ks = 0; ks < 2; ++ks) {
            uint32_t ah[2][4], al[2][4];
#pragma unroll
            for (int mt = 0; mt < 2; ++mt) {
                LDMX4(ah[mt][0], ah[mt][1], ah[mt][2], ah[mt][3],
                      ab + mt * (16 * ROWB) + ks * 32);
                LDMX4(al[mt][0], al[mt][1], al[mt][2], al[mt][3],
                      ab + mt * (16 * ROWB) + ks * 32 + 64);
            }
            uint32_t bh0[4], bl0[4], bh1[4], bl1[4];
            LDMX4(bh0[0], bh0[1], bh0[2], bh0[3], bb + ks * 32);
            LDMX4(bl0[0], bl0[1], bl0[2], bl0[3], bb + ks * 32 + 64);
            LDMX4(bh1[0], bh1[1], bh1[2], bh1[3], bb + 16 * ROWB + ks * 32);
            LDMX4(bl1[0], bl1[1], bl1[2], bl1[3], bb + 16 * ROWB + ks * 32 + 64);
            // term 1
            MMA_BF16(acc[0][0], ah[0], bh0[0], bh0[1]);
            MMA_BF16(acc[1][0], ah[1], bh0[0], bh0[1]);
            MMA_BF16(acc[0][1], ah[0], bh0[2], bh0[3]);
            MMA_BF16(acc[1][1], ah[1], bh0[2], bh0[3]);
            MMA_BF16(acc[0][2], ah[0], bh1[0], bh1[1]);
            MMA_BF16(acc[1][2], ah[1], bh1[0], bh1[1]);
            MMA_BF16(acc[0][3], ah[0], bh1[2], bh1[3]);
            MMA_BF16(acc[1][3], ah[1], bh1[2], bh1[3]);
            // term 2
            MMA_BF16(acc[0][0], al[0], bh0[0], bh0[1]);
            MMA_BF16(acc[1][0], al[1], bh0[0], bh0[1]);
            MMA_BF16(acc[0][1], al[0], bh0[2], bh0[3]);
            MMA_BF16(acc[1][1], al[1], bh0[2], bh0[3]);
            MMA_BF16(acc[0][2], al[0], bh1[0], bh1[1]);
            MMA_BF16(acc[1][2], al[1], bh1[0], bh1[1]);
            MMA_BF16(acc[0][3], al[0], bh1[2], bh1[3]);
            MMA_BF16(acc[1][3], al[1], bh1[2], bh1[3]);
            // term 3
            MMA_BF16(acc[0][0], ah[0], bl0[0], bl0[1]);
            MMA_BF16(acc[1][0], ah[1], bl0[0], bl0[1]);
            MMA_BF16(acc[0][1], ah[0], bl0[2], bl0[3]);
            MMA_BF16(acc[1][1], ah[1], bl0[2], bl0[3]);
            MMA_BF16(acc[0][2], ah[0], bl1[0], bl1[1]);
            MMA_BF16(acc[1][2], ah[1], bl1[0], bl1[1]);
            MMA_BF16(acc[0][3], ah[0], bl1[2], bl1[3]);
            MMA_BF16(acc[1][3], ah[1], bl1[2], bl1[3]);
        }
        if (have && !APAIR) stsA(fn, p ^ 1);
        CPASYNC_WAIT0();
        __syncthreads();
        p ^= 1;
    }

    // ---------------- epilogue ----------------
    const int g  = lane >> 2;
    const int t4 = lane & 3;
#pragma unroll
    for (int mt = 0; mt < 2; ++mt)
#pragma unroll
        for (int h = 0; h < 2; ++h) {
            int row  = wr * 32 + mt * 16 + g + h * 8;
            int grow = row0 + row;
            const float* rp = (EPI == 2) ? res + (size_t)grow * D_ : nullptr;
            const float* pp = (EPI == 4) ? pe + (size_t)(grow & (N_ - 1)) * D_ : nullptr;
#pragma unroll
            for (int nt = 0; nt < 4; ++nt) {
                int cc = ch * 128 + wc * 32 + nt * 8 + t4 * 2;
                float v0 = acc[mt][nt][h*2]   + biasS[cc];
                float v1 = acc[mt][nt][h*2+1] + biasS[cc + 1];
                if (EPI == 1) { v0 = fmaxf(v0, 0.0f); v1 = fmaxf(v1, 0.0f); }
                if (EPI == 2) {
                    float2 rv = *(const float2*)&rp[cc];
                    v0 += rv.x; v1 += rv.y;
                }
                if (EPI == 4) {
                    float2 pv = *(const float2*)&pp[cc];
                    v0 += pv.x; v1 += pv.y;
                }
                v0 *= scale; v1 *= scale;
                if (oF) *(float2*)&oF[(size_t)grow * D_ + cc] = make_float2(v0, v1);
                if (oP) {
                    int pidx = cc >> 1;
                    oP[(size_t)grow * 256 + pidx]       = hi_pair(v0, v1);
                    oP[(size_t)grow * 256 + 128 + pidx] = lo_pair(v0, v1);
                }
            }
        }
}

// ---------------------------------------------------------------------------
// HMMA flash attention v3: Q/K staged via cp.async from pair-plane buffers;
// V converted+transposed in-kernel; ctx emitted as pair-plane.
// ---------------------------------------------------------------------------
#define AROWB   272
#define AQ_OFF  0
#define AK_OFF  (128 * AROWB)
#define AV_OFF  (AK_OFF + 64 * AROWB)
#define ASM_TOT (AV_OFF + 64 * AROWB)
#define QSCALE  0.1803368801111204f       // 0.125 * log2(e)

__global__ __launch_bounds__(256, 2) void attn_kernel(
    const uint32_t* __restrict__ qP,
    const uint32_t* __restrict__ kP,
    const float* __restrict__ v,
    uint32_t* __restrict__ ctxP)
{
    extern __shared__ __align__(16) char asm_[];
    const uint32_t smb = smem_u32(asm_);
    const int tid  = threadIdx.x;
    const int lane = tid & 31;
    const int warp = tid >> 5;
    const int bh   = blockIdx.y;
    const int b    = bh >> 2;
    const int h    = bh & 3;
    const int q0   = blockIdx.x * 128;
    const int g    = lane >> 2;
    const int t4   = lane & 3;

    // ---- stage Q from pairs: row = tid>>1, half hf (16 words hi + 16 lo)
    {
        const int r  = tid >> 1;
        const int hf = tid & 1;
        const uint32_t* src = qP + (size_t)(b * N_ + q0 + r) * 256 + h * 32 + hf * 16;
        char* dh = asm_ + AQ_OFF + r * AROWB + hf * 64;
#pragma unroll
        for (int g2 = 0; g2 < 4; ++g2) {
            *(uint4*)(dh + g2 * 16)       = *(const uint4*)(src + g2 * 4);
            *(uint4*)(dh + 128 + g2 * 16) = *(const uint4*)(src + 128 + g2 * 4);
        }
    }

    const uint32_t a_base = smb + AQ_OFF
        + (uint32_t)(warp * 16 + (lane & 15)) * AROWB + (uint32_t)(lane >> 4) * 16;
    const uint32_t kb_base = smb + AK_OFF
        + (uint32_t)(((lane >> 4) << 3) + (lane & 7)) * AROWB
        + (uint32_t)((lane >> 3) & 1) * 16;
    const uint32_t vb_base = smb + AV_OFF
        + (uint32_t)(((lane >> 4) << 3) + (lane & 7)) * AROWB
        + (uint32_t)((lane >> 3) & 1) * 16;

    float acc_o[8][4];
#pragma unroll
    for (int nt = 0; nt < 8; ++nt)
#pragma unroll
        for (int i = 0; i < 4; ++i) acc_o[nt][i] = 0.0f;
    float mrow[2] = {-1e30f, -1e30f};
    float lrow[2] = {0.0f, 0.0f};

    for (int t0 = 0; t0 < N_; t0 += 64) {
        __syncthreads();
        // ---- stage K via cp.async: row = tid>>2 (0..63), quarter qd.
        // Full head = 32 hi words + 32 lo words per row; each thread copies
        // 8 hi (2x16B) + 8 lo. [R13 bug: only 4+4 words -> half tile stale]
        {
            const int r  = tid >> 2;
            const int qd = tid & 3;
            const uint32_t* src = kP + (size_t)(b * N_ + t0 + r) * 256 + h * 32 + qd * 8;
            uint32_t dst = smb + AK_OFF + r * AROWB + qd * 32;
            CPASYNC16(dst,            (const char*)src);
            CPASYNC16(dst + 16,       (const char*)(src + 4));
            CPASYNC16(dst + 128,      (const char*)(src + 128));
            CPASYNC16(dst + 128 + 16, (const char*)(src + 128 + 4));
        }
        CPASYNC_COMMIT();
        // ---- stage V transposed (fp32 -> pairs), lane = kv-pair
        {
            const float* v0p = v + ((size_t)(b * N_ + t0 + 2*lane))     * D_ + h * HD_ + warp * 8;
            const float* v1p = v + ((size_t)(b * N_ + t0 + 2*lane + 1)) * D_ + h * HD_ + warp * 8;
            float f0[8], f1[8];
            *(float4*)&f0[0] = *(const float4*)&v0p[0];
            *(float4*)&f0[4] = *(const float4*)&v0p[4];
            *(float4*)&f1[0] = *(const float4*)&v1p[0];
            *(float4*)&f1[4] = *(const float4*)&v1p[4];
#pragma unroll
            for (int j = 0; j < 8; ++j) {
                int hd = warp * 8 + j;
                *(uint32_t*)(asm_ + AV_OFF + hd * AROWB + lane * 4)       = hi_pair(f0[j], f1[j]);
                *(uint32_t*)(asm_ + AV_OFF + hd * AROWB + 128 + lane * 4) = lo_pair(f0[j], f1[j]);
            }
        }
        CPASYNC_WAIT0();
        __syncthreads();

        float s[8][4];
#pragma unroll
        for (int nt = 0; nt < 8; ++nt)
#pragma unroll
            for (int i = 0; i < 4; ++i) s[nt][i] = 0.0f;
#pragma unroll
        for (int ks = 0; ks < 4; ++ks) {
            uint32_t ah[4], al[4];
            LDMX4(ah[0], ah[1], ah[2], ah[3], a_base + ks * 32);
            LDMX4(al[0], al[1], al[2], al[3], a_base + ks * 32 + 128);
#pragma unroll
            for (int npp = 0; npp < 2; ++npp) {
                const int np0 = npp * 2, np1 = npp * 2 + 1;
                uint32_t bh0[4], bl0[4], bh1[4], bl1[4];
                LDMX4(bh0[0], bh0[1], bh0[2], bh0[3],
                      kb_base + np0 * (16 * AROWB) + ks * 32);
                LDMX4(bl0[0], bl0[1], bl0[2], bl0[3],
                      kb_base + np0 * (16 * AROWB) + ks * 32 + 128);
                LDMX4(bh1[0], bh1[1], bh1[2], bh1[3],
                      kb_base + np1 * (16 * AROWB) + ks * 32);
                LDMX4(bl1[0], bl1[1], bl1[2], bl1[3],
                      kb_base + np1 * (16 * AROWB) + ks * 32 + 128);
                MMA_BF16(s[2*np0],     ah, bh0[0], bh0[1]);
                MMA_BF16(s[2*np0 + 1], ah, bh0[2], bh0[3]);
                MMA_BF16(s[2*np1],     ah, bh1[0], bh1[1]);
                MMA_BF16(s[2*np1 + 1], ah, bh1[2], bh1[3]);
                MMA_BF16(s[2*np0],     al, bh0[0], bh0[1]);
                MMA_BF16(s[2*np0 + 1], al, bh0[2], bh0[3]);
                MMA_BF16(s[2*np1],     al, bh1[0], bh1[1]);
                MMA_BF16(s[2*np1 + 1], al, bh1[2], bh1[3]);
                MMA_BF16(s[2*np0],     ah, bl0[0], bl0[1]);
                MMA_BF16(s[2*np0 + 1], ah, bl0[2], bl0[3]);
                MMA_BF16(s[2*np1],     ah, bl1[0], bl1[1]);
                MMA_BF16(s[2*np1 + 1], ah, bl1[2], bl1[3]);
            }
        }

#pragma unroll
        for (int r2 = 0; r2 < 2; ++r2) {
            float mx = -1e30f;
#pragma unroll
            for (int nt = 0; nt < 8; ++nt)
                mx = fmaxf(mx, fmaxf(s[nt][r2*2], s[nt][r2*2+1]));
#pragma unroll
            for (int off = 1; off <= 2; off <<= 1)
                mx = fmaxf(mx, __shfl_xor_sync(0xffffffffu, mx, off));
            float mnew = fmaxf(mrow[r2], mx);
            float corr = fexp2(mrow[r2] - mnew);
            float ps = 0.0f;
#pragma unroll
            for (int nt = 0; nt < 8; ++nt) {
                float p0 = fexp2(s[nt][r2*2]   - mnew);
                float p1 = fexp2(s[nt][r2*2+1] - mnew);
                s[nt][r2*2] = p0; s[nt][r2*2+1] = p1;
                ps += p0 + p1;
            }
#pragma unroll
            for (int off = 1; off <= 2; off <<= 1)
                ps += __shfl_xor_sync(0xffffffffu, ps, off);
            lrow[r2] = lrow[r2] * corr + ps;
            mrow[r2] = mnew;
#pragma unroll
            for (int nt = 0; nt < 8; ++nt) {
                acc_o[nt][r2*2]   *= corr;
                acc_o[nt][r2*2+1] *= corr;
            }
        }

#pragma unroll
        for (int kt = 0; kt < 4; ++kt) {
            uint32_t pah[4], pal[4];
            pah[0] = hi_pair(s[2*kt][0],   s[2*kt][1]);
            pah[1] = hi_pair(s[2*kt][2],   s[2*kt][3]);
            pah[2] = hi_pair(s[2*kt+1][0], s[2*kt+1][1]);
            pah[3] = hi_pair(s[2*kt+1][2], s[2*kt+1][3]);
            pal[0] = lo_pair(s[2*kt][0],   s[2*kt][1]);
            pal[1] = lo_pair(s[2*kt][2],   s[2*kt][3]);
            pal[2] = lo_pair(s[2*kt+1][0], s[2*kt+1][1]);
            pal[3] = lo_pair(s[2*kt+1][2], s[2*kt+1][3]);
#pragma unroll
            for (int npp = 0; npp < 2; ++npp) {
                const int np0 = npp * 2, np1 = npp * 2 + 1;
                uint32_t vh0[4], vl0[4], vh1[4], vl1[4];
                LDMX4(vh0[0], vh0[1], vh0[2], vh0[3],
                      vb_base + np0 * (16 * AROWB) + kt * 32);
                LDMX4(vl0[0], vl0[1], vl0[2], vl0[3],
                      vb_base + np0 * (16 * AROWB) + kt * 32 + 128);
                LDMX4(vh1[0], vh1[1], vh1[2], vh1[3],
                      vb_base + np1 * (16 * AROWB) + kt * 32);
                LDMX4(vl1[0], vl1[1], vl1[2], vl1[3],
                      vb_base + np1 * (16 * AROWB) + kt * 32 + 128);
                MMA_BF16(acc_o[2*np0],     pah, vh0[0], vh0[1]);
                MMA_BF16(acc_o[2*np0 + 1], pah, vh0[2], vh0[3]);
                MMA_BF16(acc_o[2*np1],     pah, vh1[0], vh1[1]);
                MMA_BF16(acc_o[2*np1 + 1], pah, vh1[2], vh1[3]);
                MMA_BF16(acc_o[2*np0],     pal, vh0[0], vh0[1]);
                MMA_BF16(acc_o[2*np0 + 1], pal, vh0[2], vh0[3]);
                MMA_BF16(acc_o[2*np1],     pal, vh1[0], vh1[1]);
                MMA_BF16(acc_o[2*np1 + 1], pal, vh1[2], vh1[3]);
                MMA_BF16(acc_o[2*np0],     pah, vl0[0], vl0[1]);
                MMA_BF16(acc_o[2*np0 + 1], pah, vl0[2], vl0[3]);
                MMA_BF16(acc_o[2*np1],     pah, vl1[0], vl1[1]);
                MMA_BF16(acc_o[2*np1 + 1], pah, vl1[2], vl1[3]);
            }
        }
    }

    // ---- write ctx as pair-plane
    float inv0 = 1.0f / lrow[0];
    float inv1 = 1.0f / lrow[1];
#pragma unroll
    for (int r2 = 0; r2 < 2; ++r2) {
        int grow = b * N_ + q0 + warp * 16 + g + r2 * 8;
        float inv = r2 ? inv1 : inv0;
#pragma unroll
        for (int nt = 0; nt < 8; ++nt) {
            float v0 = acc_o[nt][r2*2]   * inv;
            float v1 = acc_o[nt][r2*2+1] * inv;
            int pidx = h * 32 + nt * 4 + t4;
            ctxP[(size_t)grow * 256 + pidx]       = hi_pair(v0, v1);
            ctxP[(size_t)grow * 256 + 128 + pidx] = lo_pair(v0, v1);
        }
    }
}

// ---------------------------------------------------------------------------
// mean-pool + classifier
// ---------------------------------------------------------------------------
__global__ __launch_bounds__(256) void pool_cls_kernel(
    const float* __restrict__ xm,
    const float* __restrict__ Wc,
    const float* __restrict__ bc,
    float* __restrict__ out)
{
    __shared__ float pooled[D_];
    const int b = blockIdx.x;
    const int t = threadIdx.x;
    float s = 0.0f;
    const float* p = xm + (size_t)b * N_ * D_ + t;
#pragma unroll 8
    for (int n = 0; n < N_; ++n) s += p[(size_t)n * D_];
    pooled[t] = s * (1.0f / (float)N_);
    __syncthreads();
    if (t < 2) {
        float a = bc[t];
        for (int c = 0; c < D_; ++c) a = fmaf(pooled[c], Wc[t * D_ + c], a);
        out[b * 2 + t] = a;
    }
}

// ---------------------------------------------------------------------------
// Launch
// ---------------------------------------------------------------------------
static void* symp(const void* s) {
    void* p = nullptr;
    cudaGetSymbolAddress(&p, s);
    return p;
}

extern "C" void kernel_launch(void* const* d_in, const int* in_sizes, int n_in,
                              void* d_out, int out_size)
{
    const float* x   = (const float*)d_in[0];
    const float* y   = (const float*)d_in[1];
    const float* Wr  = (const float*)d_in[3];
    const float* br  = (const float*)d_in[4];
    const float* Wf  = (const float*)d_in[5];
    const float* bf  = (const float*)d_in[6];
    const float* g_x = (const float*)d_in[7];
    const float* b_x = (const float*)d_in[8];
    const float* g_y = (const float*)d_in[9];
    const float* b_y = (const float*)d_in[10];
    const float* Wq  = (const float*)d_in[11];
    const float* bq  = (const float*)d_in[12];
    const float* Wk  = (const float*)d_in[13];
    const float* bk  = (const float*)d_in[14];
    const float* Wv  = (const float*)d_in[15];
    const float* bv  = (const float*)d_in[16];
    const float* Wo  = (const float*)d_in[17];
    const float* bo  = (const float*)d_in[18];
    const float* g_m = (const float*)d_in[19];
    const float* b_m = (const float*)d_in[20];
    const float* W1  = (const float*)d_in[21];
    const float* b1  = (const float*)d_in[22];
    const float* W2  = (const float*)d_in[23];
    const float* b2  = (const float*)d_in[24];
    const float* Wc  = (const float*)d_in[25];
    const float* bc  = (const float*)d_in[26];
    float* out = (float*)d_out;

    float*    xp   = (float*)symp(g_xp);
    float*    yp   = (float*)symp(g_yp);
    float*    vb_  = (float*)symp(g_v);
    float*    xres = (float*)symp(g_xres);
    float*    xmlp = (float*)symp(g_xmlp);
    float*    pe   = (float*)symp(g_pe);
    uint32_t* xpP  = (uint32_t*)symp(g_xpP);
    uint32_t* ypP  = (uint32_t*)symp(g_ypP);
    uint32_t* qP   = (uint32_t*)symp(g_qP);
    uint32_t* kP   = (uint32_t*)symp(g_kP);
    uint32_t* ctxP = (uint32_t*)symp(g_ctxP);
    uint32_t* xrsP = (uint32_t*)symp(g_xrsP);
    uint32_t* hidP = (uint32_t*)symp(g_hidP);
    uint32_t* wb   = (uint32_t*)symp(g_wbuf);

    static bool attr_set = false;
    if (!attr_set) {
        cudaFuncSetAttribute(attn_kernel,
                             cudaFuncAttributeMaxDynamicSharedMemorySize, ASM_TOT);
        cudaFuncSetAttribute(hmma_gemm_n128<0, 1>,
                             cudaFuncAttributeMaxDynamicSharedMemorySize, SM_TOT_S);
        cudaFuncSetAttribute(hmma_gemm_n128<1, 1>,
                             cudaFuncAttributeMaxDynamicSharedMemorySize, SM_TOT_S);
        cudaFuncSetAttribute(hmma_gemm_n128<2, 1>,
                             cudaFuncAttributeMaxDynamicSharedMemorySize, SM_TOT_S);
        cudaFuncSetAttribute(hmma_gemm_n128<4, 0>,
                             cudaFuncAttributeMaxDynamicSharedMemorySize, SM_TOT_S);
        attr_set = true;
    }

    dim3 gs(M_ / 64 * 2);  // 1024 CTAs
    dim3 bb(256);
    dim3 lg(M_ / 8);       // 4096 CTAs (LN)

    prep_kernel<<<(WB_TOT + N_ * D_ + 255) / 256, 256>>>(Wr, Wf, Wq, Wk, Wv, Wo, W1, W2);

    // xp = x @ Wr^T + br + pe ; LN in place + pairs
    hmma_gemm_n128<4, 0><<<gs, bb, SM_TOT_S>>>(x, nullptr, 769, 25, wb + WR_OFF, 800, 0,
        br, nullptr, nullptr, pe, 1.0f, xp, nullptr, nullptr, nullptr);
    ln_kernel<<<lg, bb>>>(xp, g_x, b_x, 1, xpP);
    // yp = y @ Wf^T + bf + pe ; LN -> pairs only
    hmma_gemm_n128<4, 0><<<gs, bb, SM_TOT_S>>>(y, nullptr, 674, 22, wb + WF_OFF, 704, 0,
        bf, nullptr, nullptr, pe, 1.0f, yp, nullptr, nullptr, nullptr);
    ln_kernel<<<lg, bb>>>(yp, g_y, b_y, 0, ypP);
    // q (scaled pairs)
    hmma_gemm_n128<0, 1><<<gs, bb, SM_TOT_S>>>(nullptr, xpP, 256, 8, wb + WQ_OFF, 256, 0,
        bq, nullptr, nullptr, nullptr, QSCALE, nullptr, nullptr, qP, nullptr);
    // k (pairs) + v (fp32) fused
    hmma_gemm_n128<0, 1><<<dim3(M_ / 64 * 2, 2), bb, SM_TOT_S>>>(nullptr, ypP, 256, 8,
        wb + WK_OFF, 256, 256 * 256,
        bk, bv, nullptr, nullptr, 1.0f, nullptr, vb_, kP, nullptr);
    // attention
    dim3 ag(N_ / 128, B_ * H_);
    attn_kernel<<<ag, bb, ASM_TOT>>>(qP, kP, vb_, ctxP);
    // xres = xp + ctx @ Wo^T + bo ; LN in place + pairs
    hmma_gemm_n128<2, 1><<<gs, bb, SM_TOT_S>>>(nullptr, ctxP, 256, 8, wb + WO_OFF, 256, 0,
        bo, nullptr, xp, nullptr, 1.0f, xres, nullptr, nullptr, nullptr);
    ln_kernel<<<lg, bb>>>(xres, g_m, b_m, 1, xrsP);
    // hid = relu(xres @ W1^T + b1) -> pairs only
    hmma_gemm_n128<1, 1><<<gs, bb, SM_TOT_S>>>(nullptr, xrsP, 256, 8, wb + W1_OFF, 256, 0,
        b1, nullptr, nullptr, nullptr, 1.0f, nullptr, nullptr, hidP, nullptr);
    // xmlp = xres + hid @ W2^T + b2
    hmma_gemm_n128<2, 1><<<gs, bb, SM_TOT_S>>>(nullptr, hidP, 256, 8, wb + W2_OFF, 256, 0,
        b2, nullptr, xres, nullptr, 1.0f, xmlp, nullptr, nullptr, nullptr);
    // pool + classifier
    pool_cls_kernel<<<B_, bb>>>(xmlp, Wc, bc, out);
}